// round 8
// baseline (speedup 1.0000x reference)
#include <cuda_runtime.h>
#include <math.h>

// ---------------------------------------------------------------------------
// Problem constants
// ---------------------------------------------------------------------------
#define NF 64
#define TT 7
#define H0 192
#define W0 192
#define HW0 (H0 * W0)

// ---------------------------------------------------------------------------
// Scratch layout (single static device buffer; no allocations anywhere)
// ---------------------------------------------------------------------------
#define BIGSZ (7 * 64 * HW0)
#define OFF_FEAT   0
#define OFF_PRED   (OFF_FEAT + BIGSZ)
#define OFF_ALG    (OFF_PRED + BIGSZ)           // conv1 scratch (lqs) / aligned
#define OFF_ALG2   (OFF_ALG + BIGSZ)            // conv1 scratch (preds)
#define OFF_OUT0   (OFF_ALG2 + BIGSZ)
#define OFF_OUT1   (OFF_OUT0 + 64 * HW0)
#define OFF_OUT2   (OFF_OUT1 + 64 * 96 * 96)
#define OFF_U24    (OFF_OUT2 + 64 * 48 * 48)
#define OFF_CAT48  (OFF_U24 + 64 * 24 * 24)
#define OFF_C48    (OFF_CAT48 + 128 * 48 * 48)
#define OFF_CAT96  (OFF_C48 + 64 * 48 * 48)
#define OFF_C96    (OFF_CAT96 + 128 * 96 * 96)
#define OFF_FEATF  (OFF_C96 + 64 * 96 * 96)
#define OFF_OFFM   (OFF_FEATF + 64 * HW0)
#define SCRATCH_TOTAL (OFF_OFFM + 189 * HW0)

__device__ float g_scratch[SCRATCH_TOTAL];

enum { EP_NONE = 0, EP_RELU = 1 };

// ---------------------------------------------------------------------------
// Packed f32x2 helpers (Blackwell FFMA2 path)
// ---------------------------------------------------------------------------
typedef unsigned long long ull_t;
__device__ __forceinline__ ull_t pack2s(float v) {
    ull_t r;
    asm("mov.b64 %0, {%1, %1};" : "=l"(r) : "f"(v));
    return r;
}
__device__ __forceinline__ ull_t pack2(float lo, float hi) {
    ull_t r;
    asm("mov.b64 %0, {%1, %2};" : "=l"(r) : "f"(lo), "f"(hi));
    return r;
}
__device__ __forceinline__ void ffma2(ull_t& d, ull_t a, ull_t b) {
    asm("fma.rn.f32x2 %0, %1, %2, %0;" : "+l"(d) : "l"(a), "l"(b));
}
__device__ __forceinline__ float2 unpack2(ull_t v) {
    float lo, hi;
    asm("mov.b64 {%0, %1}, %2;" : "=f"(lo), "=f"(hi) : "l"(v));
    return make_float2(lo, hi);
}
__device__ __forceinline__ float fsigmoid(float x) {
    return 1.f / (1.f + __expf(-x));
}

// ---------------------------------------------------------------------------
// 3x3 stride-1 pad-1 conv, FFMA2, 256 threads.
// Output tile 64x16: thread = 4 x-adjacent px (tx 0..15) x row (ty 0..15).
// 16 couts per chunk (8 f32x2 pairs). CBLK=8 cis per sync round.
// Input row segments read as two LDS.128 (row stride 68 -> 16B-aligned).
// ---------------------------------------------------------------------------
#define CBLK 8
__global__ void __launch_bounds__(256) conv3x3_s1(
    const float* __restrict__ in, const float* __restrict__ wgt,
    const float* __restrict__ bias, float* __restrict__ out,
    int Cin, int Cout, int H, int W, int nChunks, int ep)
{
    __shared__ float s_in[CBLK][18][68];
    __shared__ alignas(16) float s_w[CBLK][9][16];

    const int img   = blockIdx.z / nChunks;
    const int chunk = blockIdx.z % nChunks;
    const int ox0 = blockIdx.x * 64, oy0 = blockIdx.y * 16;
    const int tid = threadIdx.x;
    const int tx = tid & 15, ty = tid >> 4;
    const float* inB = in + (size_t)img * Cin * H * W;
    const int coBase = chunk * 16;

    ull_t acc[4][8];
#pragma unroll
    for (int p = 0; p < 4; p++)
#pragma unroll
        for (int j = 0; j < 8; j++) acc[p][j] = 0ull;

    for (int c0 = 0; c0 < Cin; c0 += CBLK) {
        const int nc = min(CBLK, Cin - c0);
        // stage inputs: 18 rows x 66 valid cols per ci
        for (int i = tid; i < nc * 1188; i += 256) {
            int cb = i / 1188, rem = i - cb * 1188;
            int r = rem / 66, c = rem - r * 66;
            int gy = oy0 - 1 + r, gx = ox0 - 1 + c;
            s_in[cb][r][c] = (gy >= 0 && gy < H && gx >= 0 && gx < W)
                ? __ldg(inB + ((size_t)(c0 + cb) * H + gy) * W + gx) : 0.f;
        }
        // stage weights
        for (int i = tid; i < nc * 144; i += 256) {
            int cb = i / 144, rem = i - cb * 144;
            int co = rem / 9, t = rem - co * 9;
            int cog = coBase + co;
            s_w[cb][t][co] = (cog < Cout)
                ? __ldg(wgt + ((size_t)cog * Cin + (c0 + cb)) * 9 + t) : 0.f;
        }
        __syncthreads();

        for (int cb = 0; cb < nc; cb++) {
#pragma unroll
            for (int dy = 0; dy < 3; dy++) {
                const float4* rp = reinterpret_cast<const float4*>(&s_in[cb][ty + dy][0]);
                float4 f0 = rp[tx];
                float4 f1 = rp[tx + 1];
                ull_t xs[6];
                xs[0] = pack2s(f0.x); xs[1] = pack2s(f0.y);
                xs[2] = pack2s(f0.z); xs[3] = pack2s(f0.w);
                xs[4] = pack2s(f1.x); xs[5] = pack2s(f1.y);
#pragma unroll
                for (int dx = 0; dx < 3; dx++) {
                    const int t = dy * 3 + dx;
#pragma unroll
                    for (int q2 = 0; q2 < 4; q2++) {
                        ulonglong2 w = *reinterpret_cast<const ulonglong2*>(&s_w[cb][t][4 * q2]);
#pragma unroll
                        for (int p = 0; p < 4; p++) {
                            ffma2(acc[p][2 * q2],     xs[dx + p], w.x);
                            ffma2(acc[p][2 * q2 + 1], xs[dx + p], w.y);
                        }
                    }
                }
            }
        }
        __syncthreads();
    }

    const int oy = oy0 + ty, oxb = ox0 + 4 * tx;
    if (oy >= H || oxb >= W) return;
    const size_t HWs = (size_t)H * W;
    float* ob = out + (size_t)img * Cout * HWs + (size_t)oy * W + oxb;

#pragma unroll
    for (int j = 0; j < 8; j++) {
        float2 u0 = unpack2(acc[0][j]), u1 = unpack2(acc[1][j]);
        float2 u2 = unpack2(acc[2][j]), u3 = unpack2(acc[3][j]);
#pragma unroll
        for (int s = 0; s < 2; s++) {
            int cog = coBase + 2 * j + s;
            if (cog >= Cout) continue;
            float b = __ldg(bias + cog);
            float4 o;
            o.x = (s ? u0.y : u0.x) + b;
            o.y = (s ? u1.y : u1.x) + b;
            o.z = (s ? u2.y : u2.x) + b;
            o.w = (s ? u3.y : u3.x) + b;
            if (ep == EP_RELU) {
                o.x = fmaxf(o.x, 0.f); o.y = fmaxf(o.y, 0.f);
                o.z = fmaxf(o.z, 0.f); o.w = fmaxf(o.w, 0.f);
            }
            *reinterpret_cast<float4*>(ob + (size_t)cog * HWs) = o;
        }
    }
}

// ---------------------------------------------------------------------------
// Dual-input shared-weight 3x3 conv for the fusion pair (32x16 tile, 2 px):
// out = 0.1*leaky(conv(inA)+b) + leaky(conv(inF)+b)
// ---------------------------------------------------------------------------
__global__ void __launch_bounds__(256) conv3x3_s1_dual(
    const float* __restrict__ inA, const float* __restrict__ inF,
    const float* __restrict__ wgt, const float* __restrict__ bias,
    float* __restrict__ out, int Cin, int Cout)
{
    __shared__ float s_a[CBLK][18][35];
    __shared__ float s_f[CBLK][18][35];
    __shared__ alignas(16) float s_w[CBLK][9][16];

    const int chunk = blockIdx.z;
    const int ox0 = blockIdx.x * 32, oy0 = blockIdx.y * 16;
    const int tid = threadIdx.x;
    const int tx = tid & 15, ty = tid >> 4;
    const int coBase = chunk * 16;
    const int H = H0, W = W0;

    ull_t aA0[8], aA1[8], aF0[8], aF1[8];
#pragma unroll
    for (int j = 0; j < 8; j++) { aA0[j] = aA1[j] = aF0[j] = aF1[j] = 0ull; }

    for (int c0 = 0; c0 < Cin; c0 += CBLK) {
        const int nc = min(CBLK, Cin - c0);
        for (int i = tid; i < nc * 612; i += 256) {
            int cb = i / 612, rem = i - cb * 612;
            int r = rem / 34, c = rem - r * 34;
            int gy = oy0 - 1 + r, gx = ox0 - 1 + c;
            bool ok = (gy >= 0 && gy < H && gx >= 0 && gx < W);
            size_t gidx = ((size_t)(c0 + cb) * H + gy) * W + gx;
            s_a[cb][r][c] = ok ? __ldg(inA + gidx) : 0.f;
            s_f[cb][r][c] = ok ? __ldg(inF + gidx) : 0.f;
        }
        for (int i = tid; i < nc * 144; i += 256) {
            int cb = i / 144, rem = i - cb * 144;
            int co = rem / 9, t = rem - co * 9;
            s_w[cb][t][co] = __ldg(wgt + ((size_t)(coBase + co) * Cin + (c0 + cb)) * 9 + t);
        }
        __syncthreads();

        for (int cb = 0; cb < nc; cb++) {
#pragma unroll
            for (int dy = 0; dy < 3; dy++) {
                ull_t pa[4], pf[4];
#pragma unroll
                for (int j = 0; j < 4; j++) {
                    pa[j] = pack2s(s_a[cb][ty + dy][2 * tx + j]);
                    pf[j] = pack2s(s_f[cb][ty + dy][2 * tx + j]);
                }
#pragma unroll
                for (int dx = 0; dx < 3; dx++) {
                    const int t = dy * 3 + dx;
#pragma unroll
                    for (int q2 = 0; q2 < 4; q2++) {
                        ulonglong2 w = *reinterpret_cast<const ulonglong2*>(&s_w[cb][t][4 * q2]);
                        ffma2(aA0[2 * q2],     pa[dx],     w.x);
                        ffma2(aA0[2 * q2 + 1], pa[dx],     w.y);
                        ffma2(aA1[2 * q2],     pa[dx + 1], w.x);
                        ffma2(aA1[2 * q2 + 1], pa[dx + 1], w.y);
                        ffma2(aF0[2 * q2],     pf[dx],     w.x);
                        ffma2(aF0[2 * q2 + 1], pf[dx],     w.y);
                        ffma2(aF1[2 * q2],     pf[dx + 1], w.x);
                        ffma2(aF1[2 * q2 + 1], pf[dx + 1], w.y);
                    }
                }
            }
        }
        __syncthreads();
    }

    const int oy = oy0 + ty, oxb = ox0 + 2 * tx;
    const size_t HWs = (size_t)H * W;
    float* ob = out + (size_t)oy * W + oxb;

#pragma unroll
    for (int j = 0; j < 8; j++) {
        float2 A0 = unpack2(aA0[j]), A1 = unpack2(aA1[j]);
        float2 F0 = unpack2(aF0[j]), F1 = unpack2(aF1[j]);
#pragma unroll
        for (int s = 0; s < 2; s++) {
            int cog = coBase + 2 * j + s;
            float b = __ldg(bias + cog);
            float va0 = (s ? A0.y : A0.x) + b;
            float va1 = (s ? A1.y : A1.x) + b;
            float vf0 = (s ? F0.y : F0.x) + b;
            float vf1 = (s ? F1.y : F1.x) + b;
            va0 = va0 > 0.f ? va0 : 0.1f * va0;
            va1 = va1 > 0.f ? va1 : 0.1f * va1;
            vf0 = vf0 > 0.f ? vf0 : 0.1f * vf0;
            vf1 = vf1 > 0.f ? vf1 : 0.1f * vf1;
            float2 o = make_float2(0.1f * va0 + vf0, 0.1f * va1 + vf1);
            *reinterpret_cast<float2*>(ob + (size_t)cog * HWs) = o;
        }
    }
}

// ---------------------------------------------------------------------------
// 3x3 stride-2 pad-1 conv. Output tile 16x16, 1 pixel/thread.
// ---------------------------------------------------------------------------
template <int CO>
__global__ void __launch_bounds__(256) conv3x3_s2(
    const float* __restrict__ in, const float* __restrict__ wgt,
    const float* __restrict__ bias, float* __restrict__ out,
    int Cin, int Cout, int Hin, int Win, int Hout, int Wout)
{
    __shared__ float s_in[33][33];
    __shared__ alignas(16) float s_w[9][CO];

    const int chunk = blockIdx.z;
    const int ox0 = blockIdx.x * 16, oy0 = blockIdx.y * 16;
    const int tid = threadIdx.x, tx = tid & 15, ty = tid >> 4;
    const int coBase = chunk * CO;

    float acc[CO];
#pragma unroll
    for (int i = 0; i < CO; i++) acc[i] = 0.f;

    for (int ci = 0; ci < Cin; ci++) {
        const float* ip = in + (size_t)ci * Hin * Win;
        for (int i = tid; i < 33 * 33; i += 256) {
            int r = i / 33, c = i - r * 33;
            int gy = 2 * oy0 - 1 + r, gx = 2 * ox0 - 1 + c;
            s_in[r][c] = (gy >= 0 && gy < Hin && gx >= 0 && gx < Win)
                             ? __ldg(ip + (size_t)gy * Win + gx) : 0.f;
        }
        for (int i = tid; i < 9 * CO; i += 256) {
            int co = i / 9, t = i - co * 9;
            int cog = coBase + co;
            s_w[t][co] = (cog < Cout) ? __ldg(wgt + ((size_t)cog * Cin + ci) * 9 + t) : 0.f;
        }
        __syncthreads();

        float v[9];
#pragma unroll
        for (int t = 0; t < 9; t++) v[t] = s_in[2 * ty + t / 3][2 * tx + t % 3];
#pragma unroll
        for (int t = 0; t < 9; t++) {
#pragma unroll
            for (int q = 0; q < CO / 4; q++) {
                float4 w = *reinterpret_cast<const float4*>(&s_w[t][4 * q]);
                acc[4 * q + 0] += v[t] * w.x; acc[4 * q + 1] += v[t] * w.y;
                acc[4 * q + 2] += v[t] * w.z; acc[4 * q + 3] += v[t] * w.w;
            }
        }
        __syncthreads();
    }

    const int ox = ox0 + tx, oy = oy0 + ty;
    if (ox >= Wout || oy >= Hout) return;
    size_t pbase = (size_t)oy * Wout + ox;
#pragma unroll
    for (int co = 0; co < CO; co++) {
        int cog = coBase + co;
        if (cog >= Cout) break;
        float v = acc[co] + __ldg(bias + cog);
        out[(size_t)cog * Hout * Wout + pbase] = fmaxf(v, 0.f);
    }
}

// ---------------------------------------------------------------------------
// ConvTranspose2d: kernel 4, stride 2, pad 1. Always ReLU.
// ---------------------------------------------------------------------------
template <int CO>
__global__ void __launch_bounds__(256) convT4x4_s2(
    const float* __restrict__ in, const float* __restrict__ wgt,
    const float* __restrict__ bias, float* __restrict__ out,
    int Cin, int Cout, int Hin, int Win, int Hout, int Wout)
{
    __shared__ float s_in[10][10];
    __shared__ alignas(16) float s_w[16][CO];

    const int chunk = blockIdx.z;
    const int ox0 = blockIdx.x * 16, oy0 = blockIdx.y * 16;
    const int tid = threadIdx.x, tx = tid & 15, ty = tid >> 4;
    const int coBase = chunk * CO;
    const int iy0 = oy0 / 2 - 1, ix0 = ox0 / 2 - 1;

    const int oy = oy0 + ty, ox = ox0 + tx;
    const int py = (oy + 1) & 1, px = (ox + 1) & 1;
    const int r0 = ((oy + 1 - py) >> 1) - iy0;
    const int r1 = r0 - 1;
    const int c0 = ((ox + 1 - px) >> 1) - ix0;
    const int c1 = c0 - 1;

    float acc[CO];
#pragma unroll
    for (int i = 0; i < CO; i++) acc[i] = 0.f;

    for (int ci = 0; ci < Cin; ci++) {
        const float* ip = in + (size_t)ci * Hin * Win;
        for (int i = tid; i < 100; i += 256) {
            int r = i / 10, c = i - r * 10;
            int gy = iy0 + r, gx = ix0 + c;
            s_in[r][c] = (gy >= 0 && gy < Hin && gx >= 0 && gx < Win)
                             ? __ldg(ip + (size_t)gy * Win + gx) : 0.f;
        }
        for (int i = tid; i < 16 * CO; i += 256) {
            int co = i / 16, t = i - co * 16;
            int cog = coBase + co;
            s_w[t][co] = (cog < Cout) ? __ldg(wgt + ((size_t)ci * Cout + cog) * 16 + t) : 0.f;
        }
        __syncthreads();

        float v00 = s_in[r0][c0], v01 = s_in[r0][c1];
        float v10 = s_in[r1][c0], v11 = s_in[r1][c1];
#pragma unroll
        for (int a = 0; a < 2; a++) {
#pragma unroll
            for (int b = 0; b < 2; b++) {
                float v = a ? (b ? v11 : v10) : (b ? v01 : v00);
                int t = (py + 2 * a) * 4 + (px + 2 * b);
#pragma unroll
                for (int q = 0; q < CO / 4; q++) {
                    float4 w = *reinterpret_cast<const float4*>(&s_w[t][4 * q]);
                    acc[4 * q + 0] += v * w.x; acc[4 * q + 1] += v * w.y;
                    acc[4 * q + 2] += v * w.z; acc[4 * q + 3] += v * w.w;
                }
            }
        }
        __syncthreads();
    }

    if (ox >= Wout || oy >= Hout) return;
    size_t pbase = (size_t)oy * Wout + ox;
#pragma unroll
    for (int co = 0; co < CO; co++) {
        int cog = coBase + co;
        if (cog >= Cout) break;
        float v = acc[co] + __ldg(bias + cog);
        out[(size_t)cog * Hout * Wout + pbase] = fmaxf(v, 0.f);
    }
}

// ---------------------------------------------------------------------------
// Flow warp
// ---------------------------------------------------------------------------
__global__ void flow_warp_kernel(const float* __restrict__ feat,
                                 const float* __restrict__ mv,
                                 float* __restrict__ alg)
{
    const int pix = blockIdx.x * 256 + threadIdx.x;
    if (pix >= HW0) return;
    const int t = blockIdx.y;
    const int y = pix / W0, x = pix - y * W0;

    const float fx = mv[(size_t)t * HW0 * 2 + (size_t)pix * 2 + 0];
    const float fy = mv[(size_t)t * HW0 * 2 + (size_t)pix * 2 + 1];
    const float ys = (float)y + fy;
    const float xs = (float)x + fx;
    const float y0 = floorf(ys), x0 = floorf(xs);
    const float wy = ys - y0, wx = xs - x0;

    float wgt[4]; int off[4]; bool val[4];
#pragma unroll
    for (int i = 0; i < 4; i++) {
        int dy = i >> 1, dx = i & 1;
        float yi = y0 + dy, xi = x0 + dx;
        val[i] = (yi >= 0.f) && (yi <= (float)(H0 - 1)) &&
                 (xi >= 0.f) && (xi <= (float)(W0 - 1));
        wgt[i] = (dy ? wy : 1.f - wy) * (dx ? wx : 1.f - wx);
        off[i] = val[i] ? ((int)yi * W0 + (int)xi) : 0;
    }

    const float* fb = feat + (size_t)t * 64 * HW0;
    float* ob = alg + (size_t)(t + 1) * 64 * HW0 + pix;
    for (int c = 0; c < 64; c++) {
        const float* img = fb + (size_t)c * HW0;
        float acc = 0.f;
#pragma unroll
        for (int i = 0; i < 4; i++)
            if (val[i]) acc += __ldg(img + off[i]) * wgt[i];
        ob[(size_t)c * HW0] = acc;
    }
}

// ---------------------------------------------------------------------------
// Gated fusion, float4 + __expf
// ---------------------------------------------------------------------------
__global__ void fuse_gate_kernel(const float* __restrict__ feat,
                                 const float* __restrict__ pred,
                                 float* __restrict__ alg)
{
    const size_t N4 = (size_t)7 * 64 * HW0 / 4;
    size_t i = (size_t)blockIdx.x * 256 + threadIdx.x;
    if (i >= N4) return;
    size_t rem = i % ((size_t)64 * HW0 / 4);
    float4 ref = reinterpret_cast<const float4*>(feat + (size_t)3 * 64 * HW0)[rem];
    float4 a = reinterpret_cast<float4*>(alg)[i];
    float4 p = reinterpret_cast<const float4*>(pred)[i];
    float4 o;
    o.x = a.x * fsigmoid(a.x * ref.x) + p.x * fsigmoid(p.x * ref.x);
    o.y = a.y * fsigmoid(a.y * ref.y) + p.y * fsigmoid(p.y * ref.y);
    o.z = a.z * fsigmoid(a.z * ref.z) + p.z * fsigmoid(p.z * ref.z);
    o.w = a.w * fsigmoid(a.w * ref.w) + p.w * fsigmoid(p.w * ref.w);
    reinterpret_cast<float4*>(alg)[i] = o;
}

// ---------------------------------------------------------------------------
// Modulated deformable conv, FFMA2 accumulators + __expf sigmoid.
// ---------------------------------------------------------------------------
__global__ void __launch_bounds__(256) deform_kernel(
    const float* __restrict__ lqs, const float* __restrict__ offm,
    const float* __restrict__ dcw, const float* __restrict__ dcb,
    float* __restrict__ out)
{
    __shared__ alignas(16) float s_w[63 * 64];  // [j][o]
    __shared__ float s_b[64];
    const int tid = threadIdx.x;
    for (int i = tid; i < 63 * 64; i += 256) {
        int o = i / 63, j = i - o * 63;
        s_w[j * 64 + o] = dcw[i];
    }
    if (tid < 64) s_b[tid] = dcb[tid];
    __syncthreads();

    const int pix = blockIdx.x * 256 + tid;
    if (pix >= HW0) return;
    const int y = pix / W0, x = pix - y * W0;

    ull_t acc[32];
#pragma unroll
    for (int q = 0; q < 32; q++) acc[q] = pack2(s_b[2 * q], s_b[2 * q + 1]);

    for (int g = 0; g < 7; g++) {
        const float* img = lqs + (size_t)g * HW0;
#pragma unroll
        for (int k = 0; k < 9; k++) {
            const int j = g * 9 + k;
            float offy = __ldg(offm + (size_t)(g * 18 + 2 * k + 0) * HW0 + pix);
            float offx = __ldg(offm + (size_t)(g * 18 + 2 * k + 1) * HW0 + pix);
            float mraw = __ldg(offm + (size_t)(126 + j) * HW0 + pix);
            float m = fsigmoid(mraw);
            float ys = (float)(y + k / 3 - 1) + offy;
            float xs = (float)(x + k % 3 - 1) + offx;
            float y0 = floorf(ys), x0 = floorf(xs);
            float wy = ys - y0, wx = xs - x0;
            float samp = 0.f;
#pragma unroll
            for (int ii = 0; ii < 4; ii++) {
                int dy = ii >> 1, dx = ii & 1;
                float yi = y0 + dy, xi = x0 + dx;
                if (yi >= 0.f && yi <= (float)(H0 - 1) &&
                    xi >= 0.f && xi <= (float)(W0 - 1))
                    samp += __ldg(img + (int)yi * W0 + (int)xi) *
                            ((dy ? wy : 1.f - wy) * (dx ? wx : 1.f - wx));
            }
            ull_t mod2 = pack2s(samp * m);
#pragma unroll
            for (int q2 = 0; q2 < 16; q2++) {
                ulonglong2 w = *reinterpret_cast<const ulonglong2*>(&s_w[j * 64 + 4 * q2]);
                ffma2(acc[2 * q2],     mod2, w.x);
                ffma2(acc[2 * q2 + 1], mod2, w.y);
            }
        }
    }
#pragma unroll
    for (int q = 0; q < 32; q++) {
        float2 u = unpack2(acc[q]);
        out[(size_t)(2 * q) * HW0 + pix]     = fmaxf(u.x, 0.f);
        out[(size_t)(2 * q + 1) * HW0 + pix] = fmaxf(u.y, 0.f);
    }
}

// ---------------------------------------------------------------------------
// Host orchestration (graph-capturable)
// ---------------------------------------------------------------------------
extern "C" void kernel_launch(void* const* d_in, const int* in_sizes, int n_in,
                              void* d_out, int out_size)
{
    const float* lqs    = (const float*)d_in[0];
    const float* preds  = (const float*)d_in[1];
    const float* mv     = (const float*)d_in[2];
    const float* bw1    = (const float*)d_in[3];
    const float* bb1    = (const float*)d_in[4];
    const float* bw2    = (const float*)d_in[5];
    const float* bb2    = (const float*)d_in[6];
    const float* dn1_w  = (const float*)d_in[7];
    const float* dn1_b  = (const float*)d_in[8];
    const float* dn2_w  = (const float*)d_in[9];
    const float* dn2_b  = (const float*)d_in[10];
    const float* up1_cw = (const float*)d_in[11];
    const float* up1_cb = (const float*)d_in[12];
    const float* up1_tw = (const float*)d_in[13];
    const float* up1_tb = (const float*)d_in[14];
    const float* up2_cw = (const float*)d_in[15];
    const float* up2_cb = (const float*)d_in[16];
    const float* up2_tw = (const float*)d_in[17];
    const float* up2_tb = (const float*)d_in[18];
    const float* tr_cw  = (const float*)d_in[19];
    const float* tr_cb  = (const float*)d_in[20];
    const float* tr_tw  = (const float*)d_in[21];
    const float* tr_tb  = (const float*)d_in[22];
    const float* ff_w   = (const float*)d_in[23];
    const float* ff_b   = (const float*)d_in[24];
    const float* om_w   = (const float*)d_in[25];
    const float* om_b   = (const float*)d_in[26];
    const float* dc_w   = (const float*)d_in[27];
    const float* dc_b   = (const float*)d_in[28];
    float* outp = (float*)d_out;

    float* S = nullptr;
    cudaGetSymbolAddress((void**)&S, g_scratch);
    float* feat  = S + OFF_FEAT;   // conv2 out: imgs 0..6 (lqs)
    float* pred  = S + OFF_PRED;   // conv2 out: imgs 7..13 (preds)
    float* alg   = S + OFF_ALG;    // conv1 scratch (lqs), later aligned buffer
    float* alg2  = S + OFF_ALG2;   // conv1 scratch (preds)
    float* out0  = S + OFF_OUT0;
    float* out1  = S + OFF_OUT1;
    float* out2  = S + OFF_OUT2;
    float* u24   = S + OFF_U24;
    float* cat48 = S + OFF_CAT48;
    float* c48   = S + OFF_C48;
    float* cat96 = S + OFF_CAT96;
    float* c96   = S + OFF_C96;
    float* featf = S + OFF_FEATF;
    float* offm  = S + OFF_OFFM;

    dim3 blk(256);

    // Backbone conv1 (1->64) on lqs and preds -> contiguous scratch [alg|alg2]
    conv3x3_s1<<<dim3(3, 12, 7 * 4), blk>>>(lqs,   bw1, bb1, alg,  1, 64, 192, 192, 4, EP_NONE);
    conv3x3_s1<<<dim3(3, 12, 7 * 4), blk>>>(preds, bw1, bb1, alg2, 1, 64, 192, 192, 4, EP_NONE);
    // Backbone conv2 (64->64), 14 images in ONE launch -> [feat|pred]
    conv3x3_s1<<<dim3(3, 12, 14 * 4), blk>>>(alg, bw2, bb2, feat, 64, 64, 192, 192, 4, EP_NONE);

    // aligned[0] = feat[0]; aligned[1..6] = warp(feat[0..5], mv)  (reuses alg)
    cudaMemcpyAsync(alg, feat, (size_t)64 * HW0 * sizeof(float),
                    cudaMemcpyDeviceToDevice, 0);
    flow_warp_kernel<<<dim3(HW0 / 256, 6), blk>>>(feat, mv, alg);

    // alg := a1 + a2 (gated), in place
    fuse_gate_kernel<<<(unsigned)(((size_t)7 * 64 * HW0 / 4 + 255) / 256), blk>>>(feat, pred, alg);

    // out0 = 0.1*leaky(conv448(alg)) + leaky(conv448(feat)) — one dual kernel
    conv3x3_s1_dual<<<dim3(6, 12, 4), blk>>>(alg, feat, ff_w, ff_b, out0, 448, 64);

    // Down path
    conv3x3_s2<16><<<dim3(6, 6, 4), blk>>>(out0, dn1_w, dn1_b, out1, 64, 64, 192, 192, 96, 96);
    conv3x3_s2<16><<<dim3(3, 3, 4), blk>>>(out1, dn2_w, dn2_b, out2, 64, 64, 96, 96, 48, 48);
    conv3x3_s2<16><<<dim3(2, 2, 4), blk>>>(out2, tr_cw, tr_cb, u24, 64, 64, 48, 48, 24, 24);

    // Up path with skip concats
    convT4x4_s2<32><<<dim3(3, 3, 2), blk>>>(u24, tr_tw, tr_tb, cat48, 64, 64, 24, 24, 48, 48);
    cudaMemcpyAsync(cat48 + (size_t)64 * 48 * 48, out2,
                    (size_t)64 * 48 * 48 * sizeof(float), cudaMemcpyDeviceToDevice, 0);
    conv3x3_s1<<<dim3(1, 3, 4), blk>>>(cat48, up2_cw, up2_cb, c48, 128, 64, 48, 48, 4, EP_RELU);
    convT4x4_s2<32><<<dim3(6, 6, 2), blk>>>(c48, up2_tw, up2_tb, cat96, 64, 64, 48, 48, 96, 96);
    cudaMemcpyAsync(cat96 + (size_t)64 * 96 * 96, out1,
                    (size_t)64 * 96 * 96 * sizeof(float), cudaMemcpyDeviceToDevice, 0);
    conv3x3_s1<<<dim3(2, 6, 4), blk>>>(cat96, up1_cw, up1_cb, c96, 128, 64, 96, 96, 4, EP_RELU);
    convT4x4_s2<32><<<dim3(12, 12, 2), blk>>>(c96, up1_tw, up1_tb, featf, 64, 64, 96, 96, 192, 192);

    // Offsets + masks (Cout=189 -> 12 chunks of 16)
    conv3x3_s1<<<dim3(3, 12, 12), blk>>>(featf, om_w, om_b, offm, 64, 189, 192, 192, 12, EP_NONE);

    // Modulated deformable conv + ReLU -> output
    deform_kernel<<<HW0 / 256, blk>>>(lqs, offm, dc_w, dc_b, outp);
}

// round 9
// speedup vs baseline: 1.3204x; 1.3204x over previous
#include <cuda_runtime.h>
#include <math.h>
#include <stdint.h>

// ---------------------------------------------------------------------------
// Problem constants
// ---------------------------------------------------------------------------
#define NF 64
#define TT 7
#define H0 192
#define W0 192
#define HW0 (H0 * W0)

// ---------------------------------------------------------------------------
// Scratch layout (single static device buffer; no allocations anywhere)
// ---------------------------------------------------------------------------
#define BIGSZ (7 * 64 * HW0)
#define OFF_FEAT   0
#define OFF_PRED   (OFF_FEAT + BIGSZ)
#define OFF_ALG    (OFF_PRED + BIGSZ)           // conv1 scratch (lqs) / aligned
#define OFF_ALG2   (OFF_ALG + BIGSZ)            // conv1 scratch (preds)
#define OFF_OUT0   (OFF_ALG2 + BIGSZ)
#define OFF_OUT1   (OFF_OUT0 + 64 * HW0)
#define OFF_OUT2   (OFF_OUT1 + 64 * 96 * 96)
#define OFF_U24    (OFF_OUT2 + 64 * 48 * 48)
#define OFF_CAT48  (OFF_U24 + 64 * 24 * 24)
#define OFF_C48    (OFF_CAT48 + 128 * 48 * 48)
#define OFF_CAT96  (OFF_C48 + 64 * 48 * 48)
#define OFF_C96    (OFF_CAT96 + 128 * 96 * 96)
#define OFF_FEATF  (OFF_C96 + 64 * 96 * 96)
#define OFF_OFFM   (OFF_FEATF + 64 * HW0)
#define SCRATCH_TOTAL (OFF_OFFM + 189 * HW0)

__device__ float g_scratch[SCRATCH_TOTAL];

enum { EP_NONE = 0, EP_RELU = 1 };

// ---------------------------------------------------------------------------
// Packed f32x2 helpers (Blackwell FFMA2 path)
// ---------------------------------------------------------------------------
typedef unsigned long long ull_t;
__device__ __forceinline__ ull_t pack2s(float v) {
    ull_t r;
    asm("mov.b64 %0, {%1, %1};" : "=l"(r) : "f"(v));
    return r;
}
__device__ __forceinline__ ull_t pack2(float lo, float hi) {
    ull_t r;
    asm("mov.b64 %0, {%1, %2};" : "=l"(r) : "f"(lo), "f"(hi));
    return r;
}
__device__ __forceinline__ void ffma2(ull_t& d, ull_t a, ull_t b) {
    asm("fma.rn.f32x2 %0, %1, %2, %0;" : "+l"(d) : "l"(a), "l"(b));
}
__device__ __forceinline__ float2 unpack2(ull_t v) {
    float lo, hi;
    asm("mov.b64 {%0, %1}, %2;" : "=f"(lo), "=f"(hi) : "l"(v));
    return make_float2(lo, hi);
}
__device__ __forceinline__ float fsigmoid(float x) {
    return 1.f / (1.f + __expf(-x));
}

// ---------------------------------------------------------------------------
// cp.async helpers (4-byte, zero-fill when invalid via src-size = 0)
// ---------------------------------------------------------------------------
__device__ __forceinline__ uint32_t smem_u32(const void* p) {
    return (uint32_t)__cvta_generic_to_shared(p);
}
__device__ __forceinline__ void cp_async4(uint32_t s, const float* g, bool ok) {
    asm volatile("cp.async.ca.shared.global [%0], [%1], 4, %2;"
                 :: "r"(s), "l"(g), "r"(ok ? 4u : 0u));
}
#define CP_COMMIT() asm volatile("cp.async.commit_group;")
#define CP_WAIT0()  asm volatile("cp.async.wait_group 0;")

// ---------------------------------------------------------------------------
// 3x3 stride-1 pad-1 conv, FFMA2, 256 threads, cp.async double-buffered.
// Output tile 32x16: thread = 2 x-adjacent px (tx 0..15) x row (ty 0..15).
// 16 couts per chunk (8 f32x2 pairs). 4 cis per buffer, 2 buffers ping-pong.
// ---------------------------------------------------------------------------
#define CB4 4
__global__ void __launch_bounds__(256, 3) conv3x3_s1(
    const float* __restrict__ in, const float* __restrict__ wgt,
    const float* __restrict__ bias, float* __restrict__ out,
    int Cin, int Cout, int H, int W, int nChunks, int ep)
{
    __shared__ float s_in[2][CB4][18][35];
    __shared__ alignas(16) float s_w[2][CB4][9][16];

    const int img   = blockIdx.z / nChunks;
    const int chunk = blockIdx.z % nChunks;
    const int ox0 = blockIdx.x * 32, oy0 = blockIdx.y * 16;
    const int tid = threadIdx.x;
    const int tx = tid & 15, ty = tid >> 4;
    const float* inB = in + (size_t)img * Cin * H * W;
    const int coBase = chunk * 16;

    ull_t acc0[8], acc1[8];
#pragma unroll
    for (int j = 0; j < 8; j++) { acc0[j] = 0ull; acc1[j] = 0ull; }

    const int nB = (Cin + CB4 - 1) / CB4;

    auto stage = [&](int buf, int b) {
        const int c0 = b * CB4;
        const int nc = min(CB4, Cin - c0);
        for (int i = tid; i < nc * 612; i += 256) {
            int cb = i / 612, rem = i - cb * 612;
            int r = rem / 34, c = rem - r * 34;
            int gy = oy0 - 1 + r, gx = ox0 - 1 + c;
            bool ok = (gy >= 0 && gy < H && gx >= 0 && gx < W);
            int gyc = ok ? gy : 0, gxc = ok ? gx : 0;
            cp_async4(smem_u32(&s_in[buf][cb][r][c]),
                      inB + ((size_t)(c0 + cb) * H + gyc) * W + gxc, ok);
        }
        for (int i = tid; i < nc * 144; i += 256) {
            int cb = i / 144, rem = i - cb * 144;
            int co = rem / 9, t = rem - co * 9;
            int cog = coBase + co;
            bool ok = (cog < Cout);
            cp_async4(smem_u32(&s_w[buf][cb][t][co]),
                      wgt + ((size_t)(ok ? cog : 0) * Cin + (c0 + cb)) * 9 + t, ok);
        }
        CP_COMMIT();
    };

    stage(0, 0);
    for (int b = 0; b < nB; b++) {
        CP_WAIT0();
        __syncthreads();
        if (b + 1 < nB) stage((b + 1) & 1, b + 1);
        const int buf = b & 1;
        const int nc = min(CB4, Cin - b * CB4);
        for (int cb = 0; cb < nc; cb++) {
#pragma unroll
            for (int dy = 0; dy < 3; dy++) {
                ull_t ps[4];
#pragma unroll
                for (int j = 0; j < 4; j++)
                    ps[j] = pack2s(s_in[buf][cb][ty + dy][2 * tx + j]);
#pragma unroll
                for (int dx = 0; dx < 3; dx++) {
                    const int t = dy * 3 + dx;
#pragma unroll
                    for (int q2 = 0; q2 < 4; q2++) {
                        ulonglong2 w = *reinterpret_cast<const ulonglong2*>(&s_w[buf][cb][t][4 * q2]);
                        ffma2(acc0[2 * q2],     ps[dx],     w.x);
                        ffma2(acc0[2 * q2 + 1], ps[dx],     w.y);
                        ffma2(acc1[2 * q2],     ps[dx + 1], w.x);
                        ffma2(acc1[2 * q2 + 1], ps[dx + 1], w.y);
                    }
                }
            }
        }
    }

    const int oy = oy0 + ty, oxb = ox0 + 2 * tx;
    if (oy >= H || oxb >= W) return;
    const size_t HWs = (size_t)H * W;
    float* ob = out + (size_t)img * Cout * HWs + (size_t)oy * W + oxb;

#pragma unroll
    for (int j = 0; j < 8; j++) {
        float2 u0 = unpack2(acc0[j]), u1 = unpack2(acc1[j]);
#pragma unroll
        for (int s = 0; s < 2; s++) {
            int cog = coBase + 2 * j + s;
            if (cog >= Cout) continue;
            float b = __ldg(bias + cog);
            float2 o;
            o.x = (s ? u0.y : u0.x) + b;
            o.y = (s ? u1.y : u1.x) + b;
            if (ep == EP_RELU) { o.x = fmaxf(o.x, 0.f); o.y = fmaxf(o.y, 0.f); }
            *reinterpret_cast<float2*>(ob + (size_t)cog * HWs) = o;
        }
    }
}

// ---------------------------------------------------------------------------
// Dual-input shared-weight 3x3 conv (fusion pair), cp.async double-buffered:
// out = 0.1*leaky(conv(inA)+b) + leaky(conv(inF)+b)
// ---------------------------------------------------------------------------
__global__ void __launch_bounds__(256, 2) conv3x3_s1_dual(
    const float* __restrict__ inA, const float* __restrict__ inF,
    const float* __restrict__ wgt, const float* __restrict__ bias,
    float* __restrict__ out, int Cin, int Cout)
{
    __shared__ float s_a[2][CB4][18][35];
    __shared__ float s_f[2][CB4][18][35];
    __shared__ alignas(16) float s_w[2][CB4][9][16];

    const int chunk = blockIdx.z;
    const int ox0 = blockIdx.x * 32, oy0 = blockIdx.y * 16;
    const int tid = threadIdx.x;
    const int tx = tid & 15, ty = tid >> 4;
    const int coBase = chunk * 16;
    const int H = H0, W = W0;

    ull_t aA0[8], aA1[8], aF0[8], aF1[8];
#pragma unroll
    for (int j = 0; j < 8; j++) { aA0[j] = aA1[j] = aF0[j] = aF1[j] = 0ull; }

    const int nB = (Cin + CB4 - 1) / CB4;

    auto stage = [&](int buf, int b) {
        const int c0 = b * CB4;
        const int nc = min(CB4, Cin - c0);
        for (int i = tid; i < nc * 612; i += 256) {
            int cb = i / 612, rem = i - cb * 612;
            int r = rem / 34, c = rem - r * 34;
            int gy = oy0 - 1 + r, gx = ox0 - 1 + c;
            bool ok = (gy >= 0 && gy < H && gx >= 0 && gx < W);
            int gyc = ok ? gy : 0, gxc = ok ? gx : 0;
            size_t gidx = ((size_t)(c0 + cb) * H + gyc) * W + gxc;
            cp_async4(smem_u32(&s_a[buf][cb][r][c]), inA + gidx, ok);
            cp_async4(smem_u32(&s_f[buf][cb][r][c]), inF + gidx, ok);
        }
        for (int i = tid; i < nc * 144; i += 256) {
            int cb = i / 144, rem = i - cb * 144;
            int co = rem / 9, t = rem - co * 9;
            cp_async4(smem_u32(&s_w[buf][cb][t][co]),
                      wgt + ((size_t)(coBase + co) * Cin + (c0 + cb)) * 9 + t, true);
        }
        CP_COMMIT();
    };

    stage(0, 0);
    for (int b = 0; b < nB; b++) {
        CP_WAIT0();
        __syncthreads();
        if (b + 1 < nB) stage((b + 1) & 1, b + 1);
        const int buf = b & 1;
        const int nc = min(CB4, Cin - b * CB4);
        for (int cb = 0; cb < nc; cb++) {
#pragma unroll
            for (int dy = 0; dy < 3; dy++) {
                ull_t pa[4], pf[4];
#pragma unroll
                for (int j = 0; j < 4; j++) {
                    pa[j] = pack2s(s_a[buf][cb][ty + dy][2 * tx + j]);
                    pf[j] = pack2s(s_f[buf][cb][ty + dy][2 * tx + j]);
                }
#pragma unroll
                for (int dx = 0; dx < 3; dx++) {
                    const int t = dy * 3 + dx;
#pragma unroll
                    for (int q2 = 0; q2 < 4; q2++) {
                        ulonglong2 w = *reinterpret_cast<const ulonglong2*>(&s_w[buf][cb][t][4 * q2]);
                        ffma2(aA0[2 * q2],     pa[dx],     w.x);
                        ffma2(aA0[2 * q2 + 1], pa[dx],     w.y);
                        ffma2(aA1[2 * q2],     pa[dx + 1], w.x);
                        ffma2(aA1[2 * q2 + 1], pa[dx + 1], w.y);
                        ffma2(aF0[2 * q2],     pf[dx],     w.x);
                        ffma2(aF0[2 * q2 + 1], pf[dx],     w.y);
                        ffma2(aF1[2 * q2],     pf[dx + 1], w.x);
                        ffma2(aF1[2 * q2 + 1], pf[dx + 1], w.y);
                    }
                }
            }
        }
    }

    const int oy = oy0 + ty, oxb = ox0 + 2 * tx;
    const size_t HWs = (size_t)H * W;
    float* ob = out + (size_t)oy * W + oxb;

#pragma unroll
    for (int j = 0; j < 8; j++) {
        float2 A0 = unpack2(aA0[j]), A1 = unpack2(aA1[j]);
        float2 F0 = unpack2(aF0[j]), F1 = unpack2(aF1[j]);
#pragma unroll
        for (int s = 0; s < 2; s++) {
            int cog = coBase + 2 * j + s;
            float b = __ldg(bias + cog);
            float va0 = (s ? A0.y : A0.x) + b;
            float va1 = (s ? A1.y : A1.x) + b;
            float vf0 = (s ? F0.y : F0.x) + b;
            float vf1 = (s ? F1.y : F1.x) + b;
            va0 = va0 > 0.f ? va0 : 0.1f * va0;
            va1 = va1 > 0.f ? va1 : 0.1f * va1;
            vf0 = vf0 > 0.f ? vf0 : 0.1f * vf0;
            vf1 = vf1 > 0.f ? vf1 : 0.1f * vf1;
            float2 o = make_float2(0.1f * va0 + vf0, 0.1f * va1 + vf1);
            *reinterpret_cast<float2*>(ob + (size_t)cog * HWs) = o;
        }
    }
}

// ---------------------------------------------------------------------------
// 3x3 stride-2 pad-1 conv. Output tile 16x16, 1 pixel/thread. CO=8 chunks.
// ---------------------------------------------------------------------------
template <int CO>
__global__ void __launch_bounds__(256) conv3x3_s2(
    const float* __restrict__ in, const float* __restrict__ wgt,
    const float* __restrict__ bias, float* __restrict__ out,
    int Cin, int Cout, int Hin, int Win, int Hout, int Wout)
{
    __shared__ float s_in[33][33];
    __shared__ alignas(16) float s_w[9][CO];

    const int chunk = blockIdx.z;
    const int ox0 = blockIdx.x * 16, oy0 = blockIdx.y * 16;
    const int tid = threadIdx.x, tx = tid & 15, ty = tid >> 4;
    const int coBase = chunk * CO;

    float acc[CO];
#pragma unroll
    for (int i = 0; i < CO; i++) acc[i] = 0.f;

    for (int ci = 0; ci < Cin; ci++) {
        const float* ip = in + (size_t)ci * Hin * Win;
        for (int i = tid; i < 33 * 33; i += 256) {
            int r = i / 33, c = i - r * 33;
            int gy = 2 * oy0 - 1 + r, gx = 2 * ox0 - 1 + c;
            s_in[r][c] = (gy >= 0 && gy < Hin && gx >= 0 && gx < Win)
                             ? __ldg(ip + (size_t)gy * Win + gx) : 0.f;
        }
        for (int i = tid; i < 9 * CO; i += 256) {
            int co = i / 9, t = i - co * 9;
            int cog = coBase + co;
            s_w[t][co] = (cog < Cout) ? __ldg(wgt + ((size_t)cog * Cin + ci) * 9 + t) : 0.f;
        }
        __syncthreads();

        float v[9];
#pragma unroll
        for (int t = 0; t < 9; t++) v[t] = s_in[2 * ty + t / 3][2 * tx + t % 3];
#pragma unroll
        for (int t = 0; t < 9; t++) {
#pragma unroll
            for (int q = 0; q < CO / 4; q++) {
                float4 w = *reinterpret_cast<const float4*>(&s_w[t][4 * q]);
                acc[4 * q + 0] += v[t] * w.x; acc[4 * q + 1] += v[t] * w.y;
                acc[4 * q + 2] += v[t] * w.z; acc[4 * q + 3] += v[t] * w.w;
            }
        }
        __syncthreads();
    }

    const int ox = ox0 + tx, oy = oy0 + ty;
    if (ox >= Wout || oy >= Hout) return;
    size_t pbase = (size_t)oy * Wout + ox;
#pragma unroll
    for (int co = 0; co < CO; co++) {
        int cog = coBase + co;
        if (cog >= Cout) break;
        float v = acc[co] + __ldg(bias + cog);
        out[(size_t)cog * Hout * Wout + pbase] = fmaxf(v, 0.f);
    }
}

// ---------------------------------------------------------------------------
// ConvTranspose2d: kernel 4, stride 2, pad 1. Always ReLU. CO=16 chunks.
// ---------------------------------------------------------------------------
template <int CO>
__global__ void __launch_bounds__(256) convT4x4_s2(
    const float* __restrict__ in, const float* __restrict__ wgt,
    const float* __restrict__ bias, float* __restrict__ out,
    int Cin, int Cout, int Hin, int Win, int Hout, int Wout)
{
    __shared__ float s_in[10][10];
    __shared__ alignas(16) float s_w[16][CO];

    const int chunk = blockIdx.z;
    const int ox0 = blockIdx.x * 16, oy0 = blockIdx.y * 16;
    const int tid = threadIdx.x, tx = tid & 15, ty = tid >> 4;
    const int coBase = chunk * CO;
    const int iy0 = oy0 / 2 - 1, ix0 = ox0 / 2 - 1;

    const int oy = oy0 + ty, ox = ox0 + tx;
    const int py = (oy + 1) & 1, px = (ox + 1) & 1;
    const int r0 = ((oy + 1 - py) >> 1) - iy0;
    const int r1 = r0 - 1;
    const int c0 = ((ox + 1 - px) >> 1) - ix0;
    const int c1 = c0 - 1;

    float acc[CO];
#pragma unroll
    for (int i = 0; i < CO; i++) acc[i] = 0.f;

    for (int ci = 0; ci < Cin; ci++) {
        const float* ip = in + (size_t)ci * Hin * Win;
        for (int i = tid; i < 100; i += 256) {
            int r = i / 10, c = i - r * 10;
            int gy = iy0 + r, gx = ix0 + c;
            s_in[r][c] = (gy >= 0 && gy < Hin && gx >= 0 && gx < Win)
                             ? __ldg(ip + (size_t)gy * Win + gx) : 0.f;
        }
        for (int i = tid; i < 16 * CO; i += 256) {
            int co = i / 16, t = i - co * 16;
            int cog = coBase + co;
            s_w[t][co] = (cog < Cout) ? __ldg(wgt + ((size_t)ci * Cout + cog) * 16 + t) : 0.f;
        }
        __syncthreads();

        float v00 = s_in[r0][c0], v01 = s_in[r0][c1];
        float v10 = s_in[r1][c0], v11 = s_in[r1][c1];
#pragma unroll
        for (int a = 0; a < 2; a++) {
#pragma unroll
            for (int b = 0; b < 2; b++) {
                float v = a ? (b ? v11 : v10) : (b ? v01 : v00);
                int t = (py + 2 * a) * 4 + (px + 2 * b);
#pragma unroll
                for (int q = 0; q < CO / 4; q++) {
                    float4 w = *reinterpret_cast<const float4*>(&s_w[t][4 * q]);
                    acc[4 * q + 0] += v * w.x; acc[4 * q + 1] += v * w.y;
                    acc[4 * q + 2] += v * w.z; acc[4 * q + 3] += v * w.w;
                }
            }
        }
        __syncthreads();
    }

    if (ox >= Wout || oy >= Hout) return;
    size_t pbase = (size_t)oy * Wout + ox;
#pragma unroll
    for (int co = 0; co < CO; co++) {
        int cog = coBase + co;
        if (cog >= Cout) break;
        float v = acc[co] + __ldg(bias + cog);
        out[(size_t)cog * Hout * Wout + pbase] = fmaxf(v, 0.f);
    }
}

// ---------------------------------------------------------------------------
// Flow warp
// ---------------------------------------------------------------------------
__global__ void flow_warp_kernel(const float* __restrict__ feat,
                                 const float* __restrict__ mv,
                                 float* __restrict__ alg)
{
    const int pix = blockIdx.x * 256 + threadIdx.x;
    if (pix >= HW0) return;
    const int t = blockIdx.y;
    const int y = pix / W0, x = pix - y * W0;

    const float fx = mv[(size_t)t * HW0 * 2 + (size_t)pix * 2 + 0];
    const float fy = mv[(size_t)t * HW0 * 2 + (size_t)pix * 2 + 1];
    const float ys = (float)y + fy;
    const float xs = (float)x + fx;
    const float y0 = floorf(ys), x0 = floorf(xs);
    const float wy = ys - y0, wx = xs - x0;

    float wgt[4]; int off[4]; bool val[4];
#pragma unroll
    for (int i = 0; i < 4; i++) {
        int dy = i >> 1, dx = i & 1;
        float yi = y0 + dy, xi = x0 + dx;
        val[i] = (yi >= 0.f) && (yi <= (float)(H0 - 1)) &&
                 (xi >= 0.f) && (xi <= (float)(W0 - 1));
        wgt[i] = (dy ? wy : 1.f - wy) * (dx ? wx : 1.f - wx);
        off[i] = val[i] ? ((int)yi * W0 + (int)xi) : 0;
    }

    const float* fb = feat + (size_t)t * 64 * HW0;
    float* ob = alg + (size_t)(t + 1) * 64 * HW0 + pix;
    for (int c = 0; c < 64; c++) {
        const float* img = fb + (size_t)c * HW0;
        float acc = 0.f;
#pragma unroll
        for (int i = 0; i < 4; i++)
            if (val[i]) acc += __ldg(img + off[i]) * wgt[i];
        ob[(size_t)c * HW0] = acc;
    }
}

// ---------------------------------------------------------------------------
// Gated fusion, float4 + __expf
// ---------------------------------------------------------------------------
__global__ void fuse_gate_kernel(const float* __restrict__ feat,
                                 const float* __restrict__ pred,
                                 float* __restrict__ alg)
{
    const size_t N4 = (size_t)7 * 64 * HW0 / 4;
    size_t i = (size_t)blockIdx.x * 256 + threadIdx.x;
    if (i >= N4) return;
    size_t rem = i % ((size_t)64 * HW0 / 4);
    float4 ref = reinterpret_cast<const float4*>(feat + (size_t)3 * 64 * HW0)[rem];
    float4 a = reinterpret_cast<float4*>(alg)[i];
    float4 p = reinterpret_cast<const float4*>(pred)[i];
    float4 o;
    o.x = a.x * fsigmoid(a.x * ref.x) + p.x * fsigmoid(p.x * ref.x);
    o.y = a.y * fsigmoid(a.y * ref.y) + p.y * fsigmoid(p.y * ref.y);
    o.z = a.z * fsigmoid(a.z * ref.z) + p.z * fsigmoid(p.z * ref.z);
    o.w = a.w * fsigmoid(a.w * ref.w) + p.w * fsigmoid(p.w * ref.w);
    reinterpret_cast<float4*>(alg)[i] = o;
}

// ---------------------------------------------------------------------------
// Modulated deformable conv, FFMA2 accumulators + __expf sigmoid.
// ---------------------------------------------------------------------------
__global__ void __launch_bounds__(256) deform_kernel(
    const float* __restrict__ lqs, const float* __restrict__ offm,
    const float* __restrict__ dcw, const float* __restrict__ dcb,
    float* __restrict__ out)
{
    __shared__ alignas(16) float s_w[63 * 64];  // [j][o]
    __shared__ float s_b[64];
    const int tid = threadIdx.x;
    for (int i = tid; i < 63 * 64; i += 256) {
        int o = i / 63, j = i - o * 63;
        s_w[j * 64 + o] = dcw[i];
    }
    if (tid < 64) s_b[tid] = dcb[tid];
    __syncthreads();

    const int pix = blockIdx.x * 256 + tid;
    if (pix >= HW0) return;
    const int y = pix / W0, x = pix - y * W0;

    ull_t acc[32];
#pragma unroll
    for (int q = 0; q < 32; q++) acc[q] = pack2(s_b[2 * q], s_b[2 * q + 1]);

    for (int g = 0; g < 7; g++) {
        const float* img = lqs + (size_t)g * HW0;
#pragma unroll
        for (int k = 0; k < 9; k++) {
            const int j = g * 9 + k;
            float offy = __ldg(offm + (size_t)(g * 18 + 2 * k + 0) * HW0 + pix);
            float offx = __ldg(offm + (size_t)(g * 18 + 2 * k + 1) * HW0 + pix);
            float mraw = __ldg(offm + (size_t)(126 + j) * HW0 + pix);
            float m = fsigmoid(mraw);
            float ys = (float)(y + k / 3 - 1) + offy;
            float xs = (float)(x + k % 3 - 1) + offx;
            float y0 = floorf(ys), x0 = floorf(xs);
            float wy = ys - y0, wx = xs - x0;
            float samp = 0.f;
#pragma unroll
            for (int ii = 0; ii < 4; ii++) {
                int dy = ii >> 1, dx = ii & 1;
                float yi = y0 + dy, xi = x0 + dx;
                if (yi >= 0.f && yi <= (float)(H0 - 1) &&
                    xi >= 0.f && xi <= (float)(W0 - 1))
                    samp += __ldg(img + (int)yi * W0 + (int)xi) *
                            ((dy ? wy : 1.f - wy) * (dx ? wx : 1.f - wx));
            }
            ull_t mod2 = pack2s(samp * m);
#pragma unroll
            for (int q2 = 0; q2 < 16; q2++) {
                ulonglong2 w = *reinterpret_cast<const ulonglong2*>(&s_w[j * 64 + 4 * q2]);
                ffma2(acc[2 * q2],     mod2, w.x);
                ffma2(acc[2 * q2 + 1], mod2, w.y);
            }
        }
    }
#pragma unroll
    for (int q = 0; q < 32; q++) {
        float2 u = unpack2(acc[q]);
        out[(size_t)(2 * q) * HW0 + pix]     = fmaxf(u.x, 0.f);
        out[(size_t)(2 * q + 1) * HW0 + pix] = fmaxf(u.y, 0.f);
    }
}

// ---------------------------------------------------------------------------
// Host orchestration (graph-capturable)
// ---------------------------------------------------------------------------
extern "C" void kernel_launch(void* const* d_in, const int* in_sizes, int n_in,
                              void* d_out, int out_size)
{
    const float* lqs    = (const float*)d_in[0];
    const float* preds  = (const float*)d_in[1];
    const float* mv     = (const float*)d_in[2];
    const float* bw1    = (const float*)d_in[3];
    const float* bb1    = (const float*)d_in[4];
    const float* bw2    = (const float*)d_in[5];
    const float* bb2    = (const float*)d_in[6];
    const float* dn1_w  = (const float*)d_in[7];
    const float* dn1_b  = (const float*)d_in[8];
    const float* dn2_w  = (const float*)d_in[9];
    const float* dn2_b  = (const float*)d_in[10];
    const float* up1_cw = (const float*)d_in[11];
    const float* up1_cb = (const float*)d_in[12];
    const float* up1_tw = (const float*)d_in[13];
    const float* up1_tb = (const float*)d_in[14];
    const float* up2_cw = (const float*)d_in[15];
    const float* up2_cb = (const float*)d_in[16];
    const float* up2_tw = (const float*)d_in[17];
    const float* up2_tb = (const float*)d_in[18];
    const float* tr_cw  = (const float*)d_in[19];
    const float* tr_cb  = (const float*)d_in[20];
    const float* tr_tw  = (const float*)d_in[21];
    const float* tr_tb  = (const float*)d_in[22];
    const float* ff_w   = (const float*)d_in[23];
    const float* ff_b   = (const float*)d_in[24];
    const float* om_w   = (const float*)d_in[25];
    const float* om_b   = (const float*)d_in[26];
    const float* dc_w   = (const float*)d_in[27];
    const float* dc_b   = (const float*)d_in[28];
    float* outp = (float*)d_out;

    float* S = nullptr;
    cudaGetSymbolAddress((void**)&S, g_scratch);
    float* feat  = S + OFF_FEAT;   // conv2 out: imgs 0..6 (lqs)
    float* pred  = S + OFF_PRED;   // conv2 out: imgs 7..13 (preds)
    float* alg   = S + OFF_ALG;    // conv1 scratch (lqs), later aligned buffer
    float* alg2  = S + OFF_ALG2;   // conv1 scratch (preds)
    float* out0  = S + OFF_OUT0;
    float* out1  = S + OFF_OUT1;
    float* out2  = S + OFF_OUT2;
    float* u24   = S + OFF_U24;
    float* cat48 = S + OFF_CAT48;
    float* c48   = S + OFF_C48;
    float* cat96 = S + OFF_CAT96;
    float* c96   = S + OFF_C96;
    float* featf = S + OFF_FEATF;
    float* offm  = S + OFF_OFFM;

    dim3 blk(256);

    // Backbone conv1 (1->64) on lqs and preds -> contiguous scratch [alg|alg2]
    conv3x3_s1<<<dim3(6, 12, 7 * 4), blk>>>(lqs,   bw1, bb1, alg,  1, 64, 192, 192, 4, EP_NONE);
    conv3x3_s1<<<dim3(6, 12, 7 * 4), blk>>>(preds, bw1, bb1, alg2, 1, 64, 192, 192, 4, EP_NONE);
    // Backbone conv2 (64->64), 14 images in ONE launch -> [feat|pred]
    conv3x3_s1<<<dim3(6, 12, 14 * 4), blk>>>(alg, bw2, bb2, feat, 64, 64, 192, 192, 4, EP_NONE);

    // aligned[0] = feat[0]; aligned[1..6] = warp(feat[0..5], mv)  (reuses alg)
    cudaMemcpyAsync(alg, feat, (size_t)64 * HW0 * sizeof(float),
                    cudaMemcpyDeviceToDevice, 0);
    flow_warp_kernel<<<dim3(HW0 / 256, 6), blk>>>(feat, mv, alg);

    // alg := a1 + a2 (gated), in place
    fuse_gate_kernel<<<(unsigned)(((size_t)7 * 64 * HW0 / 4 + 255) / 256), blk>>>(feat, pred, alg);

    // out0 = 0.1*leaky(conv448(alg)) + leaky(conv448(feat)) — one dual kernel
    conv3x3_s1_dual<<<dim3(6, 12, 4), blk>>>(alg, feat, ff_w, ff_b, out0, 448, 64);

    // Down path (CO=8 -> 8 chunks for more parallelism)
    conv3x3_s2<8><<<dim3(6, 6, 8), blk>>>(out0, dn1_w, dn1_b, out1, 64, 64, 192, 192, 96, 96);
    conv3x3_s2<8><<<dim3(3, 3, 8), blk>>>(out1, dn2_w, dn2_b, out2, 64, 64, 96, 96, 48, 48);
    conv3x3_s2<8><<<dim3(2, 2, 8), blk>>>(out2, tr_cw, tr_cb, u24, 64, 64, 48, 48, 24, 24);

    // Up path with skip concats (convT CO=16 -> 4 chunks)
    convT4x4_s2<16><<<dim3(3, 3, 4), blk>>>(u24, tr_tw, tr_tb, cat48, 64, 64, 24, 24, 48, 48);
    cudaMemcpyAsync(cat48 + (size_t)64 * 48 * 48, out2,
                    (size_t)64 * 48 * 48 * sizeof(float), cudaMemcpyDeviceToDevice, 0);
    conv3x3_s1<<<dim3(2, 3, 4), blk>>>(cat48, up2_cw, up2_cb, c48, 128, 64, 48, 48, 4, EP_RELU);
    convT4x4_s2<16><<<dim3(6, 6, 4), blk>>>(c48, up2_tw, up2_tb, cat96, 64, 64, 48, 48, 96, 96);
    cudaMemcpyAsync(cat96 + (size_t)64 * 96 * 96, out1,
                    (size_t)64 * 96 * 96 * sizeof(float), cudaMemcpyDeviceToDevice, 0);
    conv3x3_s1<<<dim3(3, 6, 4), blk>>>(cat96, up1_cw, up1_cb, c96, 128, 64, 96, 96, 4, EP_RELU);
    convT4x4_s2<16><<<dim3(12, 12, 4), blk>>>(c96, up1_tw, up1_tb, featf, 64, 64, 96, 96, 192, 192);

    // Offsets + masks (Cout=189 -> 12 chunks of 16)
    conv3x3_s1<<<dim3(6, 12, 12), blk>>>(featf, om_w, om_b, offm, 64, 189, 192, 192, 12, EP_NONE);

    // Modulated deformable conv + ReLU -> output
    deform_kernel<<<HW0 / 256, blk>>>(lqs, offm, dc_w, dc_b, outp);
}

// round 10
// speedup vs baseline: 1.3374x; 1.0129x over previous
#include <cuda_runtime.h>
#include <math.h>
#include <stdint.h>

// ---------------------------------------------------------------------------
// Problem constants
// ---------------------------------------------------------------------------
#define NF 64
#define TT 7
#define H0 192
#define W0 192
#define HW0 (H0 * W0)

// ---------------------------------------------------------------------------
// Scratch layout (single static device buffer; no allocations anywhere)
// ---------------------------------------------------------------------------
#define BIGSZ (7 * 64 * HW0)
#define OFF_FEAT   0
#define OFF_PRED   (OFF_FEAT + BIGSZ)
#define OFF_ALG    (OFF_PRED + BIGSZ)           // conv1 scratch (lqs) / aligned
#define OFF_ALG2   (OFF_ALG + BIGSZ)            // conv1 scratch (preds)
#define OFF_OUT0   (OFF_ALG2 + BIGSZ)
#define OFF_OUT1   (OFF_OUT0 + 64 * HW0)
#define OFF_OUT2   (OFF_OUT1 + 64 * 96 * 96)
#define OFF_U24    (OFF_OUT2 + 64 * 48 * 48)
#define OFF_CAT48  (OFF_U24 + 64 * 24 * 24)
#define OFF_C48    (OFF_CAT48 + 128 * 48 * 48)
#define OFF_CAT96  (OFF_C48 + 64 * 48 * 48)
#define OFF_C96    (OFF_CAT96 + 128 * 96 * 96)
#define OFF_FEATF  (OFF_C96 + 64 * 96 * 96)
#define OFF_OFFM   (OFF_FEATF + 64 * HW0)
#define SCRATCH_TOTAL (OFF_OFFM + 189 * HW0)

__device__ float g_scratch[SCRATCH_TOTAL];

enum { EP_NONE = 0, EP_RELU = 1 };

// ---------------------------------------------------------------------------
// Packed f32x2 helpers (Blackwell FFMA2 path)
// ---------------------------------------------------------------------------
typedef unsigned long long ull_t;
__device__ __forceinline__ ull_t pack2s(float v) {
    ull_t r;
    asm("mov.b64 %0, {%1, %1};" : "=l"(r) : "f"(v));
    return r;
}
__device__ __forceinline__ ull_t pack2(float lo, float hi) {
    ull_t r;
    asm("mov.b64 %0, {%1, %2};" : "=l"(r) : "f"(lo), "f"(hi));
    return r;
}
__device__ __forceinline__ void ffma2(ull_t& d, ull_t a, ull_t b) {
    asm("fma.rn.f32x2 %0, %1, %2, %0;" : "+l"(d) : "l"(a), "l"(b));
}
__device__ __forceinline__ float2 unpack2(ull_t v) {
    float lo, hi;
    asm("mov.b64 {%0, %1}, %2;" : "=f"(lo), "=f"(hi) : "l"(v));
    return make_float2(lo, hi);
}
__device__ __forceinline__ float fsigmoid(float x) {
    return 1.f / (1.f + __expf(-x));
}

// ---------------------------------------------------------------------------
// cp.async helpers (4-byte, zero-fill when invalid via src-size = 0)
// ---------------------------------------------------------------------------
__device__ __forceinline__ uint32_t smem_u32(const void* p) {
    return (uint32_t)__cvta_generic_to_shared(p);
}
__device__ __forceinline__ void cp_async4(uint32_t s, const float* g, bool ok) {
    asm volatile("cp.async.ca.shared.global [%0], [%1], 4, %2;"
                 :: "r"(s), "l"(g), "r"(ok ? 4u : 0u));
}
#define CP_COMMIT() asm volatile("cp.async.commit_group;")
#define CP_WAIT0()  asm volatile("cp.async.wait_group 0;")

// ---------------------------------------------------------------------------
// 3x3 stride-1 pad-1 conv, FFMA2, 256 threads, cp.async double-buffered.
// Output tile 32x16: thread = 2 x-adjacent px (tx 0..15) x row (ty 0..15).
// NP f32x2 cout-pairs per chunk (CO = 2*NP). 4 cis per buffer, ping-pong.
// NP=8 -> 3 blocks/SM; NP=16 -> 2 blocks/SM.
// ---------------------------------------------------------------------------
#define CB4 4
template <int NP>
__global__ void __launch_bounds__(256, NP == 8 ? 3 : 2) conv3x3_s1(
    const float* __restrict__ in, const float* __restrict__ wgt,
    const float* __restrict__ bias, float* __restrict__ out,
    int Cin, int Cout, int H, int W, int nChunks, int ep)
{
    const int CO = 2 * NP;
    __shared__ float s_in[2][CB4][18][35];
    __shared__ alignas(16) float s_w[2][CB4][9][2 * NP];

    const int img   = blockIdx.z / nChunks;
    const int chunk = blockIdx.z % nChunks;
    const int ox0 = blockIdx.x * 32, oy0 = blockIdx.y * 16;
    const int tid = threadIdx.x;
    const int tx = tid & 15, ty = tid >> 4;
    const float* inB = in + (size_t)img * Cin * H * W;
    const int coBase = chunk * CO;

    ull_t acc0[NP], acc1[NP];
#pragma unroll
    for (int j = 0; j < NP; j++) { acc0[j] = 0ull; acc1[j] = 0ull; }

    const int nB = (Cin + CB4 - 1) / CB4;

    auto stage = [&](int buf, int b) {
        const int c0 = b * CB4;
        const int nc = min(CB4, Cin - c0);
        for (int i = tid; i < nc * 612; i += 256) {
            int cb = i / 612, rem = i - cb * 612;
            int r = rem / 34, c = rem - r * 34;
            int gy = oy0 - 1 + r, gx = ox0 - 1 + c;
            bool ok = (gy >= 0 && gy < H && gx >= 0 && gx < W);
            int gyc = ok ? gy : 0, gxc = ok ? gx : 0;
            cp_async4(smem_u32(&s_in[buf][cb][r][c]),
                      inB + ((size_t)(c0 + cb) * H + gyc) * W + gxc, ok);
        }
        for (int i = tid; i < nc * 9 * CO; i += 256) {
            int cb = i / (9 * CO), rem = i - cb * (9 * CO);
            int co = rem / 9, t = rem - co * 9;
            int cog = coBase + co;
            bool ok = (cog < Cout);
            cp_async4(smem_u32(&s_w[buf][cb][t][co]),
                      wgt + ((size_t)(ok ? cog : 0) * Cin + (c0 + cb)) * 9 + t, ok);
        }
        CP_COMMIT();
    };

    stage(0, 0);
    for (int b = 0; b < nB; b++) {
        CP_WAIT0();
        __syncthreads();
        if (b + 1 < nB) stage((b + 1) & 1, b + 1);
        const int buf = b & 1;
        const int nc = min(CB4, Cin - b * CB4);
        for (int cb = 0; cb < nc; cb++) {
#pragma unroll
            for (int dy = 0; dy < 3; dy++) {
                ull_t ps[4];
#pragma unroll
                for (int j = 0; j < 4; j++)
                    ps[j] = pack2s(s_in[buf][cb][ty + dy][2 * tx + j]);
#pragma unroll
                for (int dx = 0; dx < 3; dx++) {
                    const int t = dy * 3 + dx;
#pragma unroll
                    for (int q2 = 0; q2 < NP / 2; q2++) {
                        ulonglong2 w = *reinterpret_cast<const ulonglong2*>(&s_w[buf][cb][t][4 * q2]);
                        ffma2(acc0[2 * q2],     ps[dx],     w.x);
                        ffma2(acc0[2 * q2 + 1], ps[dx],     w.y);
                        ffma2(acc1[2 * q2],     ps[dx + 1], w.x);
                        ffma2(acc1[2 * q2 + 1], ps[dx + 1], w.y);
                    }
                }
            }
        }
    }

    const int oy = oy0 + ty, oxb = ox0 + 2 * tx;
    if (oy >= H || oxb >= W) return;
    const size_t HWs = (size_t)H * W;
    float* ob = out + (size_t)img * Cout * HWs + (size_t)oy * W + oxb;

#pragma unroll
    for (int j = 0; j < NP; j++) {
        float2 u0 = unpack2(acc0[j]), u1 = unpack2(acc1[j]);
#pragma unroll
        for (int s = 0; s < 2; s++) {
            int cog = coBase + 2 * j + s;
            if (cog >= Cout) continue;
            float b = __ldg(bias + cog);
            float2 o;
            o.x = (s ? u0.y : u0.x) + b;
            o.y = (s ? u1.y : u1.x) + b;
            if (ep == EP_RELU) { o.x = fmaxf(o.x, 0.f); o.y = fmaxf(o.y, 0.f); }
            *reinterpret_cast<float2*>(ob + (size_t)cog * HWs) = o;
        }
    }
}

// ---------------------------------------------------------------------------
// Dual-input shared-weight 3x3 conv (fusion pair), cp.async double-buffered:
// out = 0.1*leaky(conv(inA)+b) + leaky(conv(inF)+b)
// ---------------------------------------------------------------------------
__global__ void __launch_bounds__(256, 2) conv3x3_s1_dual(
    const float* __restrict__ inA, const float* __restrict__ inF,
    const float* __restrict__ wgt, const float* __restrict__ bias,
    float* __restrict__ out, int Cin, int Cout)
{
    __shared__ float s_a[2][CB4][18][35];
    __shared__ float s_f[2][CB4][18][35];
    __shared__ alignas(16) float s_w[2][CB4][9][16];

    const int chunk = blockIdx.z;
    const int ox0 = blockIdx.x * 32, oy0 = blockIdx.y * 16;
    const int tid = threadIdx.x;
    const int tx = tid & 15, ty = tid >> 4;
    const int coBase = chunk * 16;
    const int H = H0, W = W0;

    ull_t aA0[8], aA1[8], aF0[8], aF1[8];
#pragma unroll
    for (int j = 0; j < 8; j++) { aA0[j] = aA1[j] = aF0[j] = aF1[j] = 0ull; }

    const int nB = (Cin + CB4 - 1) / CB4;

    auto stage = [&](int buf, int b) {
        const int c0 = b * CB4;
        const int nc = min(CB4, Cin - c0);
        for (int i = tid; i < nc * 612; i += 256) {
            int cb = i / 612, rem = i - cb * 612;
            int r = rem / 34, c = rem - r * 34;
            int gy = oy0 - 1 + r, gx = ox0 - 1 + c;
            bool ok = (gy >= 0 && gy < H && gx >= 0 && gx < W);
            int gyc = ok ? gy : 0, gxc = ok ? gx : 0;
            size_t gidx = ((size_t)(c0 + cb) * H + gyc) * W + gxc;
            cp_async4(smem_u32(&s_a[buf][cb][r][c]), inA + gidx, ok);
            cp_async4(smem_u32(&s_f[buf][cb][r][c]), inF + gidx, ok);
        }
        for (int i = tid; i < nc * 144; i += 256) {
            int cb = i / 144, rem = i - cb * 144;
            int co = rem / 9, t = rem - co * 9;
            cp_async4(smem_u32(&s_w[buf][cb][t][co]),
                      wgt + ((size_t)(coBase + co) * Cin + (c0 + cb)) * 9 + t, true);
        }
        CP_COMMIT();
    };

    stage(0, 0);
    for (int b = 0; b < nB; b++) {
        CP_WAIT0();
        __syncthreads();
        if (b + 1 < nB) stage((b + 1) & 1, b + 1);
        const int buf = b & 1;
        const int nc = min(CB4, Cin - b * CB4);
        for (int cb = 0; cb < nc; cb++) {
#pragma unroll
            for (int dy = 0; dy < 3; dy++) {
                ull_t pa[4], pf[4];
#pragma unroll
                for (int j = 0; j < 4; j++) {
                    pa[j] = pack2s(s_a[buf][cb][ty + dy][2 * tx + j]);
                    pf[j] = pack2s(s_f[buf][cb][ty + dy][2 * tx + j]);
                }
#pragma unroll
                for (int dx = 0; dx < 3; dx++) {
                    const int t = dy * 3 + dx;
#pragma unroll
                    for (int q2 = 0; q2 < 4; q2++) {
                        ulonglong2 w = *reinterpret_cast<const ulonglong2*>(&s_w[buf][cb][t][4 * q2]);
                        ffma2(aA0[2 * q2],     pa[dx],     w.x);
                        ffma2(aA0[2 * q2 + 1], pa[dx],     w.y);
                        ffma2(aA1[2 * q2],     pa[dx + 1], w.x);
                        ffma2(aA1[2 * q2 + 1], pa[dx + 1], w.y);
                        ffma2(aF0[2 * q2],     pf[dx],     w.x);
                        ffma2(aF0[2 * q2 + 1], pf[dx],     w.y);
                        ffma2(aF1[2 * q2],     pf[dx + 1], w.x);
                        ffma2(aF1[2 * q2 + 1], pf[dx + 1], w.y);
                    }
                }
            }
        }
    }

    const int oy = oy0 + ty, oxb = ox0 + 2 * tx;
    const size_t HWs = (size_t)H * W;
    float* ob = out + (size_t)oy * W + oxb;

#pragma unroll
    for (int j = 0; j < 8; j++) {
        float2 A0 = unpack2(aA0[j]), A1 = unpack2(aA1[j]);
        float2 F0 = unpack2(aF0[j]), F1 = unpack2(aF1[j]);
#pragma unroll
        for (int s = 0; s < 2; s++) {
            int cog = coBase + 2 * j + s;
            float b = __ldg(bias + cog);
            float va0 = (s ? A0.y : A0.x) + b;
            float va1 = (s ? A1.y : A1.x) + b;
            float vf0 = (s ? F0.y : F0.x) + b;
            float vf1 = (s ? F1.y : F1.x) + b;
            va0 = va0 > 0.f ? va0 : 0.1f * va0;
            va1 = va1 > 0.f ? va1 : 0.1f * va1;
            vf0 = vf0 > 0.f ? vf0 : 0.1f * vf0;
            vf1 = vf1 > 0.f ? vf1 : 0.1f * vf1;
            float2 o = make_float2(0.1f * va0 + vf0, 0.1f * va1 + vf1);
            *reinterpret_cast<float2*>(ob + (size_t)cog * HWs) = o;
        }
    }
}

// ---------------------------------------------------------------------------
// 3x3 stride-2 pad-1 conv. Output tile 16x16, 1 px/thread. 8 cis per sync.
// ---------------------------------------------------------------------------
#define SCB 8
template <int CO>
__global__ void __launch_bounds__(256) conv3x3_s2(
    const float* __restrict__ in, const float* __restrict__ wgt,
    const float* __restrict__ bias, float* __restrict__ out,
    int Cin, int Cout, int Hin, int Win, int Hout, int Wout)
{
    __shared__ float s_in[SCB][33][33];
    __shared__ alignas(16) float s_w[SCB][9][CO];

    const int chunk = blockIdx.z;
    const int ox0 = blockIdx.x * 16, oy0 = blockIdx.y * 16;
    const int tid = threadIdx.x, tx = tid & 15, ty = tid >> 4;
    const int coBase = chunk * CO;

    float acc[CO];
#pragma unroll
    for (int i = 0; i < CO; i++) acc[i] = 0.f;

    for (int c0 = 0; c0 < Cin; c0 += SCB) {
        const int nc = min(SCB, Cin - c0);
        for (int i = tid; i < nc * 1089; i += 256) {
            int cb = i / 1089, rem = i - cb * 1089;
            int r = rem / 33, c = rem - r * 33;
            int gy = 2 * oy0 - 1 + r, gx = 2 * ox0 - 1 + c;
            s_in[cb][r][c] = (gy >= 0 && gy < Hin && gx >= 0 && gx < Win)
                ? __ldg(in + ((size_t)(c0 + cb) * Hin + gy) * Win + gx) : 0.f;
        }
        for (int i = tid; i < nc * 9 * CO; i += 256) {
            int cb = i / (9 * CO), rem = i - cb * (9 * CO);
            int co = rem / 9, t = rem - co * 9;
            int cog = coBase + co;
            s_w[cb][t][co] = (cog < Cout)
                ? __ldg(wgt + ((size_t)cog * Cin + (c0 + cb)) * 9 + t) : 0.f;
        }
        __syncthreads();

        for (int cb = 0; cb < nc; cb++) {
            float v[9];
#pragma unroll
            for (int t = 0; t < 9; t++) v[t] = s_in[cb][2 * ty + t / 3][2 * tx + t % 3];
#pragma unroll
            for (int t = 0; t < 9; t++) {
#pragma unroll
                for (int q = 0; q < CO / 4; q++) {
                    float4 w = *reinterpret_cast<const float4*>(&s_w[cb][t][4 * q]);
                    acc[4 * q + 0] += v[t] * w.x; acc[4 * q + 1] += v[t] * w.y;
                    acc[4 * q + 2] += v[t] * w.z; acc[4 * q + 3] += v[t] * w.w;
                }
            }
        }
        __syncthreads();
    }

    const int ox = ox0 + tx, oy = oy0 + ty;
    if (ox >= Wout || oy >= Hout) return;
    size_t pbase = (size_t)oy * Wout + ox;
#pragma unroll
    for (int co = 0; co < CO; co++) {
        int cog = coBase + co;
        if (cog >= Cout) break;
        float v = acc[co] + __ldg(bias + cog);
        out[(size_t)cog * Hout * Wout + pbase] = fmaxf(v, 0.f);
    }
}

// ---------------------------------------------------------------------------
// ConvTranspose2d: kernel 4, stride 2, pad 1. Always ReLU. 8 cis per sync.
// ---------------------------------------------------------------------------
template <int CO>
__global__ void __launch_bounds__(256) convT4x4_s2(
    const float* __restrict__ in, const float* __restrict__ wgt,
    const float* __restrict__ bias, float* __restrict__ out,
    int Cin, int Cout, int Hin, int Win, int Hout, int Wout)
{
    __shared__ float s_in[SCB][10][10];
    __shared__ alignas(16) float s_w[SCB][16][CO];

    const int chunk = blockIdx.z;
    const int ox0 = blockIdx.x * 16, oy0 = blockIdx.y * 16;
    const int tid = threadIdx.x, tx = tid & 15, ty = tid >> 4;
    const int coBase = chunk * CO;
    const int iy0 = oy0 / 2 - 1, ix0 = ox0 / 2 - 1;

    const int oy = oy0 + ty, ox = ox0 + tx;
    const int py = (oy + 1) & 1, px = (ox + 1) & 1;
    const int r0 = ((oy + 1 - py) >> 1) - iy0;
    const int r1 = r0 - 1;
    const int c0i = ((ox + 1 - px) >> 1) - ix0;
    const int c1i = c0i - 1;

    float acc[CO];
#pragma unroll
    for (int i = 0; i < CO; i++) acc[i] = 0.f;

    for (int c0 = 0; c0 < Cin; c0 += SCB) {
        const int nc = min(SCB, Cin - c0);
        for (int i = tid; i < nc * 100; i += 256) {
            int cb = i / 100, rem = i - cb * 100;
            int r = rem / 10, c = rem - r * 10;
            int gy = iy0 + r, gx = ix0 + c;
            s_in[cb][r][c] = (gy >= 0 && gy < Hin && gx >= 0 && gx < Win)
                ? __ldg(in + ((size_t)(c0 + cb) * Hin + gy) * Win + gx) : 0.f;
        }
        for (int i = tid; i < nc * 16 * CO; i += 256) {
            int cb = i / (16 * CO), rem = i - cb * (16 * CO);
            int co = rem / 16, t = rem - co * 16;
            int cog = coBase + co;
            s_w[cb][t][co] = (cog < Cout)
                ? __ldg(wgt + ((size_t)(c0 + cb) * Cout + cog) * 16 + t) : 0.f;
        }
        __syncthreads();

        for (int cb = 0; cb < nc; cb++) {
            float v00 = s_in[cb][r0][c0i], v01 = s_in[cb][r0][c1i];
            float v10 = s_in[cb][r1][c0i], v11 = s_in[cb][r1][c1i];
#pragma unroll
            for (int a = 0; a < 2; a++) {
#pragma unroll
                for (int b = 0; b < 2; b++) {
                    float v = a ? (b ? v11 : v10) : (b ? v01 : v00);
                    int t = (py + 2 * a) * 4 + (px + 2 * b);
#pragma unroll
                    for (int q = 0; q < CO / 4; q++) {
                        float4 w = *reinterpret_cast<const float4*>(&s_w[cb][t][4 * q]);
                        acc[4 * q + 0] += v * w.x; acc[4 * q + 1] += v * w.y;
                        acc[4 * q + 2] += v * w.z; acc[4 * q + 3] += v * w.w;
                    }
                }
            }
        }
        __syncthreads();
    }

    if (ox >= Wout || oy >= Hout) return;
    size_t pbase = (size_t)oy * Wout + ox;
#pragma unroll
    for (int co = 0; co < CO; co++) {
        int cog = coBase + co;
        if (cog >= Cout) break;
        float v = acc[co] + __ldg(bias + cog);
        out[(size_t)cog * Hout * Wout + pbase] = fmaxf(v, 0.f);
    }
}

// ---------------------------------------------------------------------------
// Flow warp
// ---------------------------------------------------------------------------
__global__ void flow_warp_kernel(const float* __restrict__ feat,
                                 const float* __restrict__ mv,
                                 float* __restrict__ alg)
{
    const int pix = blockIdx.x * 256 + threadIdx.x;
    if (pix >= HW0) return;
    const int t = blockIdx.y;
    const int y = pix / W0, x = pix - y * W0;

    const float fx = mv[(size_t)t * HW0 * 2 + (size_t)pix * 2 + 0];
    const float fy = mv[(size_t)t * HW0 * 2 + (size_t)pix * 2 + 1];
    const float ys = (float)y + fy;
    const float xs = (float)x + fx;
    const float y0 = floorf(ys), x0 = floorf(xs);
    const float wy = ys - y0, wx = xs - x0;

    float wgt[4]; int off[4]; bool val[4];
#pragma unroll
    for (int i = 0; i < 4; i++) {
        int dy = i >> 1, dx = i & 1;
        float yi = y0 + dy, xi = x0 + dx;
        val[i] = (yi >= 0.f) && (yi <= (float)(H0 - 1)) &&
                 (xi >= 0.f) && (xi <= (float)(W0 - 1));
        wgt[i] = (dy ? wy : 1.f - wy) * (dx ? wx : 1.f - wx);
        off[i] = val[i] ? ((int)yi * W0 + (int)xi) : 0;
    }

    const float* fb = feat + (size_t)t * 64 * HW0;
    float* ob = alg + (size_t)(t + 1) * 64 * HW0 + pix;
    for (int c = 0; c < 64; c++) {
        const float* img = fb + (size_t)c * HW0;
        float acc = 0.f;
#pragma unroll
        for (int i = 0; i < 4; i++)
            if (val[i]) acc += __ldg(img + off[i]) * wgt[i];
        ob[(size_t)c * HW0] = acc;
    }
}

// ---------------------------------------------------------------------------
// Gated fusion, float4 + __expf
// ---------------------------------------------------------------------------
__global__ void fuse_gate_kernel(const float* __restrict__ feat,
                                 const float* __restrict__ pred,
                                 float* __restrict__ alg)
{
    const size_t N4 = (size_t)7 * 64 * HW0 / 4;
    size_t i = (size_t)blockIdx.x * 256 + threadIdx.x;
    if (i >= N4) return;
    size_t rem = i % ((size_t)64 * HW0 / 4);
    float4 ref = reinterpret_cast<const float4*>(feat + (size_t)3 * 64 * HW0)[rem];
    float4 a = reinterpret_cast<float4*>(alg)[i];
    float4 p = reinterpret_cast<const float4*>(pred)[i];
    float4 o;
    o.x = a.x * fsigmoid(a.x * ref.x) + p.x * fsigmoid(p.x * ref.x);
    o.y = a.y * fsigmoid(a.y * ref.y) + p.y * fsigmoid(p.y * ref.y);
    o.z = a.z * fsigmoid(a.z * ref.z) + p.z * fsigmoid(p.z * ref.z);
    o.w = a.w * fsigmoid(a.w * ref.w) + p.w * fsigmoid(p.w * ref.w);
    reinterpret_cast<float4*>(alg)[i] = o;
}

// ---------------------------------------------------------------------------
// Modulated deformable conv, FFMA2 accumulators + __expf sigmoid.
// ---------------------------------------------------------------------------
__global__ void __launch_bounds__(256) deform_kernel(
    const float* __restrict__ lqs, const float* __restrict__ offm,
    const float* __restrict__ dcw, const float* __restrict__ dcb,
    float* __restrict__ out)
{
    __shared__ alignas(16) float s_w[63 * 64];  // [j][o]
    __shared__ float s_b[64];
    const int tid = threadIdx.x;
    for (int i = tid; i < 63 * 64; i += 256) {
        int o = i / 63, j = i - o * 63;
        s_w[j * 64 + o] = dcw[i];
    }
    if (tid < 64) s_b[tid] = dcb[tid];
    __syncthreads();

    const int pix = blockIdx.x * 256 + tid;
    if (pix >= HW0) return;
    const int y = pix / W0, x = pix - y * W0;

    ull_t acc[32];
#pragma unroll
    for (int q = 0; q < 32; q++) acc[q] = pack2(s_b[2 * q], s_b[2 * q + 1]);

    for (int g = 0; g < 7; g++) {
        const float* img = lqs + (size_t)g * HW0;
#pragma unroll
        for (int k = 0; k < 9; k++) {
            const int j = g * 9 + k;
            float offy = __ldg(offm + (size_t)(g * 18 + 2 * k + 0) * HW0 + pix);
            float offx = __ldg(offm + (size_t)(g * 18 + 2 * k + 1) * HW0 + pix);
            float mraw = __ldg(offm + (size_t)(126 + j) * HW0 + pix);
            float m = fsigmoid(mraw);
            float ys = (float)(y + k / 3 - 1) + offy;
            float xs = (float)(x + k % 3 - 1) + offx;
            float y0 = floorf(ys), x0 = floorf(xs);
            float wy = ys - y0, wx = xs - x0;
            float samp = 0.f;
#pragma unroll
            for (int ii = 0; ii < 4; ii++) {
                int dy = ii >> 1, dx = ii & 1;
                float yi = y0 + dy, xi = x0 + dx;
                if (yi >= 0.f && yi <= (float)(H0 - 1) &&
                    xi >= 0.f && xi <= (float)(W0 - 1))
                    samp += __ldg(img + (int)yi * W0 + (int)xi) *
                            ((dy ? wy : 1.f - wy) * (dx ? wx : 1.f - wx));
            }
            ull_t mod2 = pack2s(samp * m);
#pragma unroll
            for (int q2 = 0; q2 < 16; q2++) {
                ulonglong2 w = *reinterpret_cast<const ulonglong2*>(&s_w[j * 64 + 4 * q2]);
                ffma2(acc[2 * q2],     mod2, w.x);
                ffma2(acc[2 * q2 + 1], mod2, w.y);
            }
        }
    }
#pragma unroll
    for (int q = 0; q < 32; q++) {
        float2 u = unpack2(acc[q]);
        out[(size_t)(2 * q) * HW0 + pix]     = fmaxf(u.x, 0.f);
        out[(size_t)(2 * q + 1) * HW0 + pix] = fmaxf(u.y, 0.f);
    }
}

// ---------------------------------------------------------------------------
// Host orchestration (graph-capturable)
// ---------------------------------------------------------------------------
extern "C" void kernel_launch(void* const* d_in, const int* in_sizes, int n_in,
                              void* d_out, int out_size)
{
    const float* lqs    = (const float*)d_in[0];
    const float* preds  = (const float*)d_in[1];
    const float* mv     = (const float*)d_in[2];
    const float* bw1    = (const float*)d_in[3];
    const float* bb1    = (const float*)d_in[4];
    const float* bw2    = (const float*)d_in[5];
    const float* bb2    = (const float*)d_in[6];
    const float* dn1_w  = (const float*)d_in[7];
    const float* dn1_b  = (const float*)d_in[8];
    const float* dn2_w  = (const float*)d_in[9];
    const float* dn2_b  = (const float*)d_in[10];
    const float* up1_cw = (const float*)d_in[11];
    const float* up1_cb = (const float*)d_in[12];
    const float* up1_tw = (const float*)d_in[13];
    const float* up1_tb = (const float*)d_in[14];
    const float* up2_cw = (const float*)d_in[15];
    const float* up2_cb = (const float*)d_in[16];
    const float* up2_tw = (const float*)d_in[17];
    const float* up2_tb = (const float*)d_in[18];
    const float* tr_cw  = (const float*)d_in[19];
    const float* tr_cb  = (const float*)d_in[20];
    const float* tr_tw  = (const float*)d_in[21];
    const float* tr_tb  = (const float*)d_in[22];
    const float* ff_w   = (const float*)d_in[23];
    const float* ff_b   = (const float*)d_in[24];
    const float* om_w   = (const float*)d_in[25];
    const float* om_b   = (const float*)d_in[26];
    const float* dc_w   = (const float*)d_in[27];
    const float* dc_b   = (const float*)d_in[28];
    float* outp = (float*)d_out;

    float* S = nullptr;
    cudaGetSymbolAddress((void**)&S, g_scratch);
    float* feat  = S + OFF_FEAT;   // conv2 out: imgs 0..6 (lqs)
    float* pred  = S + OFF_PRED;   // conv2 out: imgs 7..13 (preds)
    float* alg   = S + OFF_ALG;    // conv1 scratch (lqs), later aligned buffer
    float* alg2  = S + OFF_ALG2;   // conv1 scratch (preds)
    float* out0  = S + OFF_OUT0;
    float* out1  = S + OFF_OUT1;
    float* out2  = S + OFF_OUT2;
    float* u24   = S + OFF_U24;
    float* cat48 = S + OFF_CAT48;
    float* c48   = S + OFF_C48;
    float* cat96 = S + OFF_CAT96;
    float* c96   = S + OFF_C96;
    float* featf = S + OFF_FEATF;
    float* offm  = S + OFF_OFFM;

    dim3 blk(256);

    // Backbone conv1 (1->64) on lqs and preds -> contiguous scratch [alg|alg2]
    conv3x3_s1<8><<<dim3(6, 12, 7 * 4), blk>>>(lqs,   bw1, bb1, alg,  1, 64, 192, 192, 4, EP_NONE);
    conv3x3_s1<8><<<dim3(6, 12, 7 * 4), blk>>>(preds, bw1, bb1, alg2, 1, 64, 192, 192, 4, EP_NONE);
    // Backbone conv2 (64->64), 14 images in ONE launch, CO=32 -> [feat|pred]
    conv3x3_s1<16><<<dim3(6, 12, 14 * 2), blk>>>(alg, bw2, bb2, feat, 64, 64, 192, 192, 2, EP_NONE);

    // aligned[0] = feat[0]; aligned[1..6] = warp(feat[0..5], mv)  (reuses alg)
    cudaMemcpyAsync(alg, feat, (size_t)64 * HW0 * sizeof(float),
                    cudaMemcpyDeviceToDevice, 0);
    flow_warp_kernel<<<dim3(HW0 / 256, 6), blk>>>(feat, mv, alg);

    // alg := a1 + a2 (gated), in place
    fuse_gate_kernel<<<(unsigned)(((size_t)7 * 64 * HW0 / 4 + 255) / 256), blk>>>(feat, pred, alg);

    // out0 = 0.1*leaky(conv448(alg)) + leaky(conv448(feat)) — one dual kernel
    conv3x3_s1_dual<<<dim3(6, 12, 4), blk>>>(alg, feat, ff_w, ff_b, out0, 448, 64);

    // Down path (CO=8 chunks; channel-blocked staging)
    conv3x3_s2<8><<<dim3(6, 6, 8), blk>>>(out0, dn1_w, dn1_b, out1, 64, 64, 192, 192, 96, 96);
    conv3x3_s2<8><<<dim3(3, 3, 8), blk>>>(out1, dn2_w, dn2_b, out2, 64, 64, 96, 96, 48, 48);
    conv3x3_s2<8><<<dim3(2, 2, 8), blk>>>(out2, tr_cw, tr_cb, u24, 64, 64, 48, 48, 24, 24);

    // Up path with skip concats (convT CO=16, channel-blocked staging)
    convT4x4_s2<16><<<dim3(3, 3, 4), blk>>>(u24, tr_tw, tr_tb, cat48, 64, 64, 24, 24, 48, 48);
    cudaMemcpyAsync(cat48 + (size_t)64 * 48 * 48, out2,
                    (size_t)64 * 48 * 48 * sizeof(float), cudaMemcpyDeviceToDevice, 0);
    conv3x3_s1<8><<<dim3(2, 3, 4), blk>>>(cat48, up2_cw, up2_cb, c48, 128, 64, 48, 48, 4, EP_RELU);
    convT4x4_s2<16><<<dim3(6, 6, 4), blk>>>(c48, up2_tw, up2_tb, cat96, 64, 64, 48, 48, 96, 96);
    cudaMemcpyAsync(cat96 + (size_t)64 * 96 * 96, out1,
                    (size_t)64 * 96 * 96 * sizeof(float), cudaMemcpyDeviceToDevice, 0);
    conv3x3_s1<8><<<dim3(3, 6, 4), blk>>>(cat96, up1_cw, up1_cb, c96, 128, 64, 96, 96, 4, EP_RELU);
    convT4x4_s2<16><<<dim3(12, 12, 4), blk>>>(c96, up1_tw, up1_tb, featf, 64, 64, 96, 96, 192, 192);

    // Offsets + masks (Cout=189 -> 6 chunks of 32)
    conv3x3_s1<16><<<dim3(6, 12, 6), blk>>>(featf, om_w, om_b, offm, 64, 189, 192, 192, 6, EP_NONE);

    // Modulated deformable conv + ReLU -> output
    deform_kernel<<<HW0 / 256, blk>>>(lqs, offm, dc_w, dc_b, outp);
}

// round 11
// speedup vs baseline: 1.5811x; 1.1823x over previous
#include <cuda_runtime.h>
#include <math.h>
#include <stdint.h>

// ---------------------------------------------------------------------------
// Problem constants
// ---------------------------------------------------------------------------
#define NF 64
#define TT 7
#define H0 192
#define W0 192
#define HW0 (H0 * W0)

// ---------------------------------------------------------------------------
// Scratch layout (single static device buffer; no allocations anywhere)
// ---------------------------------------------------------------------------
#define BIGSZ (7 * 64 * HW0)
#define OFF_FEAT   0
#define OFF_PRED   (OFF_FEAT + BIGSZ)
#define OFF_ALG    (OFF_PRED + BIGSZ)           // conv1 scratch (lqs) / aligned
#define OFF_ALG2   (OFF_ALG + BIGSZ)            // conv1 scratch (preds)
#define OFF_OUT0   (OFF_ALG2 + BIGSZ)
#define OFF_OUT1   (OFF_OUT0 + 64 * HW0)
#define OFF_OUT2   (OFF_OUT1 + 64 * 96 * 96)
#define OFF_U24    (OFF_OUT2 + 64 * 48 * 48)
#define OFF_CAT48  (OFF_U24 + 64 * 24 * 24)
#define OFF_C48    (OFF_CAT48 + 128 * 48 * 48)
#define OFF_CAT96  (OFF_C48 + 64 * 48 * 48)
#define OFF_C96    (OFF_CAT96 + 128 * 96 * 96)
#define OFF_FEATF  (OFF_C96 + 64 * 96 * 96)
#define OFF_OFFM   (OFF_FEATF + 64 * HW0)
#define SCRATCH_TOTAL (OFF_OFFM + 189 * HW0)

__device__ float g_scratch[SCRATCH_TOTAL];

enum { EP_NONE = 0, EP_RELU = 1 };

// ---------------------------------------------------------------------------
// Packed f32x2 helpers (Blackwell FFMA2 path)
// ---------------------------------------------------------------------------
typedef unsigned long long ull_t;
__device__ __forceinline__ ull_t pack2s(float v) {
    ull_t r;
    asm("mov.b64 %0, {%1, %1};" : "=l"(r) : "f"(v));
    return r;
}
__device__ __forceinline__ ull_t pack2(float lo, float hi) {
    ull_t r;
    asm("mov.b64 %0, {%1, %2};" : "=l"(r) : "f"(lo), "f"(hi));
    return r;
}
__device__ __forceinline__ void ffma2(ull_t& d, ull_t a, ull_t b) {
    asm("fma.rn.f32x2 %0, %1, %2, %0;" : "+l"(d) : "l"(a), "l"(b));
}
__device__ __forceinline__ float2 unpack2(ull_t v) {
    float lo, hi;
    asm("mov.b64 {%0, %1}, %2;" : "=f"(lo), "=f"(hi) : "l"(v));
    return make_float2(lo, hi);
}
__device__ __forceinline__ float fsigmoid(float x) {
    return 1.f / (1.f + __expf(-x));
}

// ---------------------------------------------------------------------------
// cp.async helpers (zero-fill when invalid via src-size = 0)
// ---------------------------------------------------------------------------
__device__ __forceinline__ uint32_t smem_u32(const void* p) {
    return (uint32_t)__cvta_generic_to_shared(p);
}
__device__ __forceinline__ void cp_async4(uint32_t s, const float* g, bool ok) {
    asm volatile("cp.async.ca.shared.global [%0], [%1], 4, %2;"
                 :: "r"(s), "l"(g), "r"(ok ? 4u : 0u));
}
__device__ __forceinline__ void cp_async16(uint32_t s, const float* g, bool ok) {
    asm volatile("cp.async.cg.shared.global [%0], [%1], 16, %2;"
                 :: "r"(s), "l"(g), "r"(ok ? 16u : 0u));
}
#define CP_COMMIT() asm volatile("cp.async.commit_group;")
#define CP_WAIT0()  asm volatile("cp.async.wait_group 0;")

// ---------------------------------------------------------------------------
// 3x3 stride-1 pad-1 conv, FFMA2, 256 threads, cp.async double-buffered,
// 16-byte vectorized interior staging.
// Output tile 32x16: thread = 2 x-adjacent px (tx 0..15) x row (ty 0..15).
// NP f32x2 cout-pairs per chunk (CO = 2*NP).
// Input tile stored at column offset +3 in a 40-float row so the 32 interior
// columns (p=1..32, global x = ox0..ox0+31) are 16B-aligned.
// Requires W % 4 == 0 (true: 192/96/48).
// ---------------------------------------------------------------------------
#define CB4 4
#define SMC 40
template <int NP>
__global__ void __launch_bounds__(256, NP == 8 ? 3 : 2) conv3x3_s1(
    const float* __restrict__ in, const float* __restrict__ wgt,
    const float* __restrict__ bias, float* __restrict__ out,
    int Cin, int Cout, int H, int W, int nChunks, int ep)
{
    const int CO = 2 * NP;
    __shared__ alignas(16) float s_in[2][CB4][18][SMC];
    __shared__ alignas(16) float s_w[2][CB4][9][2 * NP];

    const int img   = blockIdx.z / nChunks;
    const int chunk = blockIdx.z % nChunks;
    const int ox0 = blockIdx.x * 32, oy0 = blockIdx.y * 16;
    const int tid = threadIdx.x;
    const int tx = tid & 15, ty = tid >> 4;
    const float* inB = in + (size_t)img * Cin * H * W;
    const int coBase = chunk * CO;

    ull_t acc0[NP], acc1[NP];
#pragma unroll
    for (int j = 0; j < NP; j++) { acc0[j] = 0ull; acc1[j] = 0ull; }

    const int nB = (Cin + CB4 - 1) / CB4;

    auto stage = [&](int buf, int b) {
        const int c0 = b * CB4;
        const int nc = min(CB4, Cin - c0);
        // interior: 18 rows x 8 16B-chunks per ci (p=1..32 -> cols 4..35)
        for (int i = tid; i < nc * 144; i += 256) {
            int cb = i / 144, rem = i - cb * 144;
            int r = rem >> 3, k = rem & 7;
            int gy = oy0 - 1 + r;
            int gx = ox0 + 4 * k;
            bool ok = (gy >= 0 && gy < H) && (gx + 3 < W);
            cp_async16(smem_u32(&s_in[buf][cb][r][4 + 4 * k]),
                       inB + ((size_t)(c0 + cb) * H + (ok ? gy : 0)) * W + (ok ? gx : 0), ok);
        }
        // halo: 2 scalars per row (p=0 -> col 3, p=33 -> col 36)
        for (int i = tid; i < nc * 36; i += 256) {
            int cb = i / 36, rem = i - cb * 36;
            int r = rem >> 1, e = rem & 1;
            int gy = oy0 - 1 + r;
            int gx = e ? (ox0 + 32) : (ox0 - 1);
            int col = e ? 36 : 3;
            bool ok = (gy >= 0 && gy < H && gx >= 0 && gx < W);
            cp_async4(smem_u32(&s_in[buf][cb][r][col]),
                      inB + ((size_t)(c0 + cb) * H + (ok ? gy : 0)) * W + (ok ? gx : 0), ok);
        }
        // weights
        for (int i = tid; i < nc * 9 * CO; i += 256) {
            int cb = i / (9 * CO), rem = i - cb * (9 * CO);
            int co = rem / 9, t = rem - co * 9;
            int cog = coBase + co;
            bool ok = (cog < Cout);
            cp_async4(smem_u32(&s_w[buf][cb][t][co]),
                      wgt + ((size_t)(ok ? cog : 0) * Cin + (c0 + cb)) * 9 + t, ok);
        }
        CP_COMMIT();
    };

    stage(0, 0);
    for (int b = 0; b < nB; b++) {
        CP_WAIT0();
        __syncthreads();
        if (b + 1 < nB) stage((b + 1) & 1, b + 1);
        const int buf = b & 1;
        const int nc = min(CB4, Cin - b * CB4);
        for (int cb = 0; cb < nc; cb++) {
#pragma unroll
            for (int dy = 0; dy < 3; dy++) {
                ull_t ps[4];
#pragma unroll
                for (int j = 0; j < 4; j++)
                    ps[j] = pack2s(s_in[buf][cb][ty + dy][2 * tx + j + 3]);
#pragma unroll
                for (int dx = 0; dx < 3; dx++) {
                    const int t = dy * 3 + dx;
#pragma unroll
                    for (int q2 = 0; q2 < NP / 2; q2++) {
                        ulonglong2 w = *reinterpret_cast<const ulonglong2*>(&s_w[buf][cb][t][4 * q2]);
                        ffma2(acc0[2 * q2],     ps[dx],     w.x);
                        ffma2(acc0[2 * q2 + 1], ps[dx],     w.y);
                        ffma2(acc1[2 * q2],     ps[dx + 1], w.x);
                        ffma2(acc1[2 * q2 + 1], ps[dx + 1], w.y);
                    }
                }
            }
        }
    }

    const int oy = oy0 + ty, oxb = ox0 + 2 * tx;
    if (oy >= H || oxb >= W) return;
    const size_t HWs = (size_t)H * W;
    float* ob = out + (size_t)img * Cout * HWs + (size_t)oy * W + oxb;

#pragma unroll
    for (int j = 0; j < NP; j++) {
        float2 u0 = unpack2(acc0[j]), u1 = unpack2(acc1[j]);
#pragma unroll
        for (int s = 0; s < 2; s++) {
            int cog = coBase + 2 * j + s;
            if (cog >= Cout) continue;
            float b = __ldg(bias + cog);
            float2 o;
            o.x = (s ? u0.y : u0.x) + b;
            o.y = (s ? u1.y : u1.x) + b;
            if (ep == EP_RELU) { o.x = fmaxf(o.x, 0.f); o.y = fmaxf(o.y, 0.f); }
            *reinterpret_cast<float2*>(ob + (size_t)cog * HWs) = o;
        }
    }
}

// ---------------------------------------------------------------------------
// Dual-input shared-weight 3x3 conv (fusion pair), cp.async double-buffered,
// 16B vectorized staging: out = 0.1*leaky(conv(inA)+b) + leaky(conv(inF)+b)
// ---------------------------------------------------------------------------
__global__ void __launch_bounds__(256, 2) conv3x3_s1_dual(
    const float* __restrict__ inA, const float* __restrict__ inF,
    const float* __restrict__ wgt, const float* __restrict__ bias,
    float* __restrict__ out, int Cin, int Cout)
{
    __shared__ alignas(16) float s_a[2][CB4][18][SMC];
    __shared__ alignas(16) float s_f[2][CB4][18][SMC];
    __shared__ alignas(16) float s_w[2][CB4][9][16];

    const int chunk = blockIdx.z;
    const int ox0 = blockIdx.x * 32, oy0 = blockIdx.y * 16;
    const int tid = threadIdx.x;
    const int tx = tid & 15, ty = tid >> 4;
    const int coBase = chunk * 16;
    const int H = H0, W = W0;

    ull_t aA0[8], aA1[8], aF0[8], aF1[8];
#pragma unroll
    for (int j = 0; j < 8; j++) { aA0[j] = aA1[j] = aF0[j] = aF1[j] = 0ull; }

    const int nB = (Cin + CB4 - 1) / CB4;

    auto stage = [&](int buf, int b) {
        const int c0 = b * CB4;
        const int nc = min(CB4, Cin - c0);
        for (int i = tid; i < nc * 144; i += 256) {
            int cb = i / 144, rem = i - cb * 144;
            int r = rem >> 3, k = rem & 7;
            int gy = oy0 - 1 + r;
            int gx = ox0 + 4 * k;
            bool ok = (gy >= 0 && gy < H) && (gx + 3 < W);
            size_t gidx = ((size_t)(c0 + cb) * H + (ok ? gy : 0)) * W + (ok ? gx : 0);
            cp_async16(smem_u32(&s_a[buf][cb][r][4 + 4 * k]), inA + gidx, ok);
            cp_async16(smem_u32(&s_f[buf][cb][r][4 + 4 * k]), inF + gidx, ok);
        }
        for (int i = tid; i < nc * 36; i += 256) {
            int cb = i / 36, rem = i - cb * 36;
            int r = rem >> 1, e = rem & 1;
            int gy = oy0 - 1 + r;
            int gx = e ? (ox0 + 32) : (ox0 - 1);
            int col = e ? 36 : 3;
            bool ok = (gy >= 0 && gy < H && gx >= 0 && gx < W);
            size_t gidx = ((size_t)(c0 + cb) * H + (ok ? gy : 0)) * W + (ok ? gx : 0);
            cp_async4(smem_u32(&s_a[buf][cb][r][col]), inA + gidx, ok);
            cp_async4(smem_u32(&s_f[buf][cb][r][col]), inF + gidx, ok);
        }
        for (int i = tid; i < nc * 144; i += 256) {
            int cb = i / 144, rem = i - cb * 144;
            int co = rem / 9, t = rem - co * 9;
            cp_async4(smem_u32(&s_w[buf][cb][t][co]),
                      wgt + ((size_t)(coBase + co) * Cin + (c0 + cb)) * 9 + t, true);
        }
        CP_COMMIT();
    };

    stage(0, 0);
    for (int b = 0; b < nB; b++) {
        CP_WAIT0();
        __syncthreads();
        if (b + 1 < nB) stage((b + 1) & 1, b + 1);
        const int buf = b & 1;
        const int nc = min(CB4, Cin - b * CB4);
        for (int cb = 0; cb < nc; cb++) {
#pragma unroll
            for (int dy = 0; dy < 3; dy++) {
                ull_t pa[4], pf[4];
#pragma unroll
                for (int j = 0; j < 4; j++) {
                    pa[j] = pack2s(s_a[buf][cb][ty + dy][2 * tx + j + 3]);
                    pf[j] = pack2s(s_f[buf][cb][ty + dy][2 * tx + j + 3]);
                }
#pragma unroll
                for (int dx = 0; dx < 3; dx++) {
                    const int t = dy * 3 + dx;
#pragma unroll
                    for (int q2 = 0; q2 < 4; q2++) {
                        ulonglong2 w = *reinterpret_cast<const ulonglong2*>(&s_w[buf][cb][t][4 * q2]);
                        ffma2(aA0[2 * q2],     pa[dx],     w.x);
                        ffma2(aA0[2 * q2 + 1], pa[dx],     w.y);
                        ffma2(aA1[2 * q2],     pa[dx + 1], w.x);
                        ffma2(aA1[2 * q2 + 1], pa[dx + 1], w.y);
                        ffma2(aF0[2 * q2],     pf[dx],     w.x);
                        ffma2(aF0[2 * q2 + 1], pf[dx],     w.y);
                        ffma2(aF1[2 * q2],     pf[dx + 1], w.x);
                        ffma2(aF1[2 * q2 + 1], pf[dx + 1], w.y);
                    }
                }
            }
        }
    }

    const int oy = oy0 + ty, oxb = ox0 + 2 * tx;
    const size_t HWs = (size_t)H * W;
    float* ob = out + (size_t)oy * W + oxb;

#pragma unroll
    for (int j = 0; j < 8; j++) {
        float2 A0 = unpack2(aA0[j]), A1 = unpack2(aA1[j]);
        float2 F0 = unpack2(aF0[j]), F1 = unpack2(aF1[j]);
#pragma unroll
        for (int s = 0; s < 2; s++) {
            int cog = coBase + 2 * j + s;
            float b = __ldg(bias + cog);
            float va0 = (s ? A0.y : A0.x) + b;
            float va1 = (s ? A1.y : A1.x) + b;
            float vf0 = (s ? F0.y : F0.x) + b;
            float vf1 = (s ? F1.y : F1.x) + b;
            va0 = va0 > 0.f ? va0 : 0.1f * va0;
            va1 = va1 > 0.f ? va1 : 0.1f * va1;
            vf0 = vf0 > 0.f ? vf0 : 0.1f * vf0;
            vf1 = vf1 > 0.f ? vf1 : 0.1f * vf1;
            float2 o = make_float2(0.1f * va0 + vf0, 0.1f * va1 + vf1);
            *reinterpret_cast<float2*>(ob + (size_t)cog * HWs) = o;
        }
    }
}

// ---------------------------------------------------------------------------
// 3x3 stride-2 pad-1 conv. Output tile 16x16, 1 px/thread. 8 cis per sync.
// ---------------------------------------------------------------------------
#define SCB 8
template <int CO>
__global__ void __launch_bounds__(256) conv3x3_s2(
    const float* __restrict__ in, const float* __restrict__ wgt,
    const float* __restrict__ bias, float* __restrict__ out,
    int Cin, int Cout, int Hin, int Win, int Hout, int Wout)
{
    __shared__ float s_in[SCB][33][33];
    __shared__ alignas(16) float s_w[SCB][9][CO];

    const int chunk = blockIdx.z;
    const int ox0 = blockIdx.x * 16, oy0 = blockIdx.y * 16;
    const int tid = threadIdx.x, tx = tid & 15, ty = tid >> 4;
    const int coBase = chunk * CO;

    float acc[CO];
#pragma unroll
    for (int i = 0; i < CO; i++) acc[i] = 0.f;

    for (int c0 = 0; c0 < Cin; c0 += SCB) {
        const int nc = min(SCB, Cin - c0);
        for (int i = tid; i < nc * 1089; i += 256) {
            int cb = i / 1089, rem = i - cb * 1089;
            int r = rem / 33, c = rem - r * 33;
            int gy = 2 * oy0 - 1 + r, gx = 2 * ox0 - 1 + c;
            s_in[cb][r][c] = (gy >= 0 && gy < Hin && gx >= 0 && gx < Win)
                ? __ldg(in + ((size_t)(c0 + cb) * Hin + gy) * Win + gx) : 0.f;
        }
        for (int i = tid; i < nc * 9 * CO; i += 256) {
            int cb = i / (9 * CO), rem = i - cb * (9 * CO);
            int co = rem / 9, t = rem - co * 9;
            int cog = coBase + co;
            s_w[cb][t][co] = (cog < Cout)
                ? __ldg(wgt + ((size_t)cog * Cin + (c0 + cb)) * 9 + t) : 0.f;
        }
        __syncthreads();

        for (int cb = 0; cb < nc; cb++) {
            float v[9];
#pragma unroll
            for (int t = 0; t < 9; t++) v[t] = s_in[cb][2 * ty + t / 3][2 * tx + t % 3];
#pragma unroll
            for (int t = 0; t < 9; t++) {
#pragma unroll
                for (int q = 0; q < CO / 4; q++) {
                    float4 w = *reinterpret_cast<const float4*>(&s_w[cb][t][4 * q]);
                    acc[4 * q + 0] += v[t] * w.x; acc[4 * q + 1] += v[t] * w.y;
                    acc[4 * q + 2] += v[t] * w.z; acc[4 * q + 3] += v[t] * w.w;
                }
            }
        }
        __syncthreads();
    }

    const int ox = ox0 + tx, oy = oy0 + ty;
    if (ox >= Wout || oy >= Hout) return;
    size_t pbase = (size_t)oy * Wout + ox;
#pragma unroll
    for (int co = 0; co < CO; co++) {
        int cog = coBase + co;
        if (cog >= Cout) break;
        float v = acc[co] + __ldg(bias + cog);
        out[(size_t)cog * Hout * Wout + pbase] = fmaxf(v, 0.f);
    }
}

// ---------------------------------------------------------------------------
// ConvTranspose2d: kernel 4, stride 2, pad 1. Always ReLU. 8 cis per sync.
// ---------------------------------------------------------------------------
template <int CO>
__global__ void __launch_bounds__(256) convT4x4_s2(
    const float* __restrict__ in, const float* __restrict__ wgt,
    const float* __restrict__ bias, float* __restrict__ out,
    int Cin, int Cout, int Hin, int Win, int Hout, int Wout)
{
    __shared__ float s_in[SCB][10][10];
    __shared__ alignas(16) float s_w[SCB][16][CO];

    const int chunk = blockIdx.z;
    const int ox0 = blockIdx.x * 16, oy0 = blockIdx.y * 16;
    const int tid = threadIdx.x, tx = tid & 15, ty = tid >> 4;
    const int coBase = chunk * CO;
    const int iy0 = oy0 / 2 - 1, ix0 = ox0 / 2 - 1;

    const int oy = oy0 + ty, ox = ox0 + tx;
    const int py = (oy + 1) & 1, px = (ox + 1) & 1;
    const int r0 = ((oy + 1 - py) >> 1) - iy0;
    const int r1 = r0 - 1;
    const int c0i = ((ox + 1 - px) >> 1) - ix0;
    const int c1i = c0i - 1;

    float acc[CO];
#pragma unroll
    for (int i = 0; i < CO; i++) acc[i] = 0.f;

    for (int c0 = 0; c0 < Cin; c0 += SCB) {
        const int nc = min(SCB, Cin - c0);
        for (int i = tid; i < nc * 100; i += 256) {
            int cb = i / 100, rem = i - cb * 100;
            int r = rem / 10, c = rem - r * 10;
            int gy = iy0 + r, gx = ix0 + c;
            s_in[cb][r][c] = (gy >= 0 && gy < Hin && gx >= 0 && gx < Win)
                ? __ldg(in + ((size_t)(c0 + cb) * Hin + gy) * Win + gx) : 0.f;
        }
        for (int i = tid; i < nc * 16 * CO; i += 256) {
            int cb = i / (16 * CO), rem = i - cb * (16 * CO);
            int co = rem / 16, t = rem - co * 16;
            int cog = coBase + co;
            s_w[cb][t][co] = (cog < Cout)
                ? __ldg(wgt + ((size_t)(c0 + cb) * Cout + cog) * 16 + t) : 0.f;
        }
        __syncthreads();

        for (int cb = 0; cb < nc; cb++) {
            float v00 = s_in[cb][r0][c0i], v01 = s_in[cb][r0][c1i];
            float v10 = s_in[cb][r1][c0i], v11 = s_in[cb][r1][c1i];
#pragma unroll
            for (int a = 0; a < 2; a++) {
#pragma unroll
                for (int b = 0; b < 2; b++) {
                    float v = a ? (b ? v11 : v10) : (b ? v01 : v00);
                    int t = (py + 2 * a) * 4 + (px + 2 * b);
#pragma unroll
                    for (int q = 0; q < CO / 4; q++) {
                        float4 w = *reinterpret_cast<const float4*>(&s_w[cb][t][4 * q]);
                        acc[4 * q + 0] += v * w.x; acc[4 * q + 1] += v * w.y;
                        acc[4 * q + 2] += v * w.z; acc[4 * q + 3] += v * w.w;
                    }
                }
            }
        }
        __syncthreads();
    }

    if (ox >= Wout || oy >= Hout) return;
    size_t pbase = (size_t)oy * Wout + ox;
#pragma unroll
    for (int co = 0; co < CO; co++) {
        int cog = coBase + co;
        if (cog >= Cout) break;
        float v = acc[co] + __ldg(bias + cog);
        out[(size_t)cog * Hout * Wout + pbase] = fmaxf(v, 0.f);
    }
}

// ---------------------------------------------------------------------------
// Flow warp
// ---------------------------------------------------------------------------
__global__ void flow_warp_kernel(const float* __restrict__ feat,
                                 const float* __restrict__ mv,
                                 float* __restrict__ alg)
{
    const int pix = blockIdx.x * 256 + threadIdx.x;
    if (pix >= HW0) return;
    const int t = blockIdx.y;
    const int y = pix / W0, x = pix - y * W0;

    const float fx = mv[(size_t)t * HW0 * 2 + (size_t)pix * 2 + 0];
    const float fy = mv[(size_t)t * HW0 * 2 + (size_t)pix * 2 + 1];
    const float ys = (float)y + fy;
    const float xs = (float)x + fx;
    const float y0 = floorf(ys), x0 = floorf(xs);
    const float wy = ys - y0, wx = xs - x0;

    float wgt[4]; int off[4]; bool val[4];
#pragma unroll
    for (int i = 0; i < 4; i++) {
        int dy = i >> 1, dx = i & 1;
        float yi = y0 + dy, xi = x0 + dx;
        val[i] = (yi >= 0.f) && (yi <= (float)(H0 - 1)) &&
                 (xi >= 0.f) && (xi <= (float)(W0 - 1));
        wgt[i] = (dy ? wy : 1.f - wy) * (dx ? wx : 1.f - wx);
        off[i] = val[i] ? ((int)yi * W0 + (int)xi) : 0;
    }

    const float* fb = feat + (size_t)t * 64 * HW0;
    float* ob = alg + (size_t)(t + 1) * 64 * HW0 + pix;
    for (int c = 0; c < 64; c++) {
        const float* img = fb + (size_t)c * HW0;
        float acc = 0.f;
#pragma unroll
        for (int i = 0; i < 4; i++)
            if (val[i]) acc += __ldg(img + off[i]) * wgt[i];
        ob[(size_t)c * HW0] = acc;
    }
}

// ---------------------------------------------------------------------------
// Gated fusion, float4 + __expf
// ---------------------------------------------------------------------------
__global__ void fuse_gate_kernel(const float* __restrict__ feat,
                                 const float* __restrict__ pred,
                                 float* __restrict__ alg)
{
    const size_t N4 = (size_t)7 * 64 * HW0 / 4;
    size_t i = (size_t)blockIdx.x * 256 + threadIdx.x;
    if (i >= N4) return;
    size_t rem = i % ((size_t)64 * HW0 / 4);
    float4 ref = reinterpret_cast<const float4*>(feat + (size_t)3 * 64 * HW0)[rem];
    float4 a = reinterpret_cast<float4*>(alg)[i];
    float4 p = reinterpret_cast<const float4*>(pred)[i];
    float4 o;
    o.x = a.x * fsigmoid(a.x * ref.x) + p.x * fsigmoid(p.x * ref.x);
    o.y = a.y * fsigmoid(a.y * ref.y) + p.y * fsigmoid(p.y * ref.y);
    o.z = a.z * fsigmoid(a.z * ref.z) + p.z * fsigmoid(p.z * ref.z);
    o.w = a.w * fsigmoid(a.w * ref.w) + p.w * fsigmoid(p.w * ref.w);
    reinterpret_cast<float4*>(alg)[i] = o;
}

// ---------------------------------------------------------------------------
// Modulated deformable conv, FFMA2 accumulators + __expf sigmoid.
// ---------------------------------------------------------------------------
__global__ void __launch_bounds__(256) deform_kernel(
    const float* __restrict__ lqs, const float* __restrict__ offm,
    const float* __restrict__ dcw, const float* __restrict__ dcb,
    float* __restrict__ out)
{
    __shared__ alignas(16) float s_w[63 * 64];  // [j][o]
    __shared__ float s_b[64];
    const int tid = threadIdx.x;
    for (int i = tid; i < 63 * 64; i += 256) {
        int o = i / 63, j = i - o * 63;
        s_w[j * 64 + o] = dcw[i];
    }
    if (tid < 64) s_b[tid] = dcb[tid];
    __syncthreads();

    const int pix = blockIdx.x * 256 + tid;
    if (pix >= HW0) return;
    const int y = pix / W0, x = pix - y * W0;

    ull_t acc[32];
#pragma unroll
    for (int q = 0; q < 32; q++) acc[q] = pack2(s_b[2 * q], s_b[2 * q + 1]);

    for (int g = 0; g < 7; g++) {
        const float* img = lqs + (size_t)g * HW0;
#pragma unroll
        for (int k = 0; k < 9; k++) {
            const int j = g * 9 + k;
            float offy = __ldg(offm + (size_t)(g * 18 + 2 * k + 0) * HW0 + pix);
            float offx = __ldg(offm + (size_t)(g * 18 + 2 * k + 1) * HW0 + pix);
            float mraw = __ldg(offm + (size_t)(126 + j) * HW0 + pix);
            float m = fsigmoid(mraw);
            float ys = (float)(y + k / 3 - 1) + offy;
            float xs = (float)(x + k % 3 - 1) + offx;
            float y0 = floorf(ys), x0 = floorf(xs);
            float wy = ys - y0, wx = xs - x0;
            float samp = 0.f;
#pragma unroll
            for (int ii = 0; ii < 4; ii++) {
                int dy = ii >> 1, dx = ii & 1;
                float yi = y0 + dy, xi = x0 + dx;
                if (yi >= 0.f && yi <= (float)(H0 - 1) &&
                    xi >= 0.f && xi <= (float)(W0 - 1))
                    samp += __ldg(img + (int)yi * W0 + (int)xi) *
                            ((dy ? wy : 1.f - wy) * (dx ? wx : 1.f - wx));
            }
            ull_t mod2 = pack2s(samp * m);
#pragma unroll
            for (int q2 = 0; q2 < 16; q2++) {
                ulonglong2 w = *reinterpret_cast<const ulonglong2*>(&s_w[j * 64 + 4 * q2]);
                ffma2(acc[2 * q2],     mod2, w.x);
                ffma2(acc[2 * q2 + 1], mod2, w.y);
            }
        }
    }
#pragma unroll
    for (int q = 0; q < 32; q++) {
        float2 u = unpack2(acc[q]);
        out[(size_t)(2 * q) * HW0 + pix]     = fmaxf(u.x, 0.f);
        out[(size_t)(2 * q + 1) * HW0 + pix] = fmaxf(u.y, 0.f);
    }
}

// ---------------------------------------------------------------------------
// Host orchestration (graph-capturable)
// ---------------------------------------------------------------------------
extern "C" void kernel_launch(void* const* d_in, const int* in_sizes, int n_in,
                              void* d_out, int out_size)
{
    const float* lqs    = (const float*)d_in[0];
    const float* preds  = (const float*)d_in[1];
    const float* mv     = (const float*)d_in[2];
    const float* bw1    = (const float*)d_in[3];
    const float* bb1    = (const float*)d_in[4];
    const float* bw2    = (const float*)d_in[5];
    const float* bb2    = (const float*)d_in[6];
    const float* dn1_w  = (const float*)d_in[7];
    const float* dn1_b  = (const float*)d_in[8];
    const float* dn2_w  = (const float*)d_in[9];
    const float* dn2_b  = (const float*)d_in[10];
    const float* up1_cw = (const float*)d_in[11];
    const float* up1_cb = (const float*)d_in[12];
    const float* up1_tw = (const float*)d_in[13];
    const float* up1_tb = (const float*)d_in[14];
    const float* up2_cw = (const float*)d_in[15];
    const float* up2_cb = (const float*)d_in[16];
    const float* up2_tw = (const float*)d_in[17];
    const float* up2_tb = (const float*)d_in[18];
    const float* tr_cw  = (const float*)d_in[19];
    const float* tr_cb  = (const float*)d_in[20];
    const float* tr_tw  = (const float*)d_in[21];
    const float* tr_tb  = (const float*)d_in[22];
    const float* ff_w   = (const float*)d_in[23];
    const float* ff_b   = (const float*)d_in[24];
    const float* om_w   = (const float*)d_in[25];
    const float* om_b   = (const float*)d_in[26];
    const float* dc_w   = (const float*)d_in[27];
    const float* dc_b   = (const float*)d_in[28];
    float* outp = (float*)d_out;

    float* S = nullptr;
    cudaGetSymbolAddress((void**)&S, g_scratch);
    float* feat  = S + OFF_FEAT;   // conv2 out: imgs 0..6 (lqs)
    float* pred  = S + OFF_PRED;   // conv2 out: imgs 7..13 (preds)
    float* alg   = S + OFF_ALG;    // conv1 scratch (lqs), later aligned buffer
    float* alg2  = S + OFF_ALG2;   // conv1 scratch (preds)
    float* out0  = S + OFF_OUT0;
    float* out1  = S + OFF_OUT1;
    float* out2  = S + OFF_OUT2;
    float* u24   = S + OFF_U24;
    float* cat48 = S + OFF_CAT48;
    float* c48   = S + OFF_C48;
    float* cat96 = S + OFF_CAT96;
    float* c96   = S + OFF_C96;
    float* featf = S + OFF_FEATF;
    float* offm  = S + OFF_OFFM;

    dim3 blk(256);

    // Backbone conv1 (1->64) on lqs and preds -> contiguous scratch [alg|alg2]
    conv3x3_s1<8><<<dim3(6, 12, 7 * 4), blk>>>(lqs,   bw1, bb1, alg,  1, 64, 192, 192, 4, EP_NONE);
    conv3x3_s1<8><<<dim3(6, 12, 7 * 4), blk>>>(preds, bw1, bb1, alg2, 1, 64, 192, 192, 4, EP_NONE);
    // Backbone conv2 (64->64), 14 images in ONE launch -> [feat|pred]
    conv3x3_s1<8><<<dim3(6, 12, 14 * 4), blk>>>(alg, bw2, bb2, feat, 64, 64, 192, 192, 4, EP_NONE);

    // aligned[0] = feat[0]; aligned[1..6] = warp(feat[0..5], mv)  (reuses alg)
    cudaMemcpyAsync(alg, feat, (size_t)64 * HW0 * sizeof(float),
                    cudaMemcpyDeviceToDevice, 0);
    flow_warp_kernel<<<dim3(HW0 / 256, 6), blk>>>(feat, mv, alg);

    // alg := a1 + a2 (gated), in place
    fuse_gate_kernel<<<(unsigned)(((size_t)7 * 64 * HW0 / 4 + 255) / 256), blk>>>(feat, pred, alg);

    // out0 = 0.1*leaky(conv448(alg)) + leaky(conv448(feat)) — one dual kernel
    conv3x3_s1_dual<<<dim3(6, 12, 4), blk>>>(alg, feat, ff_w, ff_b, out0, 448, 64);

    // Down path (CO=8 chunks; channel-blocked staging)
    conv3x3_s2<8><<<dim3(6, 6, 8), blk>>>(out0, dn1_w, dn1_b, out1, 64, 64, 192, 192, 96, 96);
    conv3x3_s2<8><<<dim3(3, 3, 8), blk>>>(out1, dn2_w, dn2_b, out2, 64, 64, 96, 96, 48, 48);
    conv3x3_s2<8><<<dim3(2, 2, 8), blk>>>(out2, tr_cw, tr_cb, u24, 64, 64, 48, 48, 24, 24);

    // Up path with skip concats (convT CO=16, channel-blocked staging)
    convT4x4_s2<16><<<dim3(3, 3, 4), blk>>>(u24, tr_tw, tr_tb, cat48, 64, 64, 24, 24, 48, 48);
    cudaMemcpyAsync(cat48 + (size_t)64 * 48 * 48, out2,
                    (size_t)64 * 48 * 48 * sizeof(float), cudaMemcpyDeviceToDevice, 0);
    conv3x3_s1<8><<<dim3(2, 3, 4), blk>>>(cat48, up2_cw, up2_cb, c48, 128, 64, 48, 48, 4, EP_RELU);
    convT4x4_s2<16><<<dim3(6, 6, 4), blk>>>(c48, up2_tw, up2_tb, cat96, 64, 64, 48, 48, 96, 96);
    cudaMemcpyAsync(cat96 + (size_t)64 * 96 * 96, out1,
                    (size_t)64 * 96 * 96 * sizeof(float), cudaMemcpyDeviceToDevice, 0);
    conv3x3_s1<8><<<dim3(3, 6, 4), blk>>>(cat96, up1_cw, up1_cb, c96, 128, 64, 96, 96, 4, EP_RELU);
    convT4x4_s2<16><<<dim3(12, 12, 4), blk>>>(c96, up1_tw, up1_tb, featf, 64, 64, 96, 96, 192, 192);

    // Offsets + masks (Cout=189 -> 12 chunks of 16)
    conv3x3_s1<8><<<dim3(6, 12, 12), blk>>>(featf, om_w, om_b, offm, 64, 189, 192, 192, 12, EP_NONE);

    // Modulated deformable conv + ReLU -> output
    deform_kernel<<<HW0 / 256, blk>>>(lqs, offm, dc_w, dc_b, outp);
}

// round 12
// speedup vs baseline: 1.5932x; 1.0076x over previous
#include <cuda_runtime.h>
#include <math.h>
#include <stdint.h>

// ---------------------------------------------------------------------------
// Problem constants
// ---------------------------------------------------------------------------
#define NF 64
#define TT 7
#define H0 192
#define W0 192
#define HW0 (H0 * W0)

// ---------------------------------------------------------------------------
// Scratch layout (single static device buffer; no allocations anywhere)
// ---------------------------------------------------------------------------
#define BIGSZ (7 * 64 * HW0)
#define OFF_FEAT   0
#define OFF_PRED   (OFF_FEAT + BIGSZ)
#define OFF_ALG    (OFF_PRED + BIGSZ)           // conv1 scratch (lqs) / aligned
#define OFF_ALG2   (OFF_ALG + BIGSZ)            // conv1 scratch (preds)
#define OFF_OUT0   (OFF_ALG2 + BIGSZ)
#define OFF_OUT1   (OFF_OUT0 + 64 * HW0)
#define OFF_OUT2   (OFF_OUT1 + 64 * 96 * 96)
#define OFF_U24    (OFF_OUT2 + 64 * 48 * 48)
#define OFF_CAT48  (OFF_U24 + 64 * 24 * 24)
#define OFF_C48    (OFF_CAT48 + 128 * 48 * 48)
#define OFF_CAT96  (OFF_C48 + 64 * 48 * 48)
#define OFF_C96    (OFF_CAT96 + 128 * 96 * 96)
#define OFF_FEATF  (OFF_C96 + 64 * 96 * 96)
#define OFF_OFFM   (OFF_FEATF + 64 * HW0)
#define SCRATCH_TOTAL (OFF_OFFM + 189 * HW0)

__device__ float g_scratch[SCRATCH_TOTAL];

enum { EP_NONE = 0, EP_RELU = 1 };

// ---------------------------------------------------------------------------
// Packed f32x2 helpers (Blackwell FFMA2 path)
// ---------------------------------------------------------------------------
typedef unsigned long long ull_t;
__device__ __forceinline__ ull_t pack2s(float v) {
    ull_t r;
    asm("mov.b64 %0, {%1, %1};" : "=l"(r) : "f"(v));
    return r;
}
__device__ __forceinline__ ull_t pack2(float lo, float hi) {
    ull_t r;
    asm("mov.b64 %0, {%1, %2};" : "=l"(r) : "f"(lo), "f"(hi));
    return r;
}
__device__ __forceinline__ void ffma2(ull_t& d, ull_t a, ull_t b) {
    asm("fma.rn.f32x2 %0, %1, %2, %0;" : "+l"(d) : "l"(a), "l"(b));
}
__device__ __forceinline__ float2 unpack2(ull_t v) {
    float lo, hi;
    asm("mov.b64 {%0, %1}, %2;" : "=f"(lo), "=f"(hi) : "l"(v));
    return make_float2(lo, hi);
}
__device__ __forceinline__ float fsigmoid(float x) {
    return 1.f / (1.f + __expf(-x));
}

// ---------------------------------------------------------------------------
// cp.async helpers (zero-fill when invalid via src-size = 0)
// ---------------------------------------------------------------------------
__device__ __forceinline__ uint32_t smem_u32(const void* p) {
    return (uint32_t)__cvta_generic_to_shared(p);
}
__device__ __forceinline__ void cp_async4(uint32_t s, const float* g, bool ok) {
    asm volatile("cp.async.ca.shared.global [%0], [%1], 4, %2;"
                 :: "r"(s), "l"(g), "r"(ok ? 4u : 0u));
}
__device__ __forceinline__ void cp_async16(uint32_t s, const float* g, bool ok) {
    asm volatile("cp.async.cg.shared.global [%0], [%1], 16, %2;"
                 :: "r"(s), "l"(g), "r"(ok ? 16u : 0u));
}
#define CP_COMMIT() asm volatile("cp.async.commit_group;")
#define CP_WAIT0()  asm volatile("cp.async.wait_group 0;")

// ---------------------------------------------------------------------------
// 3x3 stride-1 pad-1 conv, FFMA2, 256 threads, cp.async double-buffered,
// 16-byte vectorized interior staging. CBS=8 cis per buffer (fewer barriers).
// Output tile 32x16: thread = 2 x-adjacent px (tx 0..15) x row (ty 0..15).
// NP f32x2 cout-pairs per chunk (CO = 2*NP).
// Input tile stored at column offset +3 in a 40-float row so the 32 interior
// columns are 16B-aligned. Requires W % 4 == 0 (true: 192/96/48).
// ---------------------------------------------------------------------------
#define CBS 8
#define CB4 4
#define SMC 40
template <int NP>
__global__ void __launch_bounds__(256, NP == 8 ? 3 : 2) conv3x3_s1(
    const float* __restrict__ in, const float* __restrict__ wgt,
    const float* __restrict__ bias, float* __restrict__ out,
    int Cin, int Cout, int H, int W, int nChunks, int ep)
{
    const int CO = 2 * NP;
    __shared__ alignas(16) float s_in[2][CBS][18][SMC];
    __shared__ alignas(16) float s_w[2][CBS][9][2 * NP];

    const int img   = blockIdx.z / nChunks;
    const int chunk = blockIdx.z % nChunks;
    const int ox0 = blockIdx.x * 32, oy0 = blockIdx.y * 16;
    const int tid = threadIdx.x;
    const int tx = tid & 15, ty = tid >> 4;
    const float* inB = in + (size_t)img * Cin * H * W;
    const int coBase = chunk * CO;

    ull_t acc0[NP], acc1[NP];
#pragma unroll
    for (int j = 0; j < NP; j++) { acc0[j] = 0ull; acc1[j] = 0ull; }

    const int nB = (Cin + CBS - 1) / CBS;

    auto stage = [&](int buf, int b) {
        const int c0 = b * CBS;
        const int nc = min(CBS, Cin - c0);
        // interior: 18 rows x 8 16B-chunks per ci
        for (int i = tid; i < nc * 144; i += 256) {
            int cb = i / 144, rem = i - cb * 144;
            int r = rem >> 3, k = rem & 7;
            int gy = oy0 - 1 + r;
            int gx = ox0 + 4 * k;
            bool ok = (gy >= 0 && gy < H) && (gx + 3 < W);
            cp_async16(smem_u32(&s_in[buf][cb][r][4 + 4 * k]),
                       inB + ((size_t)(c0 + cb) * H + (ok ? gy : 0)) * W + (ok ? gx : 0), ok);
        }
        // halo: 2 scalars per row
        for (int i = tid; i < nc * 36; i += 256) {
            int cb = i / 36, rem = i - cb * 36;
            int r = rem >> 1, e = rem & 1;
            int gy = oy0 - 1 + r;
            int gx = e ? (ox0 + 32) : (ox0 - 1);
            int col = e ? 36 : 3;
            bool ok = (gy >= 0 && gy < H && gx >= 0 && gx < W);
            cp_async4(smem_u32(&s_in[buf][cb][r][col]),
                      inB + ((size_t)(c0 + cb) * H + (ok ? gy : 0)) * W + (ok ? gx : 0), ok);
        }
        // weights
        for (int i = tid; i < nc * 9 * CO; i += 256) {
            int cb = i / (9 * CO), rem = i - cb * (9 * CO);
            int co = rem / 9, t = rem - co * 9;
            int cog = coBase + co;
            bool ok = (cog < Cout);
            cp_async4(smem_u32(&s_w[buf][cb][t][co]),
                      wgt + ((size_t)(ok ? cog : 0) * Cin + (c0 + cb)) * 9 + t, ok);
        }
        CP_COMMIT();
    };

    stage(0, 0);
    for (int b = 0; b < nB; b++) {
        CP_WAIT0();
        __syncthreads();
        if (b + 1 < nB) stage((b + 1) & 1, b + 1);
        const int buf = b & 1;
        const int nc = min(CBS, Cin - b * CBS);
        for (int cb = 0; cb < nc; cb++) {
#pragma unroll
            for (int dy = 0; dy < 3; dy++) {
                ull_t ps[4];
#pragma unroll
                for (int j = 0; j < 4; j++)
                    ps[j] = pack2s(s_in[buf][cb][ty + dy][2 * tx + j + 3]);
#pragma unroll
                for (int dx = 0; dx < 3; dx++) {
                    const int t = dy * 3 + dx;
#pragma unroll
                    for (int q2 = 0; q2 < NP / 2; q2++) {
                        ulonglong2 w = *reinterpret_cast<const ulonglong2*>(&s_w[buf][cb][t][4 * q2]);
                        ffma2(acc0[2 * q2],     ps[dx],     w.x);
                        ffma2(acc0[2 * q2 + 1], ps[dx],     w.y);
                        ffma2(acc1[2 * q2],     ps[dx + 1], w.x);
                        ffma2(acc1[2 * q2 + 1], ps[dx + 1], w.y);
                    }
                }
            }
        }
    }

    const int oy = oy0 + ty, oxb = ox0 + 2 * tx;
    if (oy >= H || oxb >= W) return;
    const size_t HWs = (size_t)H * W;
    float* ob = out + (size_t)img * Cout * HWs + (size_t)oy * W + oxb;

#pragma unroll
    for (int j = 0; j < NP; j++) {
        float2 u0 = unpack2(acc0[j]), u1 = unpack2(acc1[j]);
#pragma unroll
        for (int s = 0; s < 2; s++) {
            int cog = coBase + 2 * j + s;
            if (cog >= Cout) continue;
            float b = __ldg(bias + cog);
            float2 o;
            o.x = (s ? u0.y : u0.x) + b;
            o.y = (s ? u1.y : u1.x) + b;
            if (ep == EP_RELU) { o.x = fmaxf(o.x, 0.f); o.y = fmaxf(o.y, 0.f); }
            *reinterpret_cast<float2*>(ob + (size_t)cog * HWs) = o;
        }
    }
}

// ---------------------------------------------------------------------------
// Dual-input shared-weight 3x3 conv (fusion pair), cp.async double-buffered,
// 16B vectorized staging: out = 0.1*leaky(conv(inA)+b) + leaky(conv(inF)+b)
// ---------------------------------------------------------------------------
__global__ void __launch_bounds__(256, 2) conv3x3_s1_dual(
    const float* __restrict__ inA, const float* __restrict__ inF,
    const float* __restrict__ wgt, const float* __restrict__ bias,
    float* __restrict__ out, int Cin, int Cout)
{
    __shared__ alignas(16) float s_a[2][CB4][18][SMC];
    __shared__ alignas(16) float s_f[2][CB4][18][SMC];
    __shared__ alignas(16) float s_w[2][CB4][9][16];

    const int chunk = blockIdx.z;
    const int ox0 = blockIdx.x * 32, oy0 = blockIdx.y * 16;
    const int tid = threadIdx.x;
    const int tx = tid & 15, ty = tid >> 4;
    const int coBase = chunk * 16;
    const int H = H0, W = W0;

    ull_t aA0[8], aA1[8], aF0[8], aF1[8];
#pragma unroll
    for (int j = 0; j < 8; j++) { aA0[j] = aA1[j] = aF0[j] = aF1[j] = 0ull; }

    const int nB = (Cin + CB4 - 1) / CB4;

    auto stage = [&](int buf, int b) {
        const int c0 = b * CB4;
        const int nc = min(CB4, Cin - c0);
        for (int i = tid; i < nc * 144; i += 256) {
            int cb = i / 144, rem = i - cb * 144;
            int r = rem >> 3, k = rem & 7;
            int gy = oy0 - 1 + r;
            int gx = ox0 + 4 * k;
            bool ok = (gy >= 0 && gy < H) && (gx + 3 < W);
            size_t gidx = ((size_t)(c0 + cb) * H + (ok ? gy : 0)) * W + (ok ? gx : 0);
            cp_async16(smem_u32(&s_a[buf][cb][r][4 + 4 * k]), inA + gidx, ok);
            cp_async16(smem_u32(&s_f[buf][cb][r][4 + 4 * k]), inF + gidx, ok);
        }
        for (int i = tid; i < nc * 36; i += 256) {
            int cb = i / 36, rem = i - cb * 36;
            int r = rem >> 1, e = rem & 1;
            int gy = oy0 - 1 + r;
            int gx = e ? (ox0 + 32) : (ox0 - 1);
            int col = e ? 36 : 3;
            bool ok = (gy >= 0 && gy < H && gx >= 0 && gx < W);
            size_t gidx = ((size_t)(c0 + cb) * H + (ok ? gy : 0)) * W + (ok ? gx : 0);
            cp_async4(smem_u32(&s_a[buf][cb][r][col]), inA + gidx, ok);
            cp_async4(smem_u32(&s_f[buf][cb][r][col]), inF + gidx, ok);
        }
        for (int i = tid; i < nc * 144; i += 256) {
            int cb = i / 144, rem = i - cb * 144;
            int co = rem / 9, t = rem - co * 9;
            cp_async4(smem_u32(&s_w[buf][cb][t][co]),
                      wgt + ((size_t)(coBase + co) * Cin + (c0 + cb)) * 9 + t, true);
        }
        CP_COMMIT();
    };

    stage(0, 0);
    for (int b = 0; b < nB; b++) {
        CP_WAIT0();
        __syncthreads();
        if (b + 1 < nB) stage((b + 1) & 1, b + 1);
        const int buf = b & 1;
        const int nc = min(CB4, Cin - b * CB4);
        for (int cb = 0; cb < nc; cb++) {
#pragma unroll
            for (int dy = 0; dy < 3; dy++) {
                ull_t pa[4], pf[4];
#pragma unroll
                for (int j = 0; j < 4; j++) {
                    pa[j] = pack2s(s_a[buf][cb][ty + dy][2 * tx + j + 3]);
                    pf[j] = pack2s(s_f[buf][cb][ty + dy][2 * tx + j + 3]);
                }
#pragma unroll
                for (int dx = 0; dx < 3; dx++) {
                    const int t = dy * 3 + dx;
#pragma unroll
                    for (int q2 = 0; q2 < 4; q2++) {
                        ulonglong2 w = *reinterpret_cast<const ulonglong2*>(&s_w[buf][cb][t][4 * q2]);
                        ffma2(aA0[2 * q2],     pa[dx],     w.x);
                        ffma2(aA0[2 * q2 + 1], pa[dx],     w.y);
                        ffma2(aA1[2 * q2],     pa[dx + 1], w.x);
                        ffma2(aA1[2 * q2 + 1], pa[dx + 1], w.y);
                        ffma2(aF0[2 * q2],     pf[dx],     w.x);
                        ffma2(aF0[2 * q2 + 1], pf[dx],     w.y);
                        ffma2(aF1[2 * q2],     pf[dx + 1], w.x);
                        ffma2(aF1[2 * q2 + 1], pf[dx + 1], w.y);
                    }
                }
            }
        }
    }

    const int oy = oy0 + ty, oxb = ox0 + 2 * tx;
    const size_t HWs = (size_t)H * W;
    float* ob = out + (size_t)oy * W + oxb;

#pragma unroll
    for (int j = 0; j < 8; j++) {
        float2 A0 = unpack2(aA0[j]), A1 = unpack2(aA1[j]);
        float2 F0 = unpack2(aF0[j]), F1 = unpack2(aF1[j]);
#pragma unroll
        for (int s = 0; s < 2; s++) {
            int cog = coBase + 2 * j + s;
            float b = __ldg(bias + cog);
            float va0 = (s ? A0.y : A0.x) + b;
            float va1 = (s ? A1.y : A1.x) + b;
            float vf0 = (s ? F0.y : F0.x) + b;
            float vf1 = (s ? F1.y : F1.x) + b;
            va0 = va0 > 0.f ? va0 : 0.1f * va0;
            va1 = va1 > 0.f ? va1 : 0.1f * va1;
            vf0 = vf0 > 0.f ? vf0 : 0.1f * vf0;
            vf1 = vf1 > 0.f ? vf1 : 0.1f * vf1;
            float2 o = make_float2(0.1f * va0 + vf0, 0.1f * va1 + vf1);
            *reinterpret_cast<float2*>(ob + (size_t)cog * HWs) = o;
        }
    }
}

// ---------------------------------------------------------------------------
// 3x3 stride-2 pad-1 conv. Output tile 16x16, 1 px/thread. 8 cis per sync.
// ---------------------------------------------------------------------------
#define SCB 8
template <int CO>
__global__ void __launch_bounds__(256) conv3x3_s2(
    const float* __restrict__ in, const float* __restrict__ wgt,
    const float* __restrict__ bias, float* __restrict__ out,
    int Cin, int Cout, int Hin, int Win, int Hout, int Wout)
{
    __shared__ float s_in[SCB][33][33];
    __shared__ alignas(16) float s_w[SCB][9][CO];

    const int chunk = blockIdx.z;
    const int ox0 = blockIdx.x * 16, oy0 = blockIdx.y * 16;
    const int tid = threadIdx.x, tx = tid & 15, ty = tid >> 4;
    const int coBase = chunk * CO;

    float acc[CO];
#pragma unroll
    for (int i = 0; i < CO; i++) acc[i] = 0.f;

    for (int c0 = 0; c0 < Cin; c0 += SCB) {
        const int nc = min(SCB, Cin - c0);
        for (int i = tid; i < nc * 1089; i += 256) {
            int cb = i / 1089, rem = i - cb * 1089;
            int r = rem / 33, c = rem - r * 33;
            int gy = 2 * oy0 - 1 + r, gx = 2 * ox0 - 1 + c;
            s_in[cb][r][c] = (gy >= 0 && gy < Hin && gx >= 0 && gx < Win)
                ? __ldg(in + ((size_t)(c0 + cb) * Hin + gy) * Win + gx) : 0.f;
        }
        for (int i = tid; i < nc * 9 * CO; i += 256) {
            int cb = i / (9 * CO), rem = i - cb * (9 * CO);
            int co = rem / 9, t = rem - co * 9;
            int cog = coBase + co;
            s_w[cb][t][co] = (cog < Cout)
                ? __ldg(wgt + ((size_t)cog * Cin + (c0 + cb)) * 9 + t) : 0.f;
        }
        __syncthreads();

        for (int cb = 0; cb < nc; cb++) {
            float v[9];
#pragma unroll
            for (int t = 0; t < 9; t++) v[t] = s_in[cb][2 * ty + t / 3][2 * tx + t % 3];
#pragma unroll
            for (int t = 0; t < 9; t++) {
#pragma unroll
                for (int q = 0; q < CO / 4; q++) {
                    float4 w = *reinterpret_cast<const float4*>(&s_w[cb][t][4 * q]);
                    acc[4 * q + 0] += v[t] * w.x; acc[4 * q + 1] += v[t] * w.y;
                    acc[4 * q + 2] += v[t] * w.z; acc[4 * q + 3] += v[t] * w.w;
                }
            }
        }
        __syncthreads();
    }

    const int ox = ox0 + tx, oy = oy0 + ty;
    if (ox >= Wout || oy >= Hout) return;
    size_t pbase = (size_t)oy * Wout + ox;
#pragma unroll
    for (int co = 0; co < CO; co++) {
        int cog = coBase + co;
        if (cog >= Cout) break;
        float v = acc[co] + __ldg(bias + cog);
        out[(size_t)cog * Hout * Wout + pbase] = fmaxf(v, 0.f);
    }
}

// ---------------------------------------------------------------------------
// ConvTranspose2d: kernel 4, stride 2, pad 1. Always ReLU. 8 cis per sync.
// ---------------------------------------------------------------------------
template <int CO>
__global__ void __launch_bounds__(256) convT4x4_s2(
    const float* __restrict__ in, const float* __restrict__ wgt,
    const float* __restrict__ bias, float* __restrict__ out,
    int Cin, int Cout, int Hin, int Win, int Hout, int Wout)
{
    __shared__ float s_in[SCB][10][10];
    __shared__ alignas(16) float s_w[SCB][16][CO];

    const int chunk = blockIdx.z;
    const int ox0 = blockIdx.x * 16, oy0 = blockIdx.y * 16;
    const int tid = threadIdx.x, tx = tid & 15, ty = tid >> 4;
    const int coBase = chunk * CO;
    const int iy0 = oy0 / 2 - 1, ix0 = ox0 / 2 - 1;

    const int oy = oy0 + ty, ox = ox0 + tx;
    const int py = (oy + 1) & 1, px = (ox + 1) & 1;
    const int r0 = ((oy + 1 - py) >> 1) - iy0;
    const int r1 = r0 - 1;
    const int c0i = ((ox + 1 - px) >> 1) - ix0;
    const int c1i = c0i - 1;

    float acc[CO];
#pragma unroll
    for (int i = 0; i < CO; i++) acc[i] = 0.f;

    for (int c0 = 0; c0 < Cin; c0 += SCB) {
        const int nc = min(SCB, Cin - c0);
        for (int i = tid; i < nc * 100; i += 256) {
            int cb = i / 100, rem = i - cb * 100;
            int r = rem / 10, c = rem - r * 10;
            int gy = iy0 + r, gx = ix0 + c;
            s_in[cb][r][c] = (gy >= 0 && gy < Hin && gx >= 0 && gx < Win)
                ? __ldg(in + ((size_t)(c0 + cb) * Hin + gy) * Win + gx) : 0.f;
        }
        for (int i = tid; i < nc * 16 * CO; i += 256) {
            int cb = i / (16 * CO), rem = i - cb * (16 * CO);
            int co = rem / 16, t = rem - co * 16;
            int cog = coBase + co;
            s_w[cb][t][co] = (cog < Cout)
                ? __ldg(wgt + ((size_t)(c0 + cb) * Cout + cog) * 16 + t) : 0.f;
        }
        __syncthreads();

        for (int cb = 0; cb < nc; cb++) {
            float v00 = s_in[cb][r0][c0i], v01 = s_in[cb][r0][c1i];
            float v10 = s_in[cb][r1][c0i], v11 = s_in[cb][r1][c1i];
#pragma unroll
            for (int a = 0; a < 2; a++) {
#pragma unroll
                for (int b = 0; b < 2; b++) {
                    float v = a ? (b ? v11 : v10) : (b ? v01 : v00);
                    int t = (py + 2 * a) * 4 + (px + 2 * b);
#pragma unroll
                    for (int q = 0; q < CO / 4; q++) {
                        float4 w = *reinterpret_cast<const float4*>(&s_w[cb][t][4 * q]);
                        acc[4 * q + 0] += v * w.x; acc[4 * q + 1] += v * w.y;
                        acc[4 * q + 2] += v * w.z; acc[4 * q + 3] += v * w.w;
                    }
                }
            }
        }
        __syncthreads();
    }

    if (ox >= Wout || oy >= Hout) return;
    size_t pbase = (size_t)oy * Wout + ox;
#pragma unroll
    for (int co = 0; co < CO; co++) {
        int cog = coBase + co;
        if (cog >= Cout) break;
        float v = acc[co] + __ldg(bias + cog);
        out[(size_t)cog * Hout * Wout + pbase] = fmaxf(v, 0.f);
    }
}

// ---------------------------------------------------------------------------
// Fused flow-warp + gate:
// t = 0:   a = feat[0][c]
// t >= 1:  a = bilinear(feat[t-1][c], pix + mv[t-1])
// alg[t][c] = a*sig(a*ref) + p*sig(p*ref),  ref = feat[3][c], p = pred[t][c]
// ---------------------------------------------------------------------------
__global__ void warp_gate_kernel(const float* __restrict__ feat,
                                 const float* __restrict__ pred,
                                 const float* __restrict__ mv,
                                 float* __restrict__ alg)
{
    const int pix = blockIdx.x * 256 + threadIdx.x;
    if (pix >= HW0) return;
    const int t = blockIdx.y;  // 0..6

    float wgt[4]; int off[4]; bool val[4];
    const float* fb = nullptr;
    if (t > 0) {
        const int y = pix / W0, x = pix - y * W0;
        const float fx = mv[(size_t)(t - 1) * HW0 * 2 + (size_t)pix * 2 + 0];
        const float fy = mv[(size_t)(t - 1) * HW0 * 2 + (size_t)pix * 2 + 1];
        const float ys = (float)y + fy;
        const float xs = (float)x + fx;
        const float y0 = floorf(ys), x0 = floorf(xs);
        const float wy = ys - y0, wx = xs - x0;
#pragma unroll
        for (int i = 0; i < 4; i++) {
            int dy = i >> 1, dx = i & 1;
            float yi = y0 + dy, xi = x0 + dx;
            val[i] = (yi >= 0.f) && (yi <= (float)(H0 - 1)) &&
                     (xi >= 0.f) && (xi <= (float)(W0 - 1));
            wgt[i] = (dy ? wy : 1.f - wy) * (dx ? wx : 1.f - wx);
            off[i] = val[i] ? ((int)yi * W0 + (int)xi) : 0;
        }
        fb = feat + (size_t)(t - 1) * 64 * HW0;
    }

    const float* refb = feat + (size_t)3 * 64 * HW0 + pix;
    const float* prb  = pred + (size_t)t * 64 * HW0 + pix;
    const float* f0b  = feat + pix;  // frame 0
    float* ob = alg + (size_t)t * 64 * HW0 + pix;

    for (int c = 0; c < 64; c++) {
        float a;
        if (t == 0) {
            a = __ldg(f0b + (size_t)c * HW0);
        } else {
            const float* img = fb + (size_t)c * HW0;
            a = 0.f;
#pragma unroll
            for (int i = 0; i < 4; i++)
                if (val[i]) a += __ldg(img + off[i]) * wgt[i];
        }
        float ref = __ldg(refb + (size_t)c * HW0);
        float p   = __ldg(prb + (size_t)c * HW0);
        ob[(size_t)c * HW0] = a * fsigmoid(a * ref) + p * fsigmoid(p * ref);
    }
}

// ---------------------------------------------------------------------------
// Modulated deformable conv, FFMA2 accumulators + __expf sigmoid.
// 128 threads/block -> 288 blocks (2/SM) for latency hiding.
// ---------------------------------------------------------------------------
__global__ void __launch_bounds__(128) deform_kernel(
    const float* __restrict__ lqs, const float* __restrict__ offm,
    const float* __restrict__ dcw, const float* __restrict__ dcb,
    float* __restrict__ out)
{
    __shared__ alignas(16) float s_w[63 * 64];  // [j][o]
    __shared__ float s_b[64];
    const int tid = threadIdx.x;
    for (int i = tid; i < 63 * 64; i += 128) {
        int o = i / 63, j = i - o * 63;
        s_w[j * 64 + o] = dcw[i];
    }
    if (tid < 64) s_b[tid] = dcb[tid];
    __syncthreads();

    const int pix = blockIdx.x * 128 + tid;
    if (pix >= HW0) return;
    const int y = pix / W0, x = pix - y * W0;

    ull_t acc[32];
#pragma unroll
    for (int q = 0; q < 32; q++) acc[q] = pack2(s_b[2 * q], s_b[2 * q + 1]);

    for (int g = 0; g < 7; g++) {
        const float* img = lqs + (size_t)g * HW0;
#pragma unroll
        for (int k = 0; k < 9; k++) {
            const int j = g * 9 + k;
            float offy = __ldg(offm + (size_t)(g * 18 + 2 * k + 0) * HW0 + pix);
            float offx = __ldg(offm + (size_t)(g * 18 + 2 * k + 1) * HW0 + pix);
            float mraw = __ldg(offm + (size_t)(126 + j) * HW0 + pix);
            float m = fsigmoid(mraw);
            float ys = (float)(y + k / 3 - 1) + offy;
            float xs = (float)(x + k % 3 - 1) + offx;
            float y0 = floorf(ys), x0 = floorf(xs);
            float wy = ys - y0, wx = xs - x0;
            float samp = 0.f;
#pragma unroll
            for (int ii = 0; ii < 4; ii++) {
                int dy = ii >> 1, dx = ii & 1;
                float yi = y0 + dy, xi = x0 + dx;
                if (yi >= 0.f && yi <= (float)(H0 - 1) &&
                    xi >= 0.f && xi <= (float)(W0 - 1))
                    samp += __ldg(img + (int)yi * W0 + (int)xi) *
                            ((dy ? wy : 1.f - wy) * (dx ? wx : 1.f - wx));
            }
            ull_t mod2 = pack2s(samp * m);
#pragma unroll
            for (int q2 = 0; q2 < 16; q2++) {
                ulonglong2 w = *reinterpret_cast<const ulonglong2*>(&s_w[j * 64 + 4 * q2]);
                ffma2(acc[2 * q2],     mod2, w.x);
                ffma2(acc[2 * q2 + 1], mod2, w.y);
            }
        }
    }
#pragma unroll
    for (int q = 0; q < 32; q++) {
        float2 u = unpack2(acc[q]);
        out[(size_t)(2 * q) * HW0 + pix]     = fmaxf(u.x, 0.f);
        out[(size_t)(2 * q + 1) * HW0 + pix] = fmaxf(u.y, 0.f);
    }
}

// ---------------------------------------------------------------------------
// Host orchestration (graph-capturable)
// ---------------------------------------------------------------------------
extern "C" void kernel_launch(void* const* d_in, const int* in_sizes, int n_in,
                              void* d_out, int out_size)
{
    const float* lqs    = (const float*)d_in[0];
    const float* preds  = (const float*)d_in[1];
    const float* mv     = (const float*)d_in[2];
    const float* bw1    = (const float*)d_in[3];
    const float* bb1    = (const float*)d_in[4];
    const float* bw2    = (const float*)d_in[5];
    const float* bb2    = (const float*)d_in[6];
    const float* dn1_w  = (const float*)d_in[7];
    const float* dn1_b  = (const float*)d_in[8];
    const float* dn2_w  = (const float*)d_in[9];
    const float* dn2_b  = (const float*)d_in[10];
    const float* up1_cw = (const float*)d_in[11];
    const float* up1_cb = (const float*)d_in[12];
    const float* up1_tw = (const float*)d_in[13];
    const float* up1_tb = (const float*)d_in[14];
    const float* up2_cw = (const float*)d_in[15];
    const float* up2_cb = (const float*)d_in[16];
    const float* up2_tw = (const float*)d_in[17];
    const float* up2_tb = (const float*)d_in[18];
    const float* tr_cw  = (const float*)d_in[19];
    const float* tr_cb  = (const float*)d_in[20];
    const float* tr_tw  = (const float*)d_in[21];
    const float* tr_tb  = (const float*)d_in[22];
    const float* ff_w   = (const float*)d_in[23];
    const float* ff_b   = (const float*)d_in[24];
    const float* om_w   = (const float*)d_in[25];
    const float* om_b   = (const float*)d_in[26];
    const float* dc_w   = (const float*)d_in[27];
    const float* dc_b   = (const float*)d_in[28];
    float* outp = (float*)d_out;

    float* S = nullptr;
    cudaGetSymbolAddress((void**)&S, g_scratch);
    float* feat  = S + OFF_FEAT;   // conv2 out: imgs 0..6 (lqs)
    float* pred  = S + OFF_PRED;   // conv2 out: imgs 7..13 (preds)
    float* alg   = S + OFF_ALG;    // conv1 scratch (lqs), later gated aligned
    float* alg2  = S + OFF_ALG2;   // conv1 scratch (preds)
    float* out0  = S + OFF_OUT0;
    float* out1  = S + OFF_OUT1;
    float* out2  = S + OFF_OUT2;
    float* u24   = S + OFF_U24;
    float* cat48 = S + OFF_CAT48;
    float* c48   = S + OFF_C48;
    float* cat96 = S + OFF_CAT96;
    float* c96   = S + OFF_C96;
    float* featf = S + OFF_FEATF;
    float* offm  = S + OFF_OFFM;

    dim3 blk(256);

    // Backbone conv1 (1->64) on lqs and preds -> contiguous scratch [alg|alg2]
    conv3x3_s1<8><<<dim3(6, 12, 7 * 4), blk>>>(lqs,   bw1, bb1, alg,  1, 64, 192, 192, 4, EP_NONE);
    conv3x3_s1<8><<<dim3(6, 12, 7 * 4), blk>>>(preds, bw1, bb1, alg2, 1, 64, 192, 192, 4, EP_NONE);
    // Backbone conv2 (64->64), 14 images in ONE launch -> [feat|pred]
    conv3x3_s1<8><<<dim3(6, 12, 14 * 4), blk>>>(alg, bw2, bb2, feat, 64, 64, 192, 192, 4, EP_NONE);

    // alg := gated(aligned, pred) in one fused pass (frames 0..6)
    warp_gate_kernel<<<dim3(HW0 / 256, 7), blk>>>(feat, pred, mv, alg);

    // out0 = 0.1*leaky(conv448(alg)) + leaky(conv448(feat)) — one dual kernel
    conv3x3_s1_dual<<<dim3(6, 12, 4), blk>>>(alg, feat, ff_w, ff_b, out0, 448, 64);

    // Down path (CO=8 chunks; channel-blocked staging)
    conv3x3_s2<8><<<dim3(6, 6, 8), blk>>>(out0, dn1_w, dn1_b, out1, 64, 64, 192, 192, 96, 96);
    conv3x3_s2<8><<<dim3(3, 3, 8), blk>>>(out1, dn2_w, dn2_b, out2, 64, 64, 96, 96, 48, 48);
    conv3x3_s2<8><<<dim3(2, 2, 8), blk>>>(out2, tr_cw, tr_cb, u24, 64, 64, 48, 48, 24, 24);

    // Up path with skip concats (convT CO=16, channel-blocked staging)
    convT4x4_s2<16><<<dim3(3, 3, 4), blk>>>(u24, tr_tw, tr_tb, cat48, 64, 64, 24, 24, 48, 48);
    cudaMemcpyAsync(cat48 + (size_t)64 * 48 * 48, out2,
                    (size_t)64 * 48 * 48 * sizeof(float), cudaMemcpyDeviceToDevice, 0);
    conv3x3_s1<8><<<dim3(2, 3, 4), blk>>>(cat48, up2_cw, up2_cb, c48, 128, 64, 48, 48, 4, EP_RELU);
    convT4x4_s2<16><<<dim3(6, 6, 4), blk>>>(c48, up2_tw, up2_tb, cat96, 64, 64, 48, 48, 96, 96);
    cudaMemcpyAsync(cat96 + (size_t)64 * 96 * 96, out1,
                    (size_t)64 * 96 * 96 * sizeof(float), cudaMemcpyDeviceToDevice, 0);
    conv3x3_s1<8><<<dim3(3, 6, 4), blk>>>(cat96, up1_cw, up1_cb, c96, 128, 64, 96, 96, 4, EP_RELU);
    convT4x4_s2<16><<<dim3(12, 12, 4), blk>>>(c96, up1_tw, up1_tb, featf, 64, 64, 96, 96, 192, 192);

    // Offsets + masks (Cout=189 -> 12 chunks of 16)
    conv3x3_s1<8><<<dim3(6, 12, 12), blk>>>(featf, om_w, om_b, offm, 64, 189, 192, 192, 12, EP_NONE);

    // Modulated deformable conv + ReLU -> output
    deform_kernel<<<HW0 / 128, dim3(128)>>>(lqs, offm, dc_w, dc_b, outp);
}

// round 13
// speedup vs baseline: 1.5941x; 1.0006x over previous
#include <cuda_runtime.h>
#include <math.h>
#include <stdint.h>

// ---------------------------------------------------------------------------
// Problem constants
// ---------------------------------------------------------------------------
#define NF 64
#define TT 7
#define H0 192
#define W0 192
#define HW0 (H0 * W0)

// ---------------------------------------------------------------------------
// Scratch layout (single static device buffer; no allocations anywhere)
// ---------------------------------------------------------------------------
#define BIGSZ (7 * 64 * HW0)
#define OFF_FEAT   0
#define OFF_PRED   (OFF_FEAT + BIGSZ)
#define OFF_ALG    (OFF_PRED + BIGSZ)           // conv1 scratch (lqs) / aligned
#define OFF_ALG2   (OFF_ALG + BIGSZ)            // conv1 scratch (preds)
#define OFF_OUT0   (OFF_ALG2 + BIGSZ)
#define OFF_OUT1   (OFF_OUT0 + 64 * HW0)
#define OFF_OUT2   (OFF_OUT1 + 64 * 96 * 96)
#define OFF_U24    (OFF_OUT2 + 64 * 48 * 48)
#define OFF_CAT48  (OFF_U24 + 64 * 24 * 24)
#define OFF_C48    (OFF_CAT48 + 128 * 48 * 48)
#define OFF_CAT96  (OFF_C48 + 64 * 48 * 48)
#define OFF_C96    (OFF_CAT96 + 128 * 96 * 96)
#define OFF_FEATF  (OFF_C96 + 64 * 96 * 96)
#define OFF_OFFM   (OFF_FEATF + 64 * HW0)
#define SCRATCH_TOTAL (OFF_OFFM + 189 * HW0)

__device__ float g_scratch[SCRATCH_TOTAL];

enum { EP_NONE = 0, EP_RELU = 1 };

// ---------------------------------------------------------------------------
// Packed f32x2 helpers (Blackwell FFMA2 path)
// ---------------------------------------------------------------------------
typedef unsigned long long ull_t;
__device__ __forceinline__ ull_t pack2s(float v) {
    ull_t r;
    asm("mov.b64 %0, {%1, %1};" : "=l"(r) : "f"(v));
    return r;
}
__device__ __forceinline__ ull_t pack2(float lo, float hi) {
    ull_t r;
    asm("mov.b64 %0, {%1, %2};" : "=l"(r) : "f"(lo), "f"(hi));
    return r;
}
__device__ __forceinline__ void ffma2(ull_t& d, ull_t a, ull_t b) {
    asm("fma.rn.f32x2 %0, %1, %2, %0;" : "+l"(d) : "l"(a), "l"(b));
}
__device__ __forceinline__ float2 unpack2(ull_t v) {
    float lo, hi;
    asm("mov.b64 {%0, %1}, %2;" : "=f"(lo), "=f"(hi) : "l"(v));
    return make_float2(lo, hi);
}
__device__ __forceinline__ float fsigmoid(float x) {
    return 1.f / (1.f + __expf(-x));
}

// ---------------------------------------------------------------------------
// cp.async helpers (zero-fill when invalid via src-size = 0)
// ---------------------------------------------------------------------------
__device__ __forceinline__ uint32_t smem_u32(const void* p) {
    return (uint32_t)__cvta_generic_to_shared(p);
}
__device__ __forceinline__ void cp_async4(uint32_t s, const float* g, bool ok) {
    asm volatile("cp.async.ca.shared.global [%0], [%1], 4, %2;"
                 :: "r"(s), "l"(g), "r"(ok ? 4u : 0u));
}
__device__ __forceinline__ void cp_async16(uint32_t s, const float* g, bool ok) {
    asm volatile("cp.async.cg.shared.global [%0], [%1], 16, %2;"
                 :: "r"(s), "l"(g), "r"(ok ? 16u : 0u));
}
#define CP_COMMIT() asm volatile("cp.async.commit_group;")
#define CP_WAIT0()  asm volatile("cp.async.wait_group 0;")

// ---------------------------------------------------------------------------
// 3x3 stride-1 pad-1 conv, FFMA2, 256 threads, cp.async double-buffered,
// 16-byte vectorized interior staging. CBS=8 cis per buffer (fewer barriers).
// Output tile 32x16: thread = 2 x-adjacent px (tx 0..15) x row (ty 0..15).
// NP f32x2 cout-pairs per chunk (CO = 2*NP).
// Input tile stored at column offset +3 in a 40-float row so the 32 interior
// columns are 16B-aligned. Requires W % 4 == 0 (true: 192/96/48).
// ---------------------------------------------------------------------------
#define CBS 8
#define CB4 4
#define SMC 40
template <int NP>
__global__ void __launch_bounds__(256, NP == 8 ? 3 : 2) conv3x3_s1(
    const float* __restrict__ in, const float* __restrict__ wgt,
    const float* __restrict__ bias, float* __restrict__ out,
    int Cin, int Cout, int H, int W, int nChunks, int ep)
{
    const int CO = 2 * NP;
    __shared__ alignas(16) float s_in[2][CBS][18][SMC];
    __shared__ alignas(16) float s_w[2][CBS][9][2 * NP];

    const int img   = blockIdx.z / nChunks;
    const int chunk = blockIdx.z % nChunks;
    const int ox0 = blockIdx.x * 32, oy0 = blockIdx.y * 16;
    const int tid = threadIdx.x;
    const int tx = tid & 15, ty = tid >> 4;
    const float* inB = in + (size_t)img * Cin * H * W;
    const int coBase = chunk * CO;

    ull_t acc0[NP], acc1[NP];
#pragma unroll
    for (int j = 0; j < NP; j++) { acc0[j] = 0ull; acc1[j] = 0ull; }

    const int nB = (Cin + CBS - 1) / CBS;

    auto stage = [&](int buf, int b) {
        const int c0 = b * CBS;
        const int nc = min(CBS, Cin - c0);
        // interior: 18 rows x 8 16B-chunks per ci
        for (int i = tid; i < nc * 144; i += 256) {
            int cb = i / 144, rem = i - cb * 144;
            int r = rem >> 3, k = rem & 7;
            int gy = oy0 - 1 + r;
            int gx = ox0 + 4 * k;
            bool ok = (gy >= 0 && gy < H) && (gx + 3 < W);
            cp_async16(smem_u32(&s_in[buf][cb][r][4 + 4 * k]),
                       inB + ((size_t)(c0 + cb) * H + (ok ? gy : 0)) * W + (ok ? gx : 0), ok);
        }
        // halo: 2 scalars per row
        for (int i = tid; i < nc * 36; i += 256) {
            int cb = i / 36, rem = i - cb * 36;
            int r = rem >> 1, e = rem & 1;
            int gy = oy0 - 1 + r;
            int gx = e ? (ox0 + 32) : (ox0 - 1);
            int col = e ? 36 : 3;
            bool ok = (gy >= 0 && gy < H && gx >= 0 && gx < W);
            cp_async4(smem_u32(&s_in[buf][cb][r][col]),
                      inB + ((size_t)(c0 + cb) * H + (ok ? gy : 0)) * W + (ok ? gx : 0), ok);
        }
        // weights
        for (int i = tid; i < nc * 9 * CO; i += 256) {
            int cb = i / (9 * CO), rem = i - cb * (9 * CO);
            int co = rem / 9, t = rem - co * 9;
            int cog = coBase + co;
            bool ok = (cog < Cout);
            cp_async4(smem_u32(&s_w[buf][cb][t][co]),
                      wgt + ((size_t)(ok ? cog : 0) * Cin + (c0 + cb)) * 9 + t, ok);
        }
        CP_COMMIT();
    };

    stage(0, 0);
    for (int b = 0; b < nB; b++) {
        CP_WAIT0();
        __syncthreads();
        if (b + 1 < nB) stage((b + 1) & 1, b + 1);
        const int buf = b & 1;
        const int nc = min(CBS, Cin - b * CBS);
        for (int cb = 0; cb < nc; cb++) {
#pragma unroll
            for (int dy = 0; dy < 3; dy++) {
                ull_t ps[4];
#pragma unroll
                for (int j = 0; j < 4; j++)
                    ps[j] = pack2s(s_in[buf][cb][ty + dy][2 * tx + j + 3]);
#pragma unroll
                for (int dx = 0; dx < 3; dx++) {
                    const int t = dy * 3 + dx;
#pragma unroll
                    for (int q2 = 0; q2 < NP / 2; q2++) {
                        ulonglong2 w = *reinterpret_cast<const ulonglong2*>(&s_w[buf][cb][t][4 * q2]);
                        ffma2(acc0[2 * q2],     ps[dx],     w.x);
                        ffma2(acc0[2 * q2 + 1], ps[dx],     w.y);
                        ffma2(acc1[2 * q2],     ps[dx + 1], w.x);
                        ffma2(acc1[2 * q2 + 1], ps[dx + 1], w.y);
                    }
                }
            }
        }
    }

    const int oy = oy0 + ty, oxb = ox0 + 2 * tx;
    if (oy >= H || oxb >= W) return;
    const size_t HWs = (size_t)H * W;
    float* ob = out + (size_t)img * Cout * HWs + (size_t)oy * W + oxb;

#pragma unroll
    for (int j = 0; j < NP; j++) {
        float2 u0 = unpack2(acc0[j]), u1 = unpack2(acc1[j]);
#pragma unroll
        for (int s = 0; s < 2; s++) {
            int cog = coBase + 2 * j + s;
            if (cog >= Cout) continue;
            float b = __ldg(bias + cog);
            float2 o;
            o.x = (s ? u0.y : u0.x) + b;
            o.y = (s ? u1.y : u1.x) + b;
            if (ep == EP_RELU) { o.x = fmaxf(o.x, 0.f); o.y = fmaxf(o.y, 0.f); }
            *reinterpret_cast<float2*>(ob + (size_t)cog * HWs) = o;
        }
    }
}

// ---------------------------------------------------------------------------
// Dual-input shared-weight 3x3 conv (fusion pair), cp.async double-buffered,
// 16B vectorized staging: out = 0.1*leaky(conv(inA)+b) + leaky(conv(inF)+b)
// ---------------------------------------------------------------------------
__global__ void __launch_bounds__(256, 2) conv3x3_s1_dual(
    const float* __restrict__ inA, const float* __restrict__ inF,
    const float* __restrict__ wgt, const float* __restrict__ bias,
    float* __restrict__ out, int Cin, int Cout)
{
    __shared__ alignas(16) float s_a[2][CB4][18][SMC];
    __shared__ alignas(16) float s_f[2][CB4][18][SMC];
    __shared__ alignas(16) float s_w[2][CB4][9][16];

    const int chunk = blockIdx.z;
    const int ox0 = blockIdx.x * 32, oy0 = blockIdx.y * 16;
    const int tid = threadIdx.x;
    const int tx = tid & 15, ty = tid >> 4;
    const int coBase = chunk * 16;
    const int H = H0, W = W0;

    ull_t aA0[8], aA1[8], aF0[8], aF1[8];
#pragma unroll
    for (int j = 0; j < 8; j++) { aA0[j] = aA1[j] = aF0[j] = aF1[j] = 0ull; }

    const int nB = (Cin + CB4 - 1) / CB4;

    auto stage = [&](int buf, int b) {
        const int c0 = b * CB4;
        const int nc = min(CB4, Cin - c0);
        for (int i = tid; i < nc * 144; i += 256) {
            int cb = i / 144, rem = i - cb * 144;
            int r = rem >> 3, k = rem & 7;
            int gy = oy0 - 1 + r;
            int gx = ox0 + 4 * k;
            bool ok = (gy >= 0 && gy < H) && (gx + 3 < W);
            size_t gidx = ((size_t)(c0 + cb) * H + (ok ? gy : 0)) * W + (ok ? gx : 0);
            cp_async16(smem_u32(&s_a[buf][cb][r][4 + 4 * k]), inA + gidx, ok);
            cp_async16(smem_u32(&s_f[buf][cb][r][4 + 4 * k]), inF + gidx, ok);
        }
        for (int i = tid; i < nc * 36; i += 256) {
            int cb = i / 36, rem = i - cb * 36;
            int r = rem >> 1, e = rem & 1;
            int gy = oy0 - 1 + r;
            int gx = e ? (ox0 + 32) : (ox0 - 1);
            int col = e ? 36 : 3;
            bool ok = (gy >= 0 && gy < H && gx >= 0 && gx < W);
            size_t gidx = ((size_t)(c0 + cb) * H + (ok ? gy : 0)) * W + (ok ? gx : 0);
            cp_async4(smem_u32(&s_a[buf][cb][r][col]), inA + gidx, ok);
            cp_async4(smem_u32(&s_f[buf][cb][r][col]), inF + gidx, ok);
        }
        for (int i = tid; i < nc * 144; i += 256) {
            int cb = i / 144, rem = i - cb * 144;
            int co = rem / 9, t = rem - co * 9;
            cp_async4(smem_u32(&s_w[buf][cb][t][co]),
                      wgt + ((size_t)(coBase + co) * Cin + (c0 + cb)) * 9 + t, true);
        }
        CP_COMMIT();
    };

    stage(0, 0);
    for (int b = 0; b < nB; b++) {
        CP_WAIT0();
        __syncthreads();
        if (b + 1 < nB) stage((b + 1) & 1, b + 1);
        const int buf = b & 1;
        const int nc = min(CB4, Cin - b * CB4);
        for (int cb = 0; cb < nc; cb++) {
#pragma unroll
            for (int dy = 0; dy < 3; dy++) {
                ull_t pa[4], pf[4];
#pragma unroll
                for (int j = 0; j < 4; j++) {
                    pa[j] = pack2s(s_a[buf][cb][ty + dy][2 * tx + j + 3]);
                    pf[j] = pack2s(s_f[buf][cb][ty + dy][2 * tx + j + 3]);
                }
#pragma unroll
                for (int dx = 0; dx < 3; dx++) {
                    const int t = dy * 3 + dx;
#pragma unroll
                    for (int q2 = 0; q2 < 4; q2++) {
                        ulonglong2 w = *reinterpret_cast<const ulonglong2*>(&s_w[buf][cb][t][4 * q2]);
                        ffma2(aA0[2 * q2],     pa[dx],     w.x);
                        ffma2(aA0[2 * q2 + 1], pa[dx],     w.y);
                        ffma2(aA1[2 * q2],     pa[dx + 1], w.x);
                        ffma2(aA1[2 * q2 + 1], pa[dx + 1], w.y);
                        ffma2(aF0[2 * q2],     pf[dx],     w.x);
                        ffma2(aF0[2 * q2 + 1], pf[dx],     w.y);
                        ffma2(aF1[2 * q2],     pf[dx + 1], w.x);
                        ffma2(aF1[2 * q2 + 1], pf[dx + 1], w.y);
                    }
                }
            }
        }
    }

    const int oy = oy0 + ty, oxb = ox0 + 2 * tx;
    const size_t HWs = (size_t)H * W;
    float* ob = out + (size_t)oy * W + oxb;

#pragma unroll
    for (int j = 0; j < 8; j++) {
        float2 A0 = unpack2(aA0[j]), A1 = unpack2(aA1[j]);
        float2 F0 = unpack2(aF0[j]), F1 = unpack2(aF1[j]);
#pragma unroll
        for (int s = 0; s < 2; s++) {
            int cog = coBase + 2 * j + s;
            float b = __ldg(bias + cog);
            float va0 = (s ? A0.y : A0.x) + b;
            float va1 = (s ? A1.y : A1.x) + b;
            float vf0 = (s ? F0.y : F0.x) + b;
            float vf1 = (s ? F1.y : F1.x) + b;
            va0 = va0 > 0.f ? va0 : 0.1f * va0;
            va1 = va1 > 0.f ? va1 : 0.1f * va1;
            vf0 = vf0 > 0.f ? vf0 : 0.1f * vf0;
            vf1 = vf1 > 0.f ? vf1 : 0.1f * vf1;
            float2 o = make_float2(0.1f * va0 + vf0, 0.1f * va1 + vf1);
            *reinterpret_cast<float2*>(ob + (size_t)cog * HWs) = o;
        }
    }
}

// ---------------------------------------------------------------------------
// 3x3 stride-2 pad-1 conv. Output tile 16x16, 1 px/thread. 8 cis per sync.
// ---------------------------------------------------------------------------
#define SCB 8
template <int CO>
__global__ void __launch_bounds__(256) conv3x3_s2(
    const float* __restrict__ in, const float* __restrict__ wgt,
    const float* __restrict__ bias, float* __restrict__ out,
    int Cin, int Cout, int Hin, int Win, int Hout, int Wout)
{
    __shared__ float s_in[SCB][33][33];
    __shared__ alignas(16) float s_w[SCB][9][CO];

    const int chunk = blockIdx.z;
    const int ox0 = blockIdx.x * 16, oy0 = blockIdx.y * 16;
    const int tid = threadIdx.x, tx = tid & 15, ty = tid >> 4;
    const int coBase = chunk * CO;

    float acc[CO];
#pragma unroll
    for (int i = 0; i < CO; i++) acc[i] = 0.f;

    for (int c0 = 0; c0 < Cin; c0 += SCB) {
        const int nc = min(SCB, Cin - c0);
        for (int i = tid; i < nc * 1089; i += 256) {
            int cb = i / 1089, rem = i - cb * 1089;
            int r = rem / 33, c = rem - r * 33;
            int gy = 2 * oy0 - 1 + r, gx = 2 * ox0 - 1 + c;
            s_in[cb][r][c] = (gy >= 0 && gy < Hin && gx >= 0 && gx < Win)
                ? __ldg(in + ((size_t)(c0 + cb) * Hin + gy) * Win + gx) : 0.f;
        }
        for (int i = tid; i < nc * 9 * CO; i += 256) {
            int cb = i / (9 * CO), rem = i - cb * (9 * CO);
            int co = rem / 9, t = rem - co * 9;
            int cog = coBase + co;
            s_w[cb][t][co] = (cog < Cout)
                ? __ldg(wgt + ((size_t)cog * Cin + (c0 + cb)) * 9 + t) : 0.f;
        }
        __syncthreads();

        for (int cb = 0; cb < nc; cb++) {
            float v[9];
#pragma unroll
            for (int t = 0; t < 9; t++) v[t] = s_in[cb][2 * ty + t / 3][2 * tx + t % 3];
#pragma unroll
            for (int t = 0; t < 9; t++) {
#pragma unroll
                for (int q = 0; q < CO / 4; q++) {
                    float4 w = *reinterpret_cast<const float4*>(&s_w[cb][t][4 * q]);
                    acc[4 * q + 0] += v[t] * w.x; acc[4 * q + 1] += v[t] * w.y;
                    acc[4 * q + 2] += v[t] * w.z; acc[4 * q + 3] += v[t] * w.w;
                }
            }
        }
        __syncthreads();
    }

    const int ox = ox0 + tx, oy = oy0 + ty;
    if (ox >= Wout || oy >= Hout) return;
    size_t pbase = (size_t)oy * Wout + ox;
#pragma unroll
    for (int co = 0; co < CO; co++) {
        int cog = coBase + co;
        if (cog >= Cout) break;
        float v = acc[co] + __ldg(bias + cog);
        out[(size_t)cog * Hout * Wout + pbase] = fmaxf(v, 0.f);
    }
}

// ---------------------------------------------------------------------------
// ConvTranspose2d: kernel 4, stride 2, pad 1. Always ReLU. 8 cis per sync.
// ---------------------------------------------------------------------------
template <int CO>
__global__ void __launch_bounds__(256) convT4x4_s2(
    const float* __restrict__ in, const float* __restrict__ wgt,
    const float* __restrict__ bias, float* __restrict__ out,
    int Cin, int Cout, int Hin, int Win, int Hout, int Wout)
{
    __shared__ float s_in[SCB][10][10];
    __shared__ alignas(16) float s_w[SCB][16][CO];

    const int chunk = blockIdx.z;
    const int ox0 = blockIdx.x * 16, oy0 = blockIdx.y * 16;
    const int tid = threadIdx.x, tx = tid & 15, ty = tid >> 4;
    const int coBase = chunk * CO;
    const int iy0 = oy0 / 2 - 1, ix0 = ox0 / 2 - 1;

    const int oy = oy0 + ty, ox = ox0 + tx;
    const int py = (oy + 1) & 1, px = (ox + 1) & 1;
    const int r0 = ((oy + 1 - py) >> 1) - iy0;
    const int r1 = r0 - 1;
    const int c0i = ((ox + 1 - px) >> 1) - ix0;
    const int c1i = c0i - 1;

    float acc[CO];
#pragma unroll
    for (int i = 0; i < CO; i++) acc[i] = 0.f;

    for (int c0 = 0; c0 < Cin; c0 += SCB) {
        const int nc = min(SCB, Cin - c0);
        for (int i = tid; i < nc * 100; i += 256) {
            int cb = i / 100, rem = i - cb * 100;
            int r = rem / 10, c = rem - r * 10;
            int gy = iy0 + r, gx = ix0 + c;
            s_in[cb][r][c] = (gy >= 0 && gy < Hin && gx >= 0 && gx < Win)
                ? __ldg(in + ((size_t)(c0 + cb) * Hin + gy) * Win + gx) : 0.f;
        }
        for (int i = tid; i < nc * 16 * CO; i += 256) {
            int cb = i / (16 * CO), rem = i - cb * (16 * CO);
            int co = rem / 16, t = rem - co * 16;
            int cog = coBase + co;
            s_w[cb][t][co] = (cog < Cout)
                ? __ldg(wgt + ((size_t)(c0 + cb) * Cout + cog) * 16 + t) : 0.f;
        }
        __syncthreads();

        for (int cb = 0; cb < nc; cb++) {
            float v00 = s_in[cb][r0][c0i], v01 = s_in[cb][r0][c1i];
            float v10 = s_in[cb][r1][c0i], v11 = s_in[cb][r1][c1i];
#pragma unroll
            for (int a = 0; a < 2; a++) {
#pragma unroll
                for (int b = 0; b < 2; b++) {
                    float v = a ? (b ? v11 : v10) : (b ? v01 : v00);
                    int t = (py + 2 * a) * 4 + (px + 2 * b);
#pragma unroll
                    for (int q = 0; q < CO / 4; q++) {
                        float4 w = *reinterpret_cast<const float4*>(&s_w[cb][t][4 * q]);
                        acc[4 * q + 0] += v * w.x; acc[4 * q + 1] += v * w.y;
                        acc[4 * q + 2] += v * w.z; acc[4 * q + 3] += v * w.w;
                    }
                }
            }
        }
        __syncthreads();
    }

    if (ox >= Wout || oy >= Hout) return;
    size_t pbase = (size_t)oy * Wout + ox;
#pragma unroll
    for (int co = 0; co < CO; co++) {
        int cog = coBase + co;
        if (cog >= Cout) break;
        float v = acc[co] + __ldg(bias + cog);
        out[(size_t)cog * Hout * Wout + pbase] = fmaxf(v, 0.f);
    }
}

// ---------------------------------------------------------------------------
// Fused flow-warp + gate:
// t = 0:   a = feat[0][c]
// t >= 1:  a = bilinear(feat[t-1][c], pix + mv[t-1])
// alg[t][c] = a*sig(a*ref) + p*sig(p*ref),  ref = feat[3][c], p = pred[t][c]
// ---------------------------------------------------------------------------
__global__ void warp_gate_kernel(const float* __restrict__ feat,
                                 const float* __restrict__ pred,
                                 const float* __restrict__ mv,
                                 float* __restrict__ alg)
{
    const int pix = blockIdx.x * 256 + threadIdx.x;
    if (pix >= HW0) return;
    const int t = blockIdx.y;  // 0..6

    float wgt[4]; int off[4]; bool val[4];
    const float* fb = nullptr;
    if (t > 0) {
        const int y = pix / W0, x = pix - y * W0;
        const float fx = mv[(size_t)(t - 1) * HW0 * 2 + (size_t)pix * 2 + 0];
        const float fy = mv[(size_t)(t - 1) * HW0 * 2 + (size_t)pix * 2 + 1];
        const float ys = (float)y + fy;
        const float xs = (float)x + fx;
        const float y0 = floorf(ys), x0 = floorf(xs);
        const float wy = ys - y0, wx = xs - x0;
#pragma unroll
        for (int i = 0; i < 4; i++) {
            int dy = i >> 1, dx = i & 1;
            float yi = y0 + dy, xi = x0 + dx;
            val[i] = (yi >= 0.f) && (yi <= (float)(H0 - 1)) &&
                     (xi >= 0.f) && (xi <= (float)(W0 - 1));
            wgt[i] = (dy ? wy : 1.f - wy) * (dx ? wx : 1.f - wx);
            off[i] = val[i] ? ((int)yi * W0 + (int)xi) : 0;
        }
        fb = feat + (size_t)(t - 1) * 64 * HW0;
    }

    const float* refb = feat + (size_t)3 * 64 * HW0 + pix;
    const float* prb  = pred + (size_t)t * 64 * HW0 + pix;
    const float* f0b  = feat + pix;  // frame 0
    float* ob = alg + (size_t)t * 64 * HW0 + pix;

    for (int c = 0; c < 64; c++) {
        float a;
        if (t == 0) {
            a = __ldg(f0b + (size_t)c * HW0);
        } else {
            const float* img = fb + (size_t)c * HW0;
            a = 0.f;
#pragma unroll
            for (int i = 0; i < 4; i++)
                if (val[i]) a += __ldg(img + off[i]) * wgt[i];
        }
        float ref = __ldg(refb + (size_t)c * HW0);
        float p   = __ldg(prb + (size_t)c * HW0);
        ob[(size_t)c * HW0] = a * fsigmoid(a * ref) + p * fsigmoid(p * ref);
    }
}

// ---------------------------------------------------------------------------
// Modulated deformable conv, FFMA2 accumulators + __expf sigmoid.
// 128 threads/block -> 288 blocks (2/SM) for latency hiding.
// ---------------------------------------------------------------------------
__global__ void __launch_bounds__(128) deform_kernel(
    const float* __restrict__ lqs, const float* __restrict__ offm,
    const float* __restrict__ dcw, const float* __restrict__ dcb,
    float* __restrict__ out)
{
    __shared__ alignas(16) float s_w[63 * 64];  // [j][o]
    __shared__ float s_b[64];
    const int tid = threadIdx.x;
    for (int i = tid; i < 63 * 64; i += 128) {
        int o = i / 63, j = i - o * 63;
        s_w[j * 64 + o] = dcw[i];
    }
    if (tid < 64) s_b[tid] = dcb[tid];
    __syncthreads();

    const int pix = blockIdx.x * 128 + tid;
    if (pix >= HW0) return;
    const int y = pix / W0, x = pix - y * W0;

    ull_t acc[32];
#pragma unroll
    for (int q = 0; q < 32; q++) acc[q] = pack2(s_b[2 * q], s_b[2 * q + 1]);

    for (int g = 0; g < 7; g++) {
        const float* img = lqs + (size_t)g * HW0;
#pragma unroll
        for (int k = 0; k < 9; k++) {
            const int j = g * 9 + k;
            float offy = __ldg(offm + (size_t)(g * 18 + 2 * k + 0) * HW0 + pix);
            float offx = __ldg(offm + (size_t)(g * 18 + 2 * k + 1) * HW0 + pix);
            float mraw = __ldg(offm + (size_t)(126 + j) * HW0 + pix);
            float m = fsigmoid(mraw);
            float ys = (float)(y + k / 3 - 1) + offy;
            float xs = (float)(x + k % 3 - 1) + offx;
            float y0 = floorf(ys), x0 = floorf(xs);
            float wy = ys - y0, wx = xs - x0;
            float samp = 0.f;
#pragma unroll
            for (int ii = 0; ii < 4; ii++) {
                int dy = ii >> 1, dx = ii & 1;
                float yi = y0 + dy, xi = x0 + dx;
                if (yi >= 0.f && yi <= (float)(H0 - 1) &&
                    xi >= 0.f && xi <= (float)(W0 - 1))
                    samp += __ldg(img + (int)yi * W0 + (int)xi) *
                            ((dy ? wy : 1.f - wy) * (dx ? wx : 1.f - wx));
            }
            ull_t mod2 = pack2s(samp * m);
#pragma unroll
            for (int q2 = 0; q2 < 16; q2++) {
                ulonglong2 w = *reinterpret_cast<const ulonglong2*>(&s_w[j * 64 + 4 * q2]);
                ffma2(acc[2 * q2],     mod2, w.x);
                ffma2(acc[2 * q2 + 1], mod2, w.y);
            }
        }
    }
#pragma unroll
    for (int q = 0; q < 32; q++) {
        float2 u = unpack2(acc[q]);
        out[(size_t)(2 * q) * HW0 + pix]     = fmaxf(u.x, 0.f);
        out[(size_t)(2 * q + 1) * HW0 + pix] = fmaxf(u.y, 0.f);
    }
}

// ---------------------------------------------------------------------------
// Host orchestration (graph-capturable)
// ---------------------------------------------------------------------------
extern "C" void kernel_launch(void* const* d_in, const int* in_sizes, int n_in,
                              void* d_out, int out_size)
{
    const float* lqs    = (const float*)d_in[0];
    const float* preds  = (const float*)d_in[1];
    const float* mv     = (const float*)d_in[2];
    const float* bw1    = (const float*)d_in[3];
    const float* bb1    = (const float*)d_in[4];
    const float* bw2    = (const float*)d_in[5];
    const float* bb2    = (const float*)d_in[6];
    const float* dn1_w  = (const float*)d_in[7];
    const float* dn1_b  = (const float*)d_in[8];
    const float* dn2_w  = (const float*)d_in[9];
    const float* dn2_b  = (const float*)d_in[10];
    const float* up1_cw = (const float*)d_in[11];
    const float* up1_cb = (const float*)d_in[12];
    const float* up1_tw = (const float*)d_in[13];
    const float* up1_tb = (const float*)d_in[14];
    const float* up2_cw = (const float*)d_in[15];
    const float* up2_cb = (const float*)d_in[16];
    const float* up2_tw = (const float*)d_in[17];
    const float* up2_tb = (const float*)d_in[18];
    const float* tr_cw  = (const float*)d_in[19];
    const float* tr_cb  = (const float*)d_in[20];
    const float* tr_tw  = (const float*)d_in[21];
    const float* tr_tb  = (const float*)d_in[22];
    const float* ff_w   = (const float*)d_in[23];
    const float* ff_b   = (const float*)d_in[24];
    const float* om_w   = (const float*)d_in[25];
    const float* om_b   = (const float*)d_in[26];
    const float* dc_w   = (const float*)d_in[27];
    const float* dc_b   = (const float*)d_in[28];
    float* outp = (float*)d_out;

    float* S = nullptr;
    cudaGetSymbolAddress((void**)&S, g_scratch);
    float* feat  = S + OFF_FEAT;   // conv2 out: imgs 0..6 (lqs)
    float* pred  = S + OFF_PRED;   // conv2 out: imgs 7..13 (preds)
    float* alg   = S + OFF_ALG;    // conv1 scratch (lqs), later gated aligned
    float* alg2  = S + OFF_ALG2;   // conv1 scratch (preds)
    float* out0  = S + OFF_OUT0;
    float* out1  = S + OFF_OUT1;
    float* out2  = S + OFF_OUT2;
    float* u24   = S + OFF_U24;
    float* cat48 = S + OFF_CAT48;
    float* c48   = S + OFF_C48;
    float* cat96 = S + OFF_CAT96;
    float* c96   = S + OFF_C96;
    float* featf = S + OFF_FEATF;
    float* offm  = S + OFF_OFFM;

    dim3 blk(256);

    // Backbone conv1 (1->64) on lqs and preds -> contiguous scratch [alg|alg2]
    conv3x3_s1<8><<<dim3(6, 12, 7 * 4), blk>>>(lqs,   bw1, bb1, alg,  1, 64, 192, 192, 4, EP_NONE);
    conv3x3_s1<8><<<dim3(6, 12, 7 * 4), blk>>>(preds, bw1, bb1, alg2, 1, 64, 192, 192, 4, EP_NONE);
    // Backbone conv2 (64->64), 14 images in ONE launch -> [feat|pred]
    conv3x3_s1<8><<<dim3(6, 12, 14 * 4), blk>>>(alg, bw2, bb2, feat, 64, 64, 192, 192, 4, EP_NONE);

    // alg := gated(aligned, pred) in one fused pass (frames 0..6)
    warp_gate_kernel<<<dim3(HW0 / 256, 7), blk>>>(feat, pred, mv, alg);

    // out0 = 0.1*leaky(conv448(alg)) + leaky(conv448(feat)) — one dual kernel
    conv3x3_s1_dual<<<dim3(6, 12, 4), blk>>>(alg, feat, ff_w, ff_b, out0, 448, 64);

    // Down path (CO=8 chunks; channel-blocked staging)
    conv3x3_s2<8><<<dim3(6, 6, 8), blk>>>(out0, dn1_w, dn1_b, out1, 64, 64, 192, 192, 96, 96);
    conv3x3_s2<8><<<dim3(3, 3, 8), blk>>>(out1, dn2_w, dn2_b, out2, 64, 64, 96, 96, 48, 48);
    conv3x3_s2<8><<<dim3(2, 2, 8), blk>>>(out2, tr_cw, tr_cb, u24, 64, 64, 48, 48, 24, 24);

    // Up path with skip concats (convT CO=16, channel-blocked staging)
    convT4x4_s2<16><<<dim3(3, 3, 4), blk>>>(u24, tr_tw, tr_tb, cat48, 64, 64, 24, 24, 48, 48);
    cudaMemcpyAsync(cat48 + (size_t)64 * 48 * 48, out2,
                    (size_t)64 * 48 * 48 * sizeof(float), cudaMemcpyDeviceToDevice, 0);
    conv3x3_s1<8><<<dim3(2, 3, 4), blk>>>(cat48, up2_cw, up2_cb, c48, 128, 64, 48, 48, 4, EP_RELU);
    convT4x4_s2<16><<<dim3(6, 6, 4), blk>>>(c48, up2_tw, up2_tb, cat96, 64, 64, 48, 48, 96, 96);
    cudaMemcpyAsync(cat96 + (size_t)64 * 96 * 96, out1,
                    (size_t)64 * 96 * 96 * sizeof(float), cudaMemcpyDeviceToDevice, 0);
    conv3x3_s1<8><<<dim3(3, 6, 4), blk>>>(cat96, up1_cw, up1_cb, c96, 128, 64, 96, 96, 4, EP_RELU);
    convT4x4_s2<16><<<dim3(12, 12, 4), blk>>>(c96, up1_tw, up1_tb, featf, 64, 64, 96, 96, 192, 192);

    // Offsets + masks (Cout=189 -> 12 chunks of 16)
    conv3x3_s1<8><<<dim3(6, 12, 12), blk>>>(featf, om_w, om_b, offm, 64, 189, 192, 192, 12, EP_NONE);

    // Modulated deformable conv + ReLU -> output
    deform_kernel<<<HW0 / 128, dim3(128)>>>(lqs, offm, dc_w, dc_b, outp);
}

// round 15
// speedup vs baseline: 2.1524x; 1.3502x over previous
#include <cuda_runtime.h>
#include <cuda_fp16.h>
#include <math.h>
#include <stdint.h>

#define NF 64
#define TT 7
#define H0 192
#define W0 192
#define HW0 (H0 * W0)

#define BIGSZ (7 * 64 * HW0)
#define OFF_FEAT   0
#define OFF_PRED   (OFF_FEAT + BIGSZ)
#define OFF_ALG    (OFF_PRED + BIGSZ)
#define OFF_H2     (OFF_ALG + BIGSZ)            // NHWC fp16 (u32 pairs), 14 imgs
#define OFF_OUT0   (OFF_H2 + BIGSZ)
#define OFF_OUT1   (OFF_OUT0 + 64 * HW0)
#define OFF_OUT2   (OFF_OUT1 + 64 * 96 * 96)
#define OFF_U24    (OFF_OUT2 + 64 * 48 * 48)
#define OFF_CAT48  (OFF_U24 + 64 * 24 * 24)
#define OFF_C48    (OFF_CAT48 + 128 * 48 * 48)
#define OFF_CAT96  (OFF_C48 + 64 * 48 * 48)
#define OFF_C96    (OFF_CAT96 + 128 * 96 * 96)
#define OFF_FEATF  (OFF_C96 + 64 * 96 * 96)
#define OFF_OFFM   (OFF_FEATF + 64 * HW0)
#define OFF_WB     (OFF_OFFM + 189 * HW0)       // Bt image 64*292 u32
#define SCRATCH_TOTAL (OFF_WB + 64 * 292)

__device__ float g_scratch[SCRATCH_TOTAL];

enum { EP_NONE = 0, EP_RELU = 1, EP_H2 = 2 };

typedef unsigned long long ull_t;
__device__ __forceinline__ ull_t pack2s(float v) {
    ull_t r; asm("mov.b64 %0, {%1, %1};" : "=l"(r) : "f"(v)); return r;
}
__device__ __forceinline__ ull_t pack2(float lo, float hi) {
    ull_t r; asm("mov.b64 %0, {%1, %2};" : "=l"(r) : "f"(lo), "f"(hi)); return r;
}
__device__ __forceinline__ void ffma2(ull_t& d, ull_t a, ull_t b) {
    asm("fma.rn.f32x2 %0, %1, %2, %0;" : "+l"(d) : "l"(a), "l"(b));
}
__device__ __forceinline__ float2 unpack2(ull_t v) {
    float lo, hi; asm("mov.b64 {%0, %1}, %2;" : "=f"(lo), "=f"(hi) : "l"(v));
    return make_float2(lo, hi);
}
__device__ __forceinline__ float fsigmoid(float x) { return 1.f / (1.f + __expf(-x)); }

__device__ __forceinline__ uint32_t smem_u32(const void* p) {
    return (uint32_t)__cvta_generic_to_shared(p);
}
__device__ __forceinline__ void cp_async4(uint32_t s, const float* g, bool ok) {
    asm volatile("cp.async.ca.shared.global [%0], [%1], 4, %2;"
                 :: "r"(s), "l"(g), "r"(ok ? 4u : 0u));
}
__device__ __forceinline__ void cp_async16(uint32_t s, const void* g, bool ok) {
    asm volatile("cp.async.cg.shared.global [%0], [%1], 16, %2;"
                 :: "r"(s), "l"(g), "r"(ok ? 16u : 0u));
}
#define CP_COMMIT() asm volatile("cp.async.commit_group;")
#define CP_WAIT0()  asm volatile("cp.async.wait_group 0;")

__device__ __forceinline__ void mma16816(float* d, const uint32_t* a,
                                         uint32_t b0, uint32_t b1) {
    asm volatile("mma.sync.aligned.m16n8k16.row.col.f32.f16.f16.f32 "
        "{%0,%1,%2,%3}, {%4,%5,%6,%7}, {%8,%9}, {%0,%1,%2,%3};"
        : "+f"(d[0]), "+f"(d[1]), "+f"(d[2]), "+f"(d[3])
        : "r"(a[0]), "r"(a[1]), "r"(a[2]), "r"(a[3]), "r"(b0), "r"(b1));
}

// ---------------------------------------------------------------------------
// 3x3 s1 conv, FFMA2, cp.async double-buffered, CBS=8.
// EP_H2: write NHWC fp16 (u32 cin-pairs, 32 u32 per pixel).
// ---------------------------------------------------------------------------
#define CBS 8
#define CB4 4
#define SMC 40
template <int NP>
__global__ void __launch_bounds__(256, 3) conv3x3_s1(
    const float* __restrict__ in, const float* __restrict__ wgt,
    const float* __restrict__ bias, float* __restrict__ out,
    uint32_t* __restrict__ h2out,
    int Cin, int Cout, int H, int W, int nChunks, int ep)
{
    const int CO = 2 * NP;
    __shared__ alignas(16) float s_in[2][CBS][18][SMC];
    __shared__ alignas(16) float s_w[2][CBS][9][2 * NP];

    const int img = blockIdx.z / nChunks, chunk = blockIdx.z % nChunks;
    const int ox0 = blockIdx.x * 32, oy0 = blockIdx.y * 16;
    const int tid = threadIdx.x, tx = tid & 15, ty = tid >> 4;
    const float* inB = in + (size_t)img * Cin * H * W;
    const int coBase = chunk * CO;

    ull_t acc0[NP], acc1[NP];
#pragma unroll
    for (int j = 0; j < NP; j++) { acc0[j] = 0ull; acc1[j] = 0ull; }

    const int nB = (Cin + CBS - 1) / CBS;
    auto stage = [&](int buf, int b) {
        const int c0 = b * CBS, nc = min(CBS, Cin - c0);
        for (int i = tid; i < nc * 144; i += 256) {
            int cb = i / 144, rem = i - cb * 144, r = rem >> 3, k = rem & 7;
            int gy = oy0 - 1 + r, gx = ox0 + 4 * k;
            bool ok = (gy >= 0 && gy < H) && (gx + 3 < W);
            cp_async16(smem_u32(&s_in[buf][cb][r][4 + 4 * k]),
                       inB + ((size_t)(c0 + cb) * H + (ok ? gy : 0)) * W + (ok ? gx : 0), ok);
        }
        for (int i = tid; i < nc * 36; i += 256) {
            int cb = i / 36, rem = i - cb * 36, r = rem >> 1, e = rem & 1;
            int gy = oy0 - 1 + r, gx = e ? (ox0 + 32) : (ox0 - 1), col = e ? 36 : 3;
            bool ok = (gy >= 0 && gy < H && gx >= 0 && gx < W);
            cp_async4(smem_u32(&s_in[buf][cb][r][col]),
                      inB + ((size_t)(c0 + cb) * H + (ok ? gy : 0)) * W + (ok ? gx : 0), ok);
        }
        for (int i = tid; i < nc * 9 * CO; i += 256) {
            int cb = i / (9 * CO), rem = i - cb * (9 * CO), co = rem / 9, t = rem - co * 9;
            int cog = coBase + co; bool ok = (cog < Cout);
            cp_async4(smem_u32(&s_w[buf][cb][t][co]),
                      wgt + ((size_t)(ok ? cog : 0) * Cin + (c0 + cb)) * 9 + t, ok);
        }
        CP_COMMIT();
    };

    stage(0, 0);
    for (int b = 0; b < nB; b++) {
        CP_WAIT0();
        __syncthreads();
        if (b + 1 < nB) stage((b + 1) & 1, b + 1);
        const int buf = b & 1, nc = min(CBS, Cin - b * CBS);
        for (int cb = 0; cb < nc; cb++) {
#pragma unroll
            for (int dy = 0; dy < 3; dy++) {
                ull_t ps[4];
#pragma unroll
                for (int j = 0; j < 4; j++)
                    ps[j] = pack2s(s_in[buf][cb][ty + dy][2 * tx + j + 3]);
#pragma unroll
                for (int dx = 0; dx < 3; dx++) {
                    const int t = dy * 3 + dx;
#pragma unroll
                    for (int q2 = 0; q2 < NP / 2; q2++) {
                        ulonglong2 w = *reinterpret_cast<const ulonglong2*>(&s_w[buf][cb][t][4 * q2]);
                        ffma2(acc0[2 * q2],     ps[dx],     w.x);
                        ffma2(acc0[2 * q2 + 1], ps[dx],     w.y);
                        ffma2(acc1[2 * q2],     ps[dx + 1], w.x);
                        ffma2(acc1[2 * q2 + 1], ps[dx + 1], w.y);
                    }
                }
            }
        }
    }

    const int oy = oy0 + ty, oxb = ox0 + 2 * tx;
    if (oy >= H || oxb >= W) return;
    const size_t HWs = (size_t)H * W;

    if (ep == EP_H2) {
        // NHWC fp16: u32 j of pixel = cin pair (coBase+2j, coBase+2j+1)
        uint32_t* hp = h2out + ((size_t)img * HWs + (size_t)oy * W + oxb) * 32 + chunk * 8;
        uint32_t v0[8], v1[8];
#pragma unroll
        for (int j = 0; j < NP; j++) {
            float2 u0 = unpack2(acc0[j]), u1 = unpack2(acc1[j]);
            float b0 = __ldg(bias + coBase + 2 * j);
            float b1 = __ldg(bias + coBase + 2 * j + 1);
            __half2 h0 = __floats2half2_rn(u0.x + b0, u0.y + b1);
            __half2 h1 = __floats2half2_rn(u1.x + b0, u1.y + b1);
            v0[j] = *reinterpret_cast<uint32_t*>(&h0);
            v1[j] = *reinterpret_cast<uint32_t*>(&h1);
        }
        *reinterpret_cast<uint4*>(hp)      = make_uint4(v0[0], v0[1], v0[2], v0[3]);
        *reinterpret_cast<uint4*>(hp + 4)  = make_uint4(v0[4], v0[5], v0[6], v0[7]);
        *reinterpret_cast<uint4*>(hp + 32) = make_uint4(v1[0], v1[1], v1[2], v1[3]);
        *reinterpret_cast<uint4*>(hp + 36) = make_uint4(v1[4], v1[5], v1[6], v1[7]);
        return;
    }

    float* ob = out + (size_t)img * Cout * HWs + (size_t)oy * W + oxb;
#pragma unroll
    for (int j = 0; j < NP; j++) {
        float2 u0 = unpack2(acc0[j]), u1 = unpack2(acc1[j]);
#pragma unroll
        for (int s = 0; s < 2; s++) {
            int cog = coBase + 2 * j + s;
            if (cog >= Cout) continue;
            float b = __ldg(bias + cog);
            float2 o;
            o.x = (s ? u0.y : u0.x) + b;
            o.y = (s ? u1.y : u1.x) + b;
            if (ep == EP_RELU) { o.x = fmaxf(o.x, 0.f); o.y = fmaxf(o.y, 0.f); }
            *reinterpret_cast<float2*>(ob + (size_t)cog * HWs) = o;
        }
    }
}

// ---------------------------------------------------------------------------
// Bt prep: fp16 [cout][k] image, k = tap*64+cin, row stride 292 u32 (padded).
// ---------------------------------------------------------------------------
__global__ void prep_bt_kernel(const float* __restrict__ w, uint32_t* __restrict__ bt)
{
    int i = blockIdx.x * 256 + threadIdx.x;
    if (i >= 64 * 292) return;
    int cout = i / 292, j = i - cout * 292;
    uint32_t v = 0;
    if (j < 288) {
        int tap = j / 32, cin0 = 2 * (j % 32);
        __half2 h = __floats2half2_rn(w[((size_t)cout * 64 + cin0) * 9 + tap],
                                      w[((size_t)cout * 64 + cin0 + 1) * 9 + tap]);
        v = *reinterpret_cast<uint32_t*>(&h);
    }
    bt[i] = v;
}

// ---------------------------------------------------------------------------
// conv2 via mma.sync m16n8k16 fp16. Tile M=64 px (1 row) x N=64 cout, K=576.
// 144 blocks x 256 thr (8 warps: 4 M16 x 2 N32), 56 tiles each.
// Dyn smem u32: Bt[64*292], raw[2][3*66*76] (pixel row = 64 cin fp16, pad 76).
// ---------------------------------------------------------------------------
__global__ void __launch_bounds__(256, 1) conv2_mma_kernel(
    const uint32_t* __restrict__ h2in, const uint32_t* __restrict__ btimg,
    const float* __restrict__ bias, float* __restrict__ outF)
{
    extern __shared__ __align__(16) uint32_t sm[];
    const int RAW = 64 * 292;             // 18688
    const int RBUF = 3 * 66 * 76;         // 15048
    uint32_t sb = smem_u32(sm);
    const int tid = threadIdx.x, lane = tid & 31, w = tid >> 5;
    const int wm = w & 3, wn = w >> 2;
    const int g = lane >> 2, t = lane & 3;
    const int p0 = wm * 16;

    for (int i = tid; i < 4672; i += 256)
        cp_async16(sb + i * 16, btimg + i * 4, true);

    auto stage_raw = [&](int buf, int tile) {
        int img = tile / 576, rem = tile % 576;
        int y = rem / 3, x0 = (rem % 3) * 64;
        const uint32_t* src = h2in + (size_t)img * HW0 * 32;
        for (int i = tid; i < 1584; i += 256) {
            int pr = i >> 3, c = i & 7;
            int r = pr / 66, j = pr - r * 66;
            int gy = y - 1 + r, gx = x0 - 1 + j;
            bool ok = (gy >= 0 && gy < 192 && gx >= 0 && gx < 192);
            cp_async16(sb + (uint32_t)(RAW + buf * RBUF + (r * 66 + j) * 76 + c * 4) * 4,
                       src + ((size_t)(ok ? gy : 0) * 192 + (ok ? gx : 0)) * 32 + c * 4, ok);
        }
        CP_COMMIT();
    };

    const int tile0 = blockIdx.x * 56;
    stage_raw(0, tile0);

    for (int it = 0; it < 56; it++) {
        const int tile = tile0 + it;
        CP_WAIT0();
        __syncthreads();
        if (it + 1 < 56) stage_raw((it + 1) & 1, tile + 1);
        const uint32_t* raw = sm + RAW + (it & 1) * RBUF;
        const uint32_t* bt = sm;

        float acc[4][4];
#pragma unroll
        for (int nb = 0; nb < 4; nb++)
#pragma unroll
            for (int q = 0; q < 4; q++) acc[nb][q] = 0.f;

#pragma unroll
        for (int tap = 0; tap < 9; tap++) {
            const int dy = tap / 3, dx = tap % 3;
            const uint32_t* r0 = raw + (dy * 66 + p0 + g + dx) * 76;
            const uint32_t* r1 = r0 + 8 * 76;
#pragma unroll
            for (int s = 0; s < 4; s++) {
                uint32_t a[4];
                a[0] = r0[8 * s + t];
                a[2] = r0[8 * s + t + 4];
                a[1] = r1[8 * s + t];
                a[3] = r1[8 * s + t + 4];
#pragma unroll
                for (int nb = 0; nb < 4; nb++) {
                    const uint32_t* bp = bt + (wn * 32 + nb * 8 + g) * 292 + tap * 32 + 8 * s + t;
                    mma16816(acc[nb], a, bp[0], bp[4]);
                }
            }
        }

        const int img = tile / 576, rem = tile % 576;
        const int y = rem / 3, x0 = (rem % 3) * 64;
        float* ob = outF + (size_t)img * 64 * HW0 + (size_t)y * 192 + x0 + p0 + g;
#pragma unroll
        for (int nb = 0; nb < 4; nb++) {
            int n0 = wn * 32 + nb * 8 + 2 * t;
            float b0 = __ldg(bias + n0), b1 = __ldg(bias + n0 + 1);
            ob[(size_t)n0 * HW0]           = acc[nb][0] + b0;
            ob[(size_t)(n0 + 1) * HW0]     = acc[nb][1] + b1;
            ob[(size_t)n0 * HW0 + 8]       = acc[nb][2] + b0;
            ob[(size_t)(n0 + 1) * HW0 + 8] = acc[nb][3] + b1;
        }
    }
}

// ---------------------------------------------------------------------------
// Dual-input shared-weight 3x3 conv (fusion pair).
// ---------------------------------------------------------------------------
__global__ void __launch_bounds__(256, 2) conv3x3_s1_dual(
    const float* __restrict__ inA, const float* __restrict__ inF,
    const float* __restrict__ wgt, const float* __restrict__ bias,
    float* __restrict__ out, int Cin, int Cout)
{
    __shared__ alignas(16) float s_a[2][CB4][18][SMC];
    __shared__ alignas(16) float s_f[2][CB4][18][SMC];
    __shared__ alignas(16) float s_w[2][CB4][9][16];

    const int chunk = blockIdx.z;
    const int ox0 = blockIdx.x * 32, oy0 = blockIdx.y * 16;
    const int tid = threadIdx.x, tx = tid & 15, ty = tid >> 4;
    const int coBase = chunk * 16;
    const int H = H0, W = W0;

    ull_t aA0[8], aA1[8], aF0[8], aF1[8];
#pragma unroll
    for (int j = 0; j < 8; j++) { aA0[j] = aA1[j] = aF0[j] = aF1[j] = 0ull; }

    const int nB = (Cin + CB4 - 1) / CB4;
    auto stage = [&](int buf, int b) {
        const int c0 = b * CB4, nc = min(CB4, Cin - c0);
        for (int i = tid; i < nc * 144; i += 256) {
            int cb = i / 144, rem = i - cb * 144, r = rem >> 3, k = rem & 7;
            int gy = oy0 - 1 + r, gx = ox0 + 4 * k;
            bool ok = (gy >= 0 && gy < H) && (gx + 3 < W);
            size_t gidx = ((size_t)(c0 + cb) * H + (ok ? gy : 0)) * W + (ok ? gx : 0);
            cp_async16(smem_u32(&s_a[buf][cb][r][4 + 4 * k]), inA + gidx, ok);
            cp_async16(smem_u32(&s_f[buf][cb][r][4 + 4 * k]), inF + gidx, ok);
        }
        for (int i = tid; i < nc * 36; i += 256) {
            int cb = i / 36, rem = i - cb * 36, r = rem >> 1, e = rem & 1;
            int gy = oy0 - 1 + r, gx = e ? (ox0 + 32) : (ox0 - 1), col = e ? 36 : 3;
            bool ok = (gy >= 0 && gy < H && gx >= 0 && gx < W);
            size_t gidx = ((size_t)(c0 + cb) * H + (ok ? gy : 0)) * W + (ok ? gx : 0);
            cp_async4(smem_u32(&s_a[buf][cb][r][col]), inA + gidx, ok);
            cp_async4(smem_u32(&s_f[buf][cb][r][col]), inF + gidx, ok);
        }
        for (int i = tid; i < nc * 144; i += 256) {
            int cb = i / 144, rem = i - cb * 144, co = rem / 9, t = rem - co * 9;
            cp_async4(smem_u32(&s_w[buf][cb][t][co]),
                      wgt + ((size_t)(coBase + co) * Cin + (c0 + cb)) * 9 + t, true);
        }
        CP_COMMIT();
    };

    stage(0, 0);
    for (int b = 0; b < nB; b++) {
        CP_WAIT0();
        __syncthreads();
        if (b + 1 < nB) stage((b + 1) & 1, b + 1);
        const int buf = b & 1, nc = min(CB4, Cin - b * CB4);
        for (int cb = 0; cb < nc; cb++) {
#pragma unroll
            for (int dy = 0; dy < 3; dy++) {
                ull_t pa[4], pf[4];
#pragma unroll
                for (int j = 0; j < 4; j++) {
                    pa[j] = pack2s(s_a[buf][cb][ty + dy][2 * tx + j + 3]);
                    pf[j] = pack2s(s_f[buf][cb][ty + dy][2 * tx + j + 3]);
                }
#pragma unroll
                for (int dx = 0; dx < 3; dx++) {
                    const int t = dy * 3 + dx;
#pragma unroll
                    for (int q2 = 0; q2 < 4; q2++) {
                        ulonglong2 w = *reinterpret_cast<const ulonglong2*>(&s_w[buf][cb][t][4 * q2]);
                        ffma2(aA0[2 * q2],     pa[dx],     w.x);
                        ffma2(aA0[2 * q2 + 1], pa[dx],     w.y);
                        ffma2(aA1[2 * q2],     pa[dx + 1], w.x);
                        ffma2(aA1[2 * q2 + 1], pa[dx + 1], w.y);
                        ffma2(aF0[2 * q2],     pf[dx],     w.x);
                        ffma2(aF0[2 * q2 + 1], pf[dx],     w.y);
                        ffma2(aF1[2 * q2],     pf[dx + 1], w.x);
                        ffma2(aF1[2 * q2 + 1], pf[dx + 1], w.y);
                    }
                }
            }
        }
    }

    const int oy = oy0 + ty, oxb = ox0 + 2 * tx;
    const size_t HWs = (size_t)H * W;
    float* ob = out + (size_t)oy * W + oxb;

#pragma unroll
    for (int j = 0; j < 8; j++) {
        float2 A0 = unpack2(aA0[j]), A1 = unpack2(aA1[j]);
        float2 F0 = unpack2(aF0[j]), F1 = unpack2(aF1[j]);
#pragma unroll
        for (int s = 0; s < 2; s++) {
            int cog = coBase + 2 * j + s;
            float b = __ldg(bias + cog);
            float va0 = (s ? A0.y : A0.x) + b;
            float va1 = (s ? A1.y : A1.x) + b;
            float vf0 = (s ? F0.y : F0.x) + b;
            float vf1 = (s ? F1.y : F1.x) + b;
            va0 = va0 > 0.f ? va0 : 0.1f * va0;
            va1 = va1 > 0.f ? va1 : 0.1f * va1;
            vf0 = vf0 > 0.f ? vf0 : 0.1f * vf0;
            vf1 = vf1 > 0.f ? vf1 : 0.1f * vf1;
            float2 o = make_float2(0.1f * va0 + vf0, 0.1f * va1 + vf1);
            *reinterpret_cast<float2*>(ob + (size_t)cog * HWs) = o;
        }
    }
}

// ---------------------------------------------------------------------------
// 3x3 stride-2 conv, 16x16 tile, 8 cis per sync.
// ---------------------------------------------------------------------------
#define SCB 8
template <int CO>
__global__ void __launch_bounds__(256) conv3x3_s2(
    const float* __restrict__ in, const float* __restrict__ wgt,
    const float* __restrict__ bias, float* __restrict__ out,
    int Cin, int Cout, int Hin, int Win, int Hout, int Wout)
{
    __shared__ float s_in[SCB][33][33];
    __shared__ alignas(16) float s_w[SCB][9][CO];

    const int chunk = blockIdx.z;
    const int ox0 = blockIdx.x * 16, oy0 = blockIdx.y * 16;
    const int tid = threadIdx.x, tx = tid & 15, ty = tid >> 4;
    const int coBase = chunk * CO;

    float acc[CO];
#pragma unroll
    for (int i = 0; i < CO; i++) acc[i] = 0.f;

    for (int c0 = 0; c0 < Cin; c0 += SCB) {
        const int nc = min(SCB, Cin - c0);
        for (int i = tid; i < nc * 1089; i += 256) {
            int cb = i / 1089, rem = i - cb * 1089, r = rem / 33, c = rem - r * 33;
            int gy = 2 * oy0 - 1 + r, gx = 2 * ox0 - 1 + c;
            s_in[cb][r][c] = (gy >= 0 && gy < Hin && gx >= 0 && gx < Win)
                ? __ldg(in + ((size_t)(c0 + cb) * Hin + gy) * Win + gx) : 0.f;
        }
        for (int i = tid; i < nc * 9 * CO; i += 256) {
            int cb = i / (9 * CO), rem = i - cb * (9 * CO), co = rem / 9, t = rem - co * 9;
            int cog = coBase + co;
            s_w[cb][t][co] = (cog < Cout)
                ? __ldg(wgt + ((size_t)cog * Cin + (c0 + cb)) * 9 + t) : 0.f;
        }
        __syncthreads();
        for (int cb = 0; cb < nc; cb++) {
            float v[9];
#pragma unroll
            for (int t = 0; t < 9; t++) v[t] = s_in[cb][2 * ty + t / 3][2 * tx + t % 3];
#pragma unroll
            for (int t = 0; t < 9; t++) {
#pragma unroll
                for (int q = 0; q < CO / 4; q++) {
                    float4 w = *reinterpret_cast<const float4*>(&s_w[cb][t][4 * q]);
                    acc[4 * q + 0] += v[t] * w.x; acc[4 * q + 1] += v[t] * w.y;
                    acc[4 * q + 2] += v[t] * w.z; acc[4 * q + 3] += v[t] * w.w;
                }
            }
        }
        __syncthreads();
    }

    const int ox = ox0 + tx, oy = oy0 + ty;
    if (ox >= Wout || oy >= Hout) return;
    size_t pbase = (size_t)oy * Wout + ox;
#pragma unroll
    for (int co = 0; co < CO; co++) {
        int cog = coBase + co;
        if (cog >= Cout) break;
        float v = acc[co] + __ldg(bias + cog);
        out[(size_t)cog * Hout * Wout + pbase] = fmaxf(v, 0.f);
    }
}

// ---------------------------------------------------------------------------
// ConvTranspose2d k4 s2 p1, ReLU, 8 cis per sync.
// ---------------------------------------------------------------------------
template <int CO>
__global__ void __launch_bounds__(256) convT4x4_s2(
    const float* __restrict__ in, const float* __restrict__ wgt,
    const float* __restrict__ bias, float* __restrict__ out,
    int Cin, int Cout, int Hin, int Win, int Hout, int Wout)
{
    __shared__ float s_in[SCB][10][10];
    __shared__ alignas(16) float s_w[SCB][16][CO];

    const int chunk = blockIdx.z;
    const int ox0 = blockIdx.x * 16, oy0 = blockIdx.y * 16;
    const int tid = threadIdx.x, tx = tid & 15, ty = tid >> 4;
    const int coBase = chunk * CO;
    const int iy0 = oy0 / 2 - 1, ix0 = ox0 / 2 - 1;

    const int oy = oy0 + ty, ox = ox0 + tx;
    const int py = (oy + 1) & 1, px = (ox + 1) & 1;
    const int r0 = ((oy + 1 - py) >> 1) - iy0, r1 = r0 - 1;
    const int c0i = ((ox + 1 - px) >> 1) - ix0, c1i = c0i - 1;

    float acc[CO];
#pragma unroll
    for (int i = 0; i < CO; i++) acc[i] = 0.f;

    for (int c0 = 0; c0 < Cin; c0 += SCB) {
        const int nc = min(SCB, Cin - c0);
        for (int i = tid; i < nc * 100; i += 256) {
            int cb = i / 100, rem = i - cb * 100, r = rem / 10, c = rem - r * 10;
            int gy = iy0 + r, gx = ix0 + c;
            s_in[cb][r][c] = (gy >= 0 && gy < Hin && gx >= 0 && gx < Win)
                ? __ldg(in + ((size_t)(c0 + cb) * Hin + gy) * Win + gx) : 0.f;
        }
        for (int i = tid; i < nc * 16 * CO; i += 256) {
            int cb = i / (16 * CO), rem = i - cb * (16 * CO), co = rem / 16, t = rem - co * 16;
            int cog = coBase + co;
            s_w[cb][t][co] = (cog < Cout)
                ? __ldg(wgt + ((size_t)(c0 + cb) * Cout + cog) * 16 + t) : 0.f;
        }
        __syncthreads();
        for (int cb = 0; cb < nc; cb++) {
            float v00 = s_in[cb][r0][c0i], v01 = s_in[cb][r0][c1i];
            float v10 = s_in[cb][r1][c0i], v11 = s_in[cb][r1][c1i];
#pragma unroll
            for (int a = 0; a < 2; a++) {
#pragma unroll
                for (int b = 0; b < 2; b++) {
                    float v = a ? (b ? v11 : v10) : (b ? v01 : v00);
                    int t = (py + 2 * a) * 4 + (px + 2 * b);
#pragma unroll
                    for (int q = 0; q < CO / 4; q++) {
                        float4 w = *reinterpret_cast<const float4*>(&s_w[cb][t][4 * q]);
                        acc[4 * q + 0] += v * w.x; acc[4 * q + 1] += v * w.y;
                        acc[4 * q + 2] += v * w.z; acc[4 * q + 3] += v * w.w;
                    }
                }
            }
        }
        __syncthreads();
    }

    if (ox >= Wout || oy >= Hout) return;
    size_t pbase = (size_t)oy * Wout + ox;
#pragma unroll
    for (int co = 0; co < CO; co++) {
        int cog = coBase + co;
        if (cog >= Cout) break;
        float v = acc[co] + __ldg(bias + cog);
        out[(size_t)cog * Hout * Wout + pbase] = fmaxf(v, 0.f);
    }
}

// ---------------------------------------------------------------------------
// Fused flow-warp + gate.
// ---------------------------------------------------------------------------
__global__ void warp_gate_kernel(const float* __restrict__ feat,
                                 const float* __restrict__ pred,
                                 const float* __restrict__ mv,
                                 float* __restrict__ alg)
{
    const int pix = blockIdx.x * 256 + threadIdx.x;
    if (pix >= HW0) return;
    const int t = blockIdx.y;

    float wgt[4]; int off[4]; bool val[4];
    const float* fb = nullptr;
    if (t > 0) {
        const int y = pix / W0, x = pix - y * W0;
        const float fx = mv[(size_t)(t - 1) * HW0 * 2 + (size_t)pix * 2 + 0];
        const float fy = mv[(size_t)(t - 1) * HW0 * 2 + (size_t)pix * 2 + 1];
        const float ys = (float)y + fy, xs = (float)x + fx;
        const float y0 = floorf(ys), x0 = floorf(xs);
        const float wy = ys - y0, wx = xs - x0;
#pragma unroll
        for (int i = 0; i < 4; i++) {
            int dy = i >> 1, dx = i & 1;
            float yi = y0 + dy, xi = x0 + dx;
            val[i] = (yi >= 0.f) && (yi <= (float)(H0 - 1)) &&
                     (xi >= 0.f) && (xi <= (float)(W0 - 1));
            wgt[i] = (dy ? wy : 1.f - wy) * (dx ? wx : 1.f - wx);
            off[i] = val[i] ? ((int)yi * W0 + (int)xi) : 0;
        }
        fb = feat + (size_t)(t - 1) * 64 * HW0;
    }

    const float* refb = feat + (size_t)3 * 64 * HW0 + pix;
    const float* prb  = pred + (size_t)t * 64 * HW0 + pix;
    const float* f0b  = feat + pix;
    float* ob = alg + (size_t)t * 64 * HW0 + pix;

    for (int c = 0; c < 64; c++) {
        float a;
        if (t == 0) {
            a = __ldg(f0b + (size_t)c * HW0);
        } else {
            const float* img = fb + (size_t)c * HW0;
            a = 0.f;
#pragma unroll
            for (int i = 0; i < 4; i++)
                if (val[i]) a += __ldg(img + off[i]) * wgt[i];
        }
        float ref = __ldg(refb + (size_t)c * HW0);
        float p   = __ldg(prb + (size_t)c * HW0);
        ob[(size_t)c * HW0] = a * fsigmoid(a * ref) + p * fsigmoid(p * ref);
    }
}

// ---------------------------------------------------------------------------
// Modulated deformable conv.
// ---------------------------------------------------------------------------
__global__ void __launch_bounds__(128) deform_kernel(
    const float* __restrict__ lqs, const float* __restrict__ offm,
    const float* __restrict__ dcw, const float* __restrict__ dcb,
    float* __restrict__ out)
{
    __shared__ alignas(16) float s_w[63 * 64];
    __shared__ float s_b[64];
    const int tid = threadIdx.x;
    for (int i = tid; i < 63 * 64; i += 128) {
        int o = i / 63, j = i - o * 63;
        s_w[j * 64 + o] = dcw[i];
    }
    if (tid < 64) s_b[tid] = dcb[tid];
    __syncthreads();

    const int pix = blockIdx.x * 128 + tid;
    if (pix >= HW0) return;
    const int y = pix / W0, x = pix - y * W0;

    ull_t acc[32];
#pragma unroll
    for (int q = 0; q < 32; q++) acc[q] = pack2(s_b[2 * q], s_b[2 * q + 1]);

    for (int g = 0; g < 7; g++) {
        const float* img = lqs + (size_t)g * HW0;
#pragma unroll
        for (int k = 0; k < 9; k++) {
            const int j = g * 9 + k;
            float offy = __ldg(offm + (size_t)(g * 18 + 2 * k + 0) * HW0 + pix);
            float offx = __ldg(offm + (size_t)(g * 18 + 2 * k + 1) * HW0 + pix);
            float mraw = __ldg(offm + (size_t)(126 + j) * HW0 + pix);
            float m = fsigmoid(mraw);
            float ys = (float)(y + k / 3 - 1) + offy;
            float xs = (float)(x + k % 3 - 1) + offx;
            float y0 = floorf(ys), x0 = floorf(xs);
            float wy = ys - y0, wx = xs - x0;
            float samp = 0.f;
#pragma unroll
            for (int ii = 0; ii < 4; ii++) {
                int dy = ii >> 1, dx = ii & 1;
                float yi = y0 + dy, xi = x0 + dx;
                if (yi >= 0.f && yi <= (float)(H0 - 1) &&
                    xi >= 0.f && xi <= (float)(W0 - 1))
                    samp += __ldg(img + (int)yi * W0 + (int)xi) *
                            ((dy ? wy : 1.f - wy) * (dx ? wx : 1.f - wx));
            }
            ull_t mod2 = pack2s(samp * m);
#pragma unroll
            for (int q2 = 0; q2 < 16; q2++) {
                ulonglong2 w = *reinterpret_cast<const ulonglong2*>(&s_w[j * 64 + 4 * q2]);
                ffma2(acc[2 * q2],     mod2, w.x);
                ffma2(acc[2 * q2 + 1], mod2, w.y);
            }
        }
    }
#pragma unroll
    for (int q = 0; q < 32; q++) {
        float2 u = unpack2(acc[q]);
        out[(size_t)(2 * q) * HW0 + pix]     = fmaxf(u.x, 0.f);
        out[(size_t)(2 * q + 1) * HW0 + pix] = fmaxf(u.y, 0.f);
    }
}

// ---------------------------------------------------------------------------
// Host orchestration (graph-capturable)
// ---------------------------------------------------------------------------
extern "C" void kernel_launch(void* const* d_in, const int* in_sizes, int n_in,
                              void* d_out, int out_size)
{
    const float* lqs    = (const float*)d_in[0];
    const float* preds  = (const float*)d_in[1];
    const float* mv     = (const float*)d_in[2];
    const float* bw1    = (const float*)d_in[3];
    const float* bb1    = (const float*)d_in[4];
    const float* bw2    = (const float*)d_in[5];
    const float* bb2    = (const float*)d_in[6];
    const float* dn1_w  = (const float*)d_in[7];
    const float* dn1_b  = (const float*)d_in[8];
    const float* dn2_w  = (const float*)d_in[9];
    const float* dn2_b  = (const float*)d_in[10];
    const float* up1_cw = (const float*)d_in[11];
    const float* up1_cb = (const float*)d_in[12];
    const float* up1_tw = (const float*)d_in[13];
    const float* up1_tb = (const float*)d_in[14];
    const float* up2_cw = (const float*)d_in[15];
    const float* up2_cb = (const float*)d_in[16];
    const float* up2_tw = (const float*)d_in[17];
    const float* up2_tb = (const float*)d_in[18];
    const float* tr_cw  = (const float*)d_in[19];
    const float* tr_cb  = (const float*)d_in[20];
    const float* tr_tw  = (const float*)d_in[21];
    const float* tr_tb  = (const float*)d_in[22];
    const float* ff_w   = (const float*)d_in[23];
    const float* ff_b   = (const float*)d_in[24];
    const float* om_w   = (const float*)d_in[25];
    const float* om_b   = (const float*)d_in[26];
    const float* dc_w   = (const float*)d_in[27];
    const float* dc_b   = (const float*)d_in[28];
    float* outp = (float*)d_out;

    float* S = nullptr;
    cudaGetSymbolAddress((void**)&S, g_scratch);
    float* feat  = S + OFF_FEAT;
    float* pred  = S + OFF_PRED;
    float* alg   = S + OFF_ALG;
    uint32_t* h2buf = (uint32_t*)(S + OFF_H2);
    uint32_t* btimg = (uint32_t*)(S + OFF_WB);
    float* out0  = S + OFF_OUT0;
    float* out1  = S + OFF_OUT1;
    float* out2  = S + OFF_OUT2;
    float* u24   = S + OFF_U24;
    float* cat48 = S + OFF_CAT48;
    float* c48   = S + OFF_C48;
    float* cat96 = S + OFF_CAT96;
    float* c96   = S + OFF_C96;
    float* featf = S + OFF_FEATF;
    float* offm  = S + OFF_OFFM;

    cudaFuncSetAttribute(conv2_mma_kernel,
                         cudaFuncAttributeMaxDynamicSharedMemorySize, 195136);

    dim3 blk(256);

    // conv1 (1->64) -> NHWC fp16: lqs imgs 0..6, preds imgs 7..13
    conv3x3_s1<8><<<dim3(6, 12, 7 * 4), blk>>>(lqs,   bw1, bb1, nullptr, h2buf,
                                               1, 64, 192, 192, 4, EP_H2);
    conv3x3_s1<8><<<dim3(6, 12, 7 * 4), blk>>>(preds, bw1, bb1, nullptr,
                                               h2buf + (size_t)7 * HW0 * 32,
                                               1, 64, 192, 192, 4, EP_H2);
    // conv2 via mma.sync (14 imgs -> [feat|pred] fp32 planar)
    prep_bt_kernel<<<73, blk>>>(bw2, btimg);
    conv2_mma_kernel<<<144, blk, 195136>>>(h2buf, btimg, bb2, feat);

    // gated aligned features
    warp_gate_kernel<<<dim3(HW0 / 256, 7), blk>>>(feat, pred, mv, alg);

    // fusion pair
    conv3x3_s1_dual<<<dim3(6, 12, 4), blk>>>(alg, feat, ff_w, ff_b, out0, 448, 64);

    // down path
    conv3x3_s2<8><<<dim3(6, 6, 8), blk>>>(out0, dn1_w, dn1_b, out1, 64, 64, 192, 192, 96, 96);
    conv3x3_s2<8><<<dim3(3, 3, 8), blk>>>(out1, dn2_w, dn2_b, out2, 64, 64, 96, 96, 48, 48);
    conv3x3_s2<8><<<dim3(2, 2, 8), blk>>>(out2, tr_cw, tr_cb, u24, 64, 64, 48, 48, 24, 24);

    // up path with skip concats
    convT4x4_s2<16><<<dim3(3, 3, 4), blk>>>(u24, tr_tw, tr_tb, cat48, 64, 64, 24, 24, 48, 48);
    cudaMemcpyAsync(cat48 + (size_t)64 * 48 * 48, out2,
                    (size_t)64 * 48 * 48 * sizeof(float), cudaMemcpyDeviceToDevice, 0);
    conv3x3_s1<8><<<dim3(2, 3, 4), blk>>>(cat48, up2_cw, up2_cb, c48, nullptr,
                                          128, 64, 48, 48, 4, EP_RELU);
    convT4x4_s2<16><<<dim3(6, 6, 4), blk>>>(c48, up2_tw, up2_tb, cat96, 64, 64, 48, 48, 96, 96);
    cudaMemcpyAsync(cat96 + (size_t)64 * 96 * 96, out1,
                    (size_t)64 * 96 * 96 * sizeof(float), cudaMemcpyDeviceToDevice, 0);
    conv3x3_s1<8><<<dim3(3, 6, 4), blk>>>(cat96, up1_cw, up1_cb, c96, nullptr,
                                          128, 64, 96, 96, 4, EP_RELU);
    convT4x4_s2<16><<<dim3(12, 12, 4), blk>>>(c96, up1_tw, up1_tb, featf, 64, 64, 96, 96, 192, 192);

    // offsets + masks
    conv3x3_s1<8><<<dim3(6, 12, 12), blk>>>(featf, om_w, om_b, offm, nullptr,
                                            64, 189, 192, 192, 12, EP_NONE);

    // modulated deformable conv -> output
    deform_kernel<<<HW0 / 128, dim3(128)>>>(lqs, offm, dc_w, dc_b, outp);
}

// round 16
// speedup vs baseline: 2.9402x; 1.3660x over previous
#include <cuda_runtime.h>
#include <cuda_fp16.h>
#include <math.h>
#include <stdint.h>

#define NF 64
#define TT 7
#define H0 192
#define W0 192
#define HW0 (H0 * W0)

#define BIGSZ (7 * 64 * HW0)
#define OFF_FEAT   0
#define OFF_PRED   (OFF_FEAT + BIGSZ)
#define OFF_ALG    (OFF_PRED + BIGSZ)           // a16 (7*HW0*32 u32) + f16 (same)
#define OFF_H2     (OFF_ALG + BIGSZ)            // conv1 NHWC fp16, 14 imgs
#define OFF_OUT0   (OFF_H2 + BIGSZ)
#define OFF_OUT1   (OFF_OUT0 + 64 * HW0)
#define OFF_OUT2   (OFF_OUT1 + 64 * 96 * 96)
#define OFF_U24    (OFF_OUT2 + 64 * 48 * 48)
#define OFF_CAT48  (OFF_U24 + 64 * 24 * 24)
#define OFF_C48    (OFF_CAT48 + 128 * 48 * 48)
#define OFF_CAT96  (OFF_C48 + 64 * 48 * 48)
#define OFF_C96    (OFF_CAT96 + 128 * 96 * 96)
#define OFF_FEATF  (OFF_C96 + 64 * 96 * 96)
#define OFF_OFFM   (OFF_FEATF + 64 * HW0)
#define OFF_WB     (OFF_OFFM + 189 * HW0)       // conv2 Bt: 64*292 u32
#define OFF_WBF    (OFF_WB + 64 * 292)          // ff Bt: 64*2020 u32
#define SCRATCH_TOTAL (OFF_WBF + 64 * 2020)

__device__ float g_scratch[SCRATCH_TOTAL];

enum { EP_NONE = 0, EP_RELU = 1, EP_H2 = 2 };

typedef unsigned long long ull_t;
__device__ __forceinline__ ull_t pack2s(float v) {
    ull_t r; asm("mov.b64 %0, {%1, %1};" : "=l"(r) : "f"(v)); return r;
}
__device__ __forceinline__ ull_t pack2(float lo, float hi) {
    ull_t r; asm("mov.b64 %0, {%1, %2};" : "=l"(r) : "f"(lo), "f"(hi)); return r;
}
__device__ __forceinline__ void ffma2(ull_t& d, ull_t a, ull_t b) {
    asm("fma.rn.f32x2 %0, %1, %2, %0;" : "+l"(d) : "l"(a), "l"(b));
}
__device__ __forceinline__ float2 unpack2(ull_t v) {
    float lo, hi; asm("mov.b64 {%0, %1}, %2;" : "=f"(lo), "=f"(hi) : "l"(v));
    return make_float2(lo, hi);
}
__device__ __forceinline__ float fsigmoid(float x) { return 1.f / (1.f + __expf(-x)); }
__device__ __forceinline__ float lrelu(float x) { return x > 0.f ? x : 0.1f * x; }

__device__ __forceinline__ uint32_t smem_u32(const void* p) {
    return (uint32_t)__cvta_generic_to_shared(p);
}
__device__ __forceinline__ void cp_async4(uint32_t s, const float* g, bool ok) {
    asm volatile("cp.async.ca.shared.global [%0], [%1], 4, %2;"
                 :: "r"(s), "l"(g), "r"(ok ? 4u : 0u));
}
__device__ __forceinline__ void cp_async16(uint32_t s, const void* g, bool ok) {
    asm volatile("cp.async.cg.shared.global [%0], [%1], 16, %2;"
                 :: "r"(s), "l"(g), "r"(ok ? 16u : 0u));
}
#define CP_COMMIT() asm volatile("cp.async.commit_group;")
#define CP_WAIT0()  asm volatile("cp.async.wait_group 0;")

__device__ __forceinline__ void mma16816(float* d, const uint32_t* a,
                                         uint32_t b0, uint32_t b1) {
    asm volatile("mma.sync.aligned.m16n8k16.row.col.f32.f16.f16.f32 "
        "{%0,%1,%2,%3}, {%4,%5,%6,%7}, {%8,%9}, {%0,%1,%2,%3};"
        : "+f"(d[0]), "+f"(d[1]), "+f"(d[2]), "+f"(d[3])
        : "r"(a[0]), "r"(a[1]), "r"(a[2]), "r"(a[3]), "r"(b0), "r"(b1));
}

// ---------------------------------------------------------------------------
// 3x3 s1 conv, FFMA2, cp.async double-buffered. EP_H2: NHWC fp16 output.
// ---------------------------------------------------------------------------
#define CBS 8
#define SMC 40
template <int NP>
__global__ void __launch_bounds__(256, 3) conv3x3_s1(
    const float* __restrict__ in, const float* __restrict__ wgt,
    const float* __restrict__ bias, float* __restrict__ out,
    uint32_t* __restrict__ h2out,
    int Cin, int Cout, int H, int W, int nChunks, int ep)
{
    const int CO = 2 * NP;
    __shared__ alignas(16) float s_in[2][CBS][18][SMC];
    __shared__ alignas(16) float s_w[2][CBS][9][2 * NP];

    const int img = blockIdx.z / nChunks, chunk = blockIdx.z % nChunks;
    const int ox0 = blockIdx.x * 32, oy0 = blockIdx.y * 16;
    const int tid = threadIdx.x, tx = tid & 15, ty = tid >> 4;
    const float* inB = in + (size_t)img * Cin * H * W;
    const int coBase = chunk * CO;

    ull_t acc0[NP], acc1[NP];
#pragma unroll
    for (int j = 0; j < NP; j++) { acc0[j] = 0ull; acc1[j] = 0ull; }

    const int nB = (Cin + CBS - 1) / CBS;
    auto stage = [&](int buf, int b) {
        const int c0 = b * CBS, nc = min(CBS, Cin - c0);
        for (int i = tid; i < nc * 144; i += 256) {
            int cb = i / 144, rem = i - cb * 144, r = rem >> 3, k = rem & 7;
            int gy = oy0 - 1 + r, gx = ox0 + 4 * k;
            bool ok = (gy >= 0 && gy < H) && (gx + 3 < W);
            cp_async16(smem_u32(&s_in[buf][cb][r][4 + 4 * k]),
                       inB + ((size_t)(c0 + cb) * H + (ok ? gy : 0)) * W + (ok ? gx : 0), ok);
        }
        for (int i = tid; i < nc * 36; i += 256) {
            int cb = i / 36, rem = i - cb * 36, r = rem >> 1, e = rem & 1;
            int gy = oy0 - 1 + r, gx = e ? (ox0 + 32) : (ox0 - 1), col = e ? 36 : 3;
            bool ok = (gy >= 0 && gy < H && gx >= 0 && gx < W);
            cp_async4(smem_u32(&s_in[buf][cb][r][col]),
                      inB + ((size_t)(c0 + cb) * H + (ok ? gy : 0)) * W + (ok ? gx : 0), ok);
        }
        for (int i = tid; i < nc * 9 * CO; i += 256) {
            int cb = i / (9 * CO), rem = i - cb * (9 * CO), co = rem / 9, t = rem - co * 9;
            int cog = coBase + co; bool ok = (cog < Cout);
            cp_async4(smem_u32(&s_w[buf][cb][t][co]),
                      wgt + ((size_t)(ok ? cog : 0) * Cin + (c0 + cb)) * 9 + t, ok);
        }
        CP_COMMIT();
    };

    stage(0, 0);
    for (int b = 0; b < nB; b++) {
        CP_WAIT0();
        __syncthreads();
        if (b + 1 < nB) stage((b + 1) & 1, b + 1);
        const int buf = b & 1, nc = min(CBS, Cin - b * CBS);
        for (int cb = 0; cb < nc; cb++) {
#pragma unroll
            for (int dy = 0; dy < 3; dy++) {
                ull_t ps[4];
#pragma unroll
                for (int j = 0; j < 4; j++)
                    ps[j] = pack2s(s_in[buf][cb][ty + dy][2 * tx + j + 3]);
#pragma unroll
                for (int dx = 0; dx < 3; dx++) {
                    const int t = dy * 3 + dx;
#pragma unroll
                    for (int q2 = 0; q2 < NP / 2; q2++) {
                        ulonglong2 w = *reinterpret_cast<const ulonglong2*>(&s_w[buf][cb][t][4 * q2]);
                        ffma2(acc0[2 * q2],     ps[dx],     w.x);
                        ffma2(acc0[2 * q2 + 1], ps[dx],     w.y);
                        ffma2(acc1[2 * q2],     ps[dx + 1], w.x);
                        ffma2(acc1[2 * q2 + 1], ps[dx + 1], w.y);
                    }
                }
            }
        }
    }

    const int oy = oy0 + ty, oxb = ox0 + 2 * tx;
    if (oy >= H || oxb >= W) return;
    const size_t HWs = (size_t)H * W;

    if (ep == EP_H2) {
        uint32_t* hp = h2out + ((size_t)img * HWs + (size_t)oy * W + oxb) * 32 + chunk * 8;
        uint32_t v0[8], v1[8];
#pragma unroll
        for (int j = 0; j < NP; j++) {
            float2 u0 = unpack2(acc0[j]), u1 = unpack2(acc1[j]);
            float b0 = __ldg(bias + coBase + 2 * j);
            float b1 = __ldg(bias + coBase + 2 * j + 1);
            __half2 h0 = __floats2half2_rn(u0.x + b0, u0.y + b1);
            __half2 h1 = __floats2half2_rn(u1.x + b0, u1.y + b1);
            v0[j] = *reinterpret_cast<uint32_t*>(&h0);
            v1[j] = *reinterpret_cast<uint32_t*>(&h1);
        }
        *reinterpret_cast<uint4*>(hp)      = make_uint4(v0[0], v0[1], v0[2], v0[3]);
        *reinterpret_cast<uint4*>(hp + 4)  = make_uint4(v0[4], v0[5], v0[6], v0[7]);
        *reinterpret_cast<uint4*>(hp + 32) = make_uint4(v1[0], v1[1], v1[2], v1[3]);
        *reinterpret_cast<uint4*>(hp + 36) = make_uint4(v1[4], v1[5], v1[6], v1[7]);
        return;
    }

    float* ob = out + (size_t)img * Cout * HWs + (size_t)oy * W + oxb;
#pragma unroll
    for (int j = 0; j < NP; j++) {
        float2 u0 = unpack2(acc0[j]), u1 = unpack2(acc1[j]);
#pragma unroll
        for (int s = 0; s < 2; s++) {
            int cog = coBase + 2 * j + s;
            if (cog >= Cout) continue;
            float b = __ldg(bias + cog);
            float2 o;
            o.x = (s ? u0.y : u0.x) + b;
            o.y = (s ? u1.y : u1.x) + b;
            if (ep == EP_RELU) { o.x = fmaxf(o.x, 0.f); o.y = fmaxf(o.y, 0.f); }
            *reinterpret_cast<float2*>(ob + (size_t)cog * HWs) = o;
        }
    }
}

// ---------------------------------------------------------------------------
// Bt preps: fp16 [cout][k] images (col-major-K fragments).
// conv2: k = tap*64+cin, row stride 292. ff: k = f*576+tap*64+cin, stride 2020.
// ---------------------------------------------------------------------------
__global__ void prep_bt_kernel(const float* __restrict__ w, uint32_t* __restrict__ bt)
{
    int i = blockIdx.x * 256 + threadIdx.x;
    if (i >= 64 * 292) return;
    int cout = i / 292, j = i - cout * 292;
    uint32_t v = 0;
    if (j < 288) {
        int tap = j / 32, cin0 = 2 * (j % 32);
        __half2 h = __floats2half2_rn(w[((size_t)cout * 64 + cin0) * 9 + tap],
                                      w[((size_t)cout * 64 + cin0 + 1) * 9 + tap]);
        v = *reinterpret_cast<uint32_t*>(&h);
    }
    bt[i] = v;
}

__global__ void prep_btff_kernel(const float* __restrict__ w, uint32_t* __restrict__ bt)
{
    int i = blockIdx.x * 256 + threadIdx.x;
    if (i >= 64 * 2020) return;
    int cout = i / 2020, j = i - cout * 2020;
    uint32_t v = 0;
    if (j < 2016) {
        int f = j / 288, rem = j % 288, tap = rem / 32, cin0 = f * 64 + 2 * (rem % 32);
        __half2 h = __floats2half2_rn(w[((size_t)cout * 448 + cin0) * 9 + tap],
                                      w[((size_t)cout * 448 + cin0 + 1) * 9 + tap]);
        v = *reinterpret_cast<uint32_t*>(&h);
    }
    bt[i] = v;
}

// ---------------------------------------------------------------------------
// conv2 via mma.sync: 14 imgs, K=576. Also emits NHWC fp16 for imgs 0..6.
// ---------------------------------------------------------------------------
__global__ void __launch_bounds__(256, 1) conv2_mma_kernel(
    const uint32_t* __restrict__ h2in, const uint32_t* __restrict__ btimg,
    const float* __restrict__ bias, float* __restrict__ outF,
    uint32_t* __restrict__ f16out)
{
    extern __shared__ __align__(16) uint32_t sm[];
    const int RAW = 64 * 292;
    const int RBUF = 3 * 66 * 76;
    uint32_t sb = smem_u32(sm);
    const int tid = threadIdx.x, lane = tid & 31, w = tid >> 5;
    const int wm = w & 3, wn = w >> 2;
    const int g = lane >> 2, t = lane & 3;
    const int p0 = wm * 16;

    for (int i = tid; i < 4672; i += 256)
        cp_async16(sb + i * 16, btimg + i * 4, true);

    auto stage_raw = [&](int buf, int tile) {
        int img = tile / 576, rem = tile % 576;
        int y = rem / 3, x0 = (rem % 3) * 64;
        const uint32_t* src = h2in + (size_t)img * HW0 * 32;
        for (int i = tid; i < 1584; i += 256) {
            int pr = i >> 3, c = i & 7;
            int r = pr / 66, j = pr - r * 66;
            int gy = y - 1 + r, gx = x0 - 1 + j;
            bool ok = (gy >= 0 && gy < 192 && gx >= 0 && gx < 192);
            cp_async16(sb + (uint32_t)(RAW + buf * RBUF + (r * 66 + j) * 76 + c * 4) * 4,
                       src + ((size_t)(ok ? gy : 0) * 192 + (ok ? gx : 0)) * 32 + c * 4, ok);
        }
        CP_COMMIT();
    };

    const int tile0 = blockIdx.x * 56;
    stage_raw(0, tile0);

    for (int it = 0; it < 56; it++) {
        const int tile = tile0 + it;
        CP_WAIT0();
        __syncthreads();
        if (it + 1 < 56) stage_raw((it + 1) & 1, tile + 1);
        const uint32_t* raw = sm + RAW + (it & 1) * RBUF;
        const uint32_t* bt = sm;

        float acc[4][4];
#pragma unroll
        for (int nb = 0; nb < 4; nb++)
#pragma unroll
            for (int q = 0; q < 4; q++) acc[nb][q] = 0.f;

#pragma unroll
        for (int tap = 0; tap < 9; tap++) {
            const int dy = tap / 3, dx = tap % 3;
            const uint32_t* r0 = raw + (dy * 66 + p0 + g + dx) * 76;
            const uint32_t* r1 = r0 + 8 * 76;
#pragma unroll
            for (int s = 0; s < 4; s++) {
                uint32_t a[4];
                a[0] = r0[8 * s + t];
                a[2] = r0[8 * s + t + 4];
                a[1] = r1[8 * s + t];
                a[3] = r1[8 * s + t + 4];
#pragma unroll
                for (int nb = 0; nb < 4; nb++) {
                    const uint32_t* bp = bt + (wn * 32 + nb * 8 + g) * 292 + tap * 32 + 8 * s + t;
                    mma16816(acc[nb], a, bp[0], bp[4]);
                }
            }
        }

        const int img = tile / 576, rem = tile % 576;
        const int y = rem / 3, x0 = (rem % 3) * 64;
        const size_t pix = (size_t)y * 192 + x0 + p0 + g;
        float* ob = outF + (size_t)img * 64 * HW0 + pix;
        uint32_t* fp = (img < 7) ? f16out + ((size_t)img * HW0 + pix) * 32 : nullptr;
#pragma unroll
        for (int nb = 0; nb < 4; nb++) {
            int n0 = wn * 32 + nb * 8 + 2 * t;
            float b0 = __ldg(bias + n0), b1 = __ldg(bias + n0 + 1);
            float v00 = acc[nb][0] + b0, v01 = acc[nb][1] + b1;
            float v10 = acc[nb][2] + b0, v11 = acc[nb][3] + b1;
            ob[(size_t)n0 * HW0]           = v00;
            ob[(size_t)(n0 + 1) * HW0]     = v01;
            ob[(size_t)n0 * HW0 + 8]       = v10;
            ob[(size_t)(n0 + 1) * HW0 + 8] = v11;
            if (fp) {
                __half2 h0 = __floats2half2_rn(v00, v01);
                __half2 h1 = __floats2half2_rn(v10, v11);
                fp[n0 >> 1]           = *reinterpret_cast<uint32_t*>(&h0);
                fp[(n0 >> 1) + 8 * 32] = *reinterpret_cast<uint32_t*>(&h1);
            }
        }
    }
}

// ---------------------------------------------------------------------------
// dual fusion conv via mma.sync: out0 = 0.1*leaky(conv(alg)) + leaky(conv(feat)),
// shared weights, K=4032 (7 frames x 576). B from L2 (__ldg), A smem dbl-buf.
// 144 blocks x 256 thr, 4 row-tiles each; 28 steps = 4 tiles x 7 frames.
// Dyn smem u32: A[2 buf][2 inp][3*66*36] = 28512 u32 = 114048 B.
// ---------------------------------------------------------------------------
__global__ void __launch_bounds__(256, 1) dual_mma_kernel(
    const uint32_t* __restrict__ a16, const uint32_t* __restrict__ f16,
    const uint32_t* __restrict__ btff, const float* __restrict__ bias,
    float* __restrict__ out0)
{
    extern __shared__ __align__(16) uint32_t sm[];
    const int ABUF = 3 * 66 * 36;  // 7128
    uint32_t sb = smem_u32(sm);
    const int tid = threadIdx.x, lane = tid & 31, w = tid >> 5;
    const int wm = w & 3, wn = w >> 2;
    const int g = lane >> 2, t = lane & 3;
    const int p0 = wm * 16;

    auto stage = [&](int buf, int step) {
        int ti = step / 7, f = step % 7;
        int tile = blockIdx.x * 4 + ti;
        int y = tile / 3, x0 = (tile % 3) * 64;
        const uint32_t* sA = a16 + (size_t)f * HW0 * 32;
        const uint32_t* sF = f16 + (size_t)f * HW0 * 32;
        for (int i = tid; i < 3168; i += 256) {
            int inp = (i >= 1584) ? 1 : 0;
            int ii = i - inp * 1584;
            int pr = ii >> 3, c = ii & 7;
            int r = pr / 66, j = pr - r * 66;
            int gy = y - 1 + r, gx = x0 - 1 + j;
            bool ok = (gy >= 0 && gy < 192 && gx >= 0 && gx < 192);
            const uint32_t* s = (inp ? sF : sA) +
                ((size_t)(ok ? gy : 0) * 192 + (ok ? gx : 0)) * 32 + c * 4;
            cp_async16(sb + (uint32_t)(buf * 2 * ABUF + inp * ABUF + (r * 66 + j) * 36 + c * 4) * 4,
                       s, ok);
        }
        CP_COMMIT();
    };

    stage(0, 0);
    float accA[4][4], accF[4][4];

    for (int step = 0; step < 28; step++) {
        const int f = step % 7;
        CP_WAIT0();
        __syncthreads();
        if (step + 1 < 28) stage((step + 1) & 1, step + 1);
        const uint32_t* Aa = sm + (step & 1) * 2 * ABUF;
        const uint32_t* Af = Aa + ABUF;

        if (f == 0) {
#pragma unroll
            for (int nb = 0; nb < 4; nb++)
#pragma unroll
                for (int q = 0; q < 4; q++) { accA[nb][q] = 0.f; accF[nb][q] = 0.f; }
        }

#pragma unroll
        for (int tap = 0; tap < 9; tap++) {
            const int dy = tap / 3, dx = tap % 3;
            const int rbase = (dy * 66 + p0 + g + dx) * 36;
#pragma unroll
            for (int s = 0; s < 4; s++) {
                const int o = rbase + 8 * s + t;
                uint32_t aA[4], aF[4];
                aA[0] = Aa[o];       aA[2] = Aa[o + 4];
                aA[1] = Aa[o + 288]; aA[3] = Aa[o + 292];
                aF[0] = Af[o];       aF[2] = Af[o + 4];
                aF[1] = Af[o + 288]; aF[3] = Af[o + 292];
#pragma unroll
                for (int nb = 0; nb < 4; nb++) {
                    const uint32_t* bp = btff + (size_t)(wn * 32 + nb * 8 + g) * 2020
                                       + f * 288 + tap * 32 + 8 * s + t;
                    uint32_t b0 = __ldg(bp), b1 = __ldg(bp + 4);
                    mma16816(accA[nb], aA, b0, b1);
                    mma16816(accF[nb], aF, b0, b1);
                }
            }
        }

        if (f == 6) {
            const int tile = blockIdx.x * 4 + step / 7;
            const int y = tile / 3, x0 = (tile % 3) * 64;
            float* ob = out0 + (size_t)y * 192 + x0 + p0 + g;
#pragma unroll
            for (int nb = 0; nb < 4; nb++) {
                int n0 = wn * 32 + nb * 8 + 2 * t;
                float b0 = __ldg(bias + n0), b1 = __ldg(bias + n0 + 1);
                ob[(size_t)n0 * HW0] =
                    0.1f * lrelu(accA[nb][0] + b0) + lrelu(accF[nb][0] + b0);
                ob[(size_t)(n0 + 1) * HW0] =
                    0.1f * lrelu(accA[nb][1] + b1) + lrelu(accF[nb][1] + b1);
                ob[(size_t)n0 * HW0 + 8] =
                    0.1f * lrelu(accA[nb][2] + b0) + lrelu(accF[nb][2] + b0);
                ob[(size_t)(n0 + 1) * HW0 + 8] =
                    0.1f * lrelu(accA[nb][3] + b1) + lrelu(accF[nb][3] + b1);
            }
        }
    }
}

// ---------------------------------------------------------------------------
// 3x3 stride-2 conv, 16x16 tile, 8 cis per sync.
// ---------------------------------------------------------------------------
#define SCB 8
template <int CO>
__global__ void __launch_bounds__(256) conv3x3_s2(
    const float* __restrict__ in, const float* __restrict__ wgt,
    const float* __restrict__ bias, float* __restrict__ out,
    int Cin, int Cout, int Hin, int Win, int Hout, int Wout)
{
    __shared__ float s_in[SCB][33][33];
    __shared__ alignas(16) float s_w[SCB][9][CO];

    const int chunk = blockIdx.z;
    const int ox0 = blockIdx.x * 16, oy0 = blockIdx.y * 16;
    const int tid = threadIdx.x, tx = tid & 15, ty = tid >> 4;
    const int coBase = chunk * CO;

    float acc[CO];
#pragma unroll
    for (int i = 0; i < CO; i++) acc[i] = 0.f;

    for (int c0 = 0; c0 < Cin; c0 += SCB) {
        const int nc = min(SCB, Cin - c0);
        for (int i = tid; i < nc * 1089; i += 256) {
            int cb = i / 1089, rem = i - cb * 1089, r = rem / 33, c = rem - r * 33;
            int gy = 2 * oy0 - 1 + r, gx = 2 * ox0 - 1 + c;
            s_in[cb][r][c] = (gy >= 0 && gy < Hin && gx >= 0 && gx < Win)
                ? __ldg(in + ((size_t)(c0 + cb) * Hin + gy) * Win + gx) : 0.f;
        }
        for (int i = tid; i < nc * 9 * CO; i += 256) {
            int cb = i / (9 * CO), rem = i - cb * (9 * CO), co = rem / 9, t = rem - co * 9;
            int cog = coBase + co;
            s_w[cb][t][co] = (cog < Cout)
                ? __ldg(wgt + ((size_t)cog * Cin + (c0 + cb)) * 9 + t) : 0.f;
        }
        __syncthreads();
        for (int cb = 0; cb < nc; cb++) {
            float v[9];
#pragma unroll
            for (int t = 0; t < 9; t++) v[t] = s_in[cb][2 * ty + t / 3][2 * tx + t % 3];
#pragma unroll
            for (int t = 0; t < 9; t++) {
#pragma unroll
                for (int q = 0; q < CO / 4; q++) {
                    float4 w = *reinterpret_cast<const float4*>(&s_w[cb][t][4 * q]);
                    acc[4 * q + 0] += v[t] * w.x; acc[4 * q + 1] += v[t] * w.y;
                    acc[4 * q + 2] += v[t] * w.z; acc[4 * q + 3] += v[t] * w.w;
                }
            }
        }
        __syncthreads();
    }

    const int ox = ox0 + tx, oy = oy0 + ty;
    if (ox >= Wout || oy >= Hout) return;
    size_t pbase = (size_t)oy * Wout + ox;
#pragma unroll
    for (int co = 0; co < CO; co++) {
        int cog = coBase + co;
        if (cog >= Cout) break;
        float v = acc[co] + __ldg(bias + cog);
        out[(size_t)cog * Hout * Wout + pbase] = fmaxf(v, 0.f);
    }
}

// ---------------------------------------------------------------------------
// ConvTranspose2d k4 s2 p1, ReLU, 8 cis per sync.
// ---------------------------------------------------------------------------
template <int CO>
__global__ void __launch_bounds__(256) convT4x4_s2(
    const float* __restrict__ in, const float* __restrict__ wgt,
    const float* __restrict__ bias, float* __restrict__ out,
    int Cin, int Cout, int Hin, int Win, int Hout, int Wout)
{
    __shared__ float s_in[SCB][10][10];
    __shared__ alignas(16) float s_w[SCB][16][CO];

    const int chunk = blockIdx.z;
    const int ox0 = blockIdx.x * 16, oy0 = blockIdx.y * 16;
    const int tid = threadIdx.x, tx = tid & 15, ty = tid >> 4;
    const int coBase = chunk * CO;
    const int iy0 = oy0 / 2 - 1, ix0 = ox0 / 2 - 1;

    const int oy = oy0 + ty, ox = ox0 + tx;
    const int py = (oy + 1) & 1, px = (ox + 1) & 1;
    const int r0 = ((oy + 1 - py) >> 1) - iy0, r1 = r0 - 1;
    const int c0i = ((ox + 1 - px) >> 1) - ix0, c1i = c0i - 1;

    float acc[CO];
#pragma unroll
    for (int i = 0; i < CO; i++) acc[i] = 0.f;

    for (int c0 = 0; c0 < Cin; c0 += SCB) {
        const int nc = min(SCB, Cin - c0);
        for (int i = tid; i < nc * 100; i += 256) {
            int cb = i / 100, rem = i - cb * 100, r = rem / 10, c = rem - r * 10;
            int gy = iy0 + r, gx = ix0 + c;
            s_in[cb][r][c] = (gy >= 0 && gy < Hin && gx >= 0 && gx < Win)
                ? __ldg(in + ((size_t)(c0 + cb) * Hin + gy) * Win + gx) : 0.f;
        }
        for (int i = tid; i < nc * 16 * CO; i += 256) {
            int cb = i / (16 * CO), rem = i - cb * (16 * CO), co = rem / 16, t = rem - co * 16;
            int cog = coBase + co;
            s_w[cb][t][co] = (cog < Cout)
                ? __ldg(wgt + ((size_t)(c0 + cb) * Cout + cog) * 16 + t) : 0.f;
        }
        __syncthreads();
        for (int cb = 0; cb < nc; cb++) {
            float v00 = s_in[cb][r0][c0i], v01 = s_in[cb][r0][c1i];
            float v10 = s_in[cb][r1][c0i], v11 = s_in[cb][r1][c1i];
#pragma unroll
            for (int a = 0; a < 2; a++) {
#pragma unroll
                for (int b = 0; b < 2; b++) {
                    float v = a ? (b ? v11 : v10) : (b ? v01 : v00);
                    int t = (py + 2 * a) * 4 + (px + 2 * b);
#pragma unroll
                    for (int q = 0; q < CO / 4; q++) {
                        float4 w = *reinterpret_cast<const float4*>(&s_w[cb][t][4 * q]);
                        acc[4 * q + 0] += v * w.x; acc[4 * q + 1] += v * w.y;
                        acc[4 * q + 2] += v * w.z; acc[4 * q + 3] += v * w.w;
                    }
                }
            }
        }
        __syncthreads();
    }

    if (ox >= Wout || oy >= Hout) return;
    size_t pbase = (size_t)oy * Wout + ox;
#pragma unroll
    for (int co = 0; co < CO; co++) {
        int cog = coBase + co;
        if (cog >= Cout) break;
        float v = acc[co] + __ldg(bias + cog);
        out[(size_t)cog * Hout * Wout + pbase] = fmaxf(v, 0.f);
    }
}

// ---------------------------------------------------------------------------
// Fused flow-warp + gate -> NHWC fp16 (u32 channel pairs).
// ---------------------------------------------------------------------------
__global__ void warp_gate_kernel(const float* __restrict__ feat,
                                 const float* __restrict__ pred,
                                 const float* __restrict__ mv,
                                 uint32_t* __restrict__ a16)
{
    const int pix = blockIdx.x * 256 + threadIdx.x;
    if (pix >= HW0) return;
    const int t = blockIdx.y;

    float wgt[4]; int off[4]; bool val[4];
    const float* fb = nullptr;
    if (t > 0) {
        const int y = pix / W0, x = pix - y * W0;
        const float fx = mv[(size_t)(t - 1) * HW0 * 2 + (size_t)pix * 2 + 0];
        const float fy = mv[(size_t)(t - 1) * HW0 * 2 + (size_t)pix * 2 + 1];
        const float ys = (float)y + fy, xs = (float)x + fx;
        const float y0 = floorf(ys), x0 = floorf(xs);
        const float wy = ys - y0, wx = xs - x0;
#pragma unroll
        for (int i = 0; i < 4; i++) {
            int dy = i >> 1, dx = i & 1;
            float yi = y0 + dy, xi = x0 + dx;
            val[i] = (yi >= 0.f) && (yi <= (float)(H0 - 1)) &&
                     (xi >= 0.f) && (xi <= (float)(W0 - 1));
            wgt[i] = (dy ? wy : 1.f - wy) * (dx ? wx : 1.f - wx);
            off[i] = val[i] ? ((int)yi * W0 + (int)xi) : 0;
        }
        fb = feat + (size_t)(t - 1) * 64 * HW0;
    }

    const float* refb = feat + (size_t)3 * 64 * HW0 + pix;
    const float* prb  = pred + (size_t)t * 64 * HW0 + pix;
    const float* f0b  = feat + pix;
    uint32_t* ob = a16 + ((size_t)t * HW0 + pix) * 32;

    for (int c2 = 0; c2 < 32; c2++) {
        float o01[2];
#pragma unroll
        for (int s = 0; s < 2; s++) {
            const int c = 2 * c2 + s;
            float a;
            if (t == 0) {
                a = __ldg(f0b + (size_t)c * HW0);
            } else {
                const float* img = fb + (size_t)c * HW0;
                a = 0.f;
#pragma unroll
                for (int i = 0; i < 4; i++)
                    if (val[i]) a += __ldg(img + off[i]) * wgt[i];
            }
            float ref = __ldg(refb + (size_t)c * HW0);
            float p   = __ldg(prb + (size_t)c * HW0);
            o01[s] = a * fsigmoid(a * ref) + p * fsigmoid(p * ref);
        }
        __half2 h = __floats2half2_rn(o01[0], o01[1]);
        ob[c2] = *reinterpret_cast<uint32_t*>(&h);
    }
}

// ---------------------------------------------------------------------------
// Modulated deformable conv.
// ---------------------------------------------------------------------------
__global__ void __launch_bounds__(128) deform_kernel(
    const float* __restrict__ lqs, const float* __restrict__ offm,
    const float* __restrict__ dcw, const float* __restrict__ dcb,
    float* __restrict__ out)
{
    __shared__ alignas(16) float s_w[63 * 64];
    __shared__ float s_b[64];
    const int tid = threadIdx.x;
    for (int i = tid; i < 63 * 64; i += 128) {
        int o = i / 63, j = i - o * 63;
        s_w[j * 64 + o] = dcw[i];
    }
    if (tid < 64) s_b[tid] = dcb[tid];
    __syncthreads();

    const int pix = blockIdx.x * 128 + tid;
    if (pix >= HW0) return;
    const int y = pix / W0, x = pix - y * W0;

    ull_t acc[32];
#pragma unroll
    for (int q = 0; q < 32; q++) acc[q] = pack2(s_b[2 * q], s_b[2 * q + 1]);

    for (int g = 0; g < 7; g++) {
        const float* img = lqs + (size_t)g * HW0;
#pragma unroll
        for (int k = 0; k < 9; k++) {
            const int j = g * 9 + k;
            float offy = __ldg(offm + (size_t)(g * 18 + 2 * k + 0) * HW0 + pix);
            float offx = __ldg(offm + (size_t)(g * 18 + 2 * k + 1) * HW0 + pix);
            float mraw = __ldg(offm + (size_t)(126 + j) * HW0 + pix);
            float m = fsigmoid(mraw);
            float ys = (float)(y + k / 3 - 1) + offy;
            float xs = (float)(x + k % 3 - 1) + offx;
            float y0 = floorf(ys), x0 = floorf(xs);
            float wy = ys - y0, wx = xs - x0;
            float samp = 0.f;
#pragma unroll
            for (int ii = 0; ii < 4; ii++) {
                int dy = ii >> 1, dx = ii & 1;
                float yi = y0 + dy, xi = x0 + dx;
                if (yi >= 0.f && yi <= (float)(H0 - 1) &&
                    xi >= 0.f && xi <= (float)(W0 - 1))
                    samp += __ldg(img + (int)yi * W0 + (int)xi) *
                            ((dy ? wy : 1.f - wy) * (dx ? wx : 1.f - wx));
            }
            ull_t mod2 = pack2s(samp * m);
#pragma unroll
            for (int q2 = 0; q2 < 16; q2++) {
                ulonglong2 w = *reinterpret_cast<const ulonglong2*>(&s_w[j * 64 + 4 * q2]);
                ffma2(acc[2 * q2],     mod2, w.x);
                ffma2(acc[2 * q2 + 1], mod2, w.y);
            }
        }
    }
#pragma unroll
    for (int q = 0; q < 32; q++) {
        float2 u = unpack2(acc[q]);
        out[(size_t)(2 * q) * HW0 + pix]     = fmaxf(u.x, 0.f);
        out[(size_t)(2 * q + 1) * HW0 + pix] = fmaxf(u.y, 0.f);
    }
}

// ---------------------------------------------------------------------------
// Host orchestration (graph-capturable)
// ---------------------------------------------------------------------------
extern "C" void kernel_launch(void* const* d_in, const int* in_sizes, int n_in,
                              void* d_out, int out_size)
{
    const float* lqs    = (const float*)d_in[0];
    const float* preds  = (const float*)d_in[1];
    const float* mv     = (const float*)d_in[2];
    const float* bw1    = (const float*)d_in[3];
    const float* bb1    = (const float*)d_in[4];
    const float* bw2    = (const float*)d_in[5];
    const float* bb2    = (const float*)d_in[6];
    const float* dn1_w  = (const float*)d_in[7];
    const float* dn1_b  = (const float*)d_in[8];
    const float* dn2_w  = (const float*)d_in[9];
    const float* dn2_b  = (const float*)d_in[10];
    const float* up1_cw = (const float*)d_in[11];
    const float* up1_cb = (const float*)d_in[12];
    const float* up1_tw = (const float*)d_in[13];
    const float* up1_tb = (const float*)d_in[14];
    const float* up2_cw = (const float*)d_in[15];
    const float* up2_cb = (const float*)d_in[16];
    const float* up2_tw = (const float*)d_in[17];
    const float* up2_tb = (const float*)d_in[18];
    const float* tr_cw  = (const float*)d_in[19];
    const float* tr_cb  = (const float*)d_in[20];
    const float* tr_tw  = (const float*)d_in[21];
    const float* tr_tb  = (const float*)d_in[22];
    const float* ff_w   = (const float*)d_in[23];
    const float* ff_b   = (const float*)d_in[24];
    const float* om_w   = (const float*)d_in[25];
    const float* om_b   = (const float*)d_in[26];
    const float* dc_w   = (const float*)d_in[27];
    const float* dc_b   = (const float*)d_in[28];
    float* outp = (float*)d_out;

    float* S = nullptr;
    cudaGetSymbolAddress((void**)&S, g_scratch);
    float* feat  = S + OFF_FEAT;
    float* pred  = S + OFF_PRED;
    uint32_t* a16 = (uint32_t*)(S + OFF_ALG);                    // 7*HW0*32 u32
    uint32_t* f16 = (uint32_t*)(S + OFF_ALG) + (size_t)7 * HW0 * 32;
    uint32_t* h2buf = (uint32_t*)(S + OFF_H2);
    uint32_t* btimg = (uint32_t*)(S + OFF_WB);
    uint32_t* btff  = (uint32_t*)(S + OFF_WBF);
    float* out0  = S + OFF_OUT0;
    float* out1  = S + OFF_OUT1;
    float* out2  = S + OFF_OUT2;
    float* u24   = S + OFF_U24;
    float* cat48 = S + OFF_CAT48;
    float* c48   = S + OFF_C48;
    float* cat96 = S + OFF_CAT96;
    float* c96   = S + OFF_C96;
    float* featf = S + OFF_FEATF;
    float* offm  = S + OFF_OFFM;

    cudaFuncSetAttribute(conv2_mma_kernel,
                         cudaFuncAttributeMaxDynamicSharedMemorySize, 195136);
    cudaFuncSetAttribute(dual_mma_kernel,
                         cudaFuncAttributeMaxDynamicSharedMemorySize, 114048);

    dim3 blk(256);

    // conv1 (1->64) -> NHWC fp16: lqs imgs 0..6, preds imgs 7..13
    conv3x3_s1<8><<<dim3(6, 12, 7 * 4), blk>>>(lqs,   bw1, bb1, nullptr, h2buf,
                                               1, 64, 192, 192, 4, EP_H2);
    conv3x3_s1<8><<<dim3(6, 12, 7 * 4), blk>>>(preds, bw1, bb1, nullptr,
                                               h2buf + (size_t)7 * HW0 * 32,
                                               1, 64, 192, 192, 4, EP_H2);
    // conv2 via mma (planar fp32 [feat|pred] + NHWC fp16 feat for imgs 0..6)
    prep_bt_kernel<<<73, blk>>>(bw2, btimg);
    prep_btff_kernel<<<505, blk>>>(ff_w, btff);
    conv2_mma_kernel<<<144, blk, 195136>>>(h2buf, btimg, bb2, feat, f16);

    // gated aligned features -> NHWC fp16
    warp_gate_kernel<<<dim3(HW0 / 256, 7), blk>>>(feat, pred, mv, a16);

    // fusion pair via mma (shared weights, both inputs in one pass)
    dual_mma_kernel<<<144, blk, 114048>>>(a16, f16, btff, ff_b, out0);

    // down path
    conv3x3_s2<8><<<dim3(6, 6, 8), blk>>>(out0, dn1_w, dn1_b, out1, 64, 64, 192, 192, 96, 96);
    conv3x3_s2<8><<<dim3(3, 3, 8), blk>>>(out1, dn2_w, dn2_b, out2, 64, 64, 96, 96, 48, 48);
    conv3x3_s2<8><<<dim3(2, 2, 8), blk>>>(out2, tr_cw, tr_cb, u24, 64, 64, 48, 48, 24, 24);

    // up path with skip concats
    convT4x4_s2<16><<<dim3(3, 3, 4), blk>>>(u24, tr_tw, tr_tb, cat48, 64, 64, 24, 24, 48, 48);
    cudaMemcpyAsync(cat48 + (size_t)64 * 48 * 48, out2,
                    (size_t)64 * 48 * 48 * sizeof(float), cudaMemcpyDeviceToDevice, 0);
    conv3x3_s1<8><<<dim3(2, 3, 4), blk>>>(cat48, up2_cw, up2_cb, c48, nullptr,
                                          128, 64, 48, 48, 4, EP_RELU);
    convT4x4_s2<16><<<dim3(6, 6, 4), blk>>>(c48, up2_tw, up2_tb, cat96, 64, 64, 48, 48, 96, 96);
    cudaMemcpyAsync(cat96 + (size_t)64 * 96 * 96, out1,
                    (size_t)64 * 96 * 96 * sizeof(float), cudaMemcpyDeviceToDevice, 0);
    conv3x3_s1<8><<<dim3(3, 6, 4), blk>>>(cat96, up1_cw, up1_cb, c96, nullptr,
                                          128, 64, 96, 96, 4, EP_RELU);
    convT4x4_s2<16><<<dim3(12, 12, 4), blk>>>(c96, up1_tw, up1_tb, featf, 64, 64, 96, 96, 192, 192);

    // offsets + masks
    conv3x3_s1<8><<<dim3(6, 12, 12), blk>>>(featf, om_w, om_b, offm, nullptr,
                                            64, 189, 192, 192, 12, EP_NONE);

    // modulated deformable conv -> output
    deform_kernel<<<HW0 / 128, dim3(128)>>>(lqs, offm, dc_w, dc_b, outp);
}

// round 17
// speedup vs baseline: 3.2920x; 1.1196x over previous
#include <cuda_runtime.h>
#include <cuda_fp16.h>
#include <math.h>
#include <stdint.h>

#define NF 64
#define TT 7
#define H0 192
#define W0 192
#define HW0 (H0 * W0)

#define BIGSZ (7 * 64 * HW0)
#define OFF_FEAT   0
#define OFF_PRED   (OFF_FEAT + BIGSZ)
#define OFF_ALG    (OFF_PRED + BIGSZ)           // a16 (7*HW0*32 u32) + f16 (same)
#define OFF_H2     (OFF_ALG + BIGSZ)            // conv1 NHWC fp16, 14 imgs
#define OFF_OUT0   (OFF_H2 + BIGSZ)
#define OFF_OUT1   (OFF_OUT0 + 64 * HW0)
#define OFF_OUT2   (OFF_OUT1 + 64 * 96 * 96)
#define OFF_U24    (OFF_OUT2 + 64 * 48 * 48)
#define OFF_CAT48  (OFF_U24 + 64 * 24 * 24)
#define OFF_C48    (OFF_CAT48 + 128 * 48 * 48)
#define OFF_CAT96  (OFF_C48 + 64 * 48 * 48)
#define OFF_C96    (OFF_CAT96 + 128 * 96 * 96)
#define OFF_FEATF  (OFF_C96 + 64 * 96 * 96)     // NHWC fp16 featf (32 u32/px)
#define OFF_OFFM   (OFF_FEATF + 64 * HW0)
#define OFF_WB     (OFF_OFFM + 189 * HW0)       // conv2 Bt: 64*292 u32
#define OFF_WBF    (OFF_WB + 64 * 292)          // ff Bt: 64*2020 u32
#define OFF_WBOM   (OFF_WBF + 64 * 2020)        // om Bt: 192*292 u32
#define SCRATCH_TOTAL (OFF_WBOM + 192 * 292)

__device__ float g_scratch[SCRATCH_TOTAL];

enum { EP_NONE = 0, EP_RELU = 1, EP_H2 = 2 };

typedef unsigned long long ull_t;
__device__ __forceinline__ ull_t pack2s(float v) {
    ull_t r; asm("mov.b64 %0, {%1, %1};" : "=l"(r) : "f"(v)); return r;
}
__device__ __forceinline__ ull_t pack2(float lo, float hi) {
    ull_t r; asm("mov.b64 %0, {%1, %2};" : "=l"(r) : "f"(lo), "f"(hi)); return r;
}
__device__ __forceinline__ void ffma2(ull_t& d, ull_t a, ull_t b) {
    asm("fma.rn.f32x2 %0, %1, %2, %0;" : "+l"(d) : "l"(a), "l"(b));
}
__device__ __forceinline__ float2 unpack2(ull_t v) {
    float lo, hi; asm("mov.b64 {%0, %1}, %2;" : "=f"(lo), "=f"(hi) : "l"(v));
    return make_float2(lo, hi);
}
__device__ __forceinline__ float fsigmoid(float x) { return 1.f / (1.f + __expf(-x)); }
__device__ __forceinline__ float lrelu(float x) { return x > 0.f ? x : 0.1f * x; }

__device__ __forceinline__ uint32_t smem_u32(const void* p) {
    return (uint32_t)__cvta_generic_to_shared(p);
}
__device__ __forceinline__ void cp_async4(uint32_t s, const float* g, bool ok) {
    asm volatile("cp.async.ca.shared.global [%0], [%1], 4, %2;"
                 :: "r"(s), "l"(g), "r"(ok ? 4u : 0u));
}
__device__ __forceinline__ void cp_async16(uint32_t s, const void* g, bool ok) {
    asm volatile("cp.async.cg.shared.global [%0], [%1], 16, %2;"
                 :: "r"(s), "l"(g), "r"(ok ? 16u : 0u));
}
#define CP_COMMIT() asm volatile("cp.async.commit_group;")
#define CP_WAIT0()  asm volatile("cp.async.wait_group 0;")

__device__ __forceinline__ void mma16816(float* d, const uint32_t* a,
                                         uint32_t b0, uint32_t b1) {
    asm volatile("mma.sync.aligned.m16n8k16.row.col.f32.f16.f16.f32 "
        "{%0,%1,%2,%3}, {%4,%5,%6,%7}, {%8,%9}, {%0,%1,%2,%3};"
        : "+f"(d[0]), "+f"(d[1]), "+f"(d[2]), "+f"(d[3])
        : "r"(a[0]), "r"(a[1]), "r"(a[2]), "r"(a[3]), "r"(b0), "r"(b1));
}

// ---------------------------------------------------------------------------
// 3x3 s1 conv, FFMA2, cp.async double-buffered. EP_H2: NHWC fp16 output.
// ---------------------------------------------------------------------------
#define CBS 8
#define SMC 40
template <int NP>
__global__ void __launch_bounds__(256, 3) conv3x3_s1(
    const float* __restrict__ in, const float* __restrict__ wgt,
    const float* __restrict__ bias, float* __restrict__ out,
    uint32_t* __restrict__ h2out,
    int Cin, int Cout, int H, int W, int nChunks, int ep)
{
    const int CO = 2 * NP;
    __shared__ alignas(16) float s_in[2][CBS][18][SMC];
    __shared__ alignas(16) float s_w[2][CBS][9][2 * NP];

    const int img = blockIdx.z / nChunks, chunk = blockIdx.z % nChunks;
    const int ox0 = blockIdx.x * 32, oy0 = blockIdx.y * 16;
    const int tid = threadIdx.x, tx = tid & 15, ty = tid >> 4;
    const float* inB = in + (size_t)img * Cin * H * W;
    const int coBase = chunk * CO;

    ull_t acc0[NP], acc1[NP];
#pragma unroll
    for (int j = 0; j < NP; j++) { acc0[j] = 0ull; acc1[j] = 0ull; }

    const int nB = (Cin + CBS - 1) / CBS;
    auto stage = [&](int buf, int b) {
        const int c0 = b * CBS, nc = min(CBS, Cin - c0);
        for (int i = tid; i < nc * 144; i += 256) {
            int cb = i / 144, rem = i - cb * 144, r = rem >> 3, k = rem & 7;
            int gy = oy0 - 1 + r, gx = ox0 + 4 * k;
            bool ok = (gy >= 0 && gy < H) && (gx + 3 < W);
            cp_async16(smem_u32(&s_in[buf][cb][r][4 + 4 * k]),
                       inB + ((size_t)(c0 + cb) * H + (ok ? gy : 0)) * W + (ok ? gx : 0), ok);
        }
        for (int i = tid; i < nc * 36; i += 256) {
            int cb = i / 36, rem = i - cb * 36, r = rem >> 1, e = rem & 1;
            int gy = oy0 - 1 + r, gx = e ? (ox0 + 32) : (ox0 - 1), col = e ? 36 : 3;
            bool ok = (gy >= 0 && gy < H && gx >= 0 && gx < W);
            cp_async4(smem_u32(&s_in[buf][cb][r][col]),
                      inB + ((size_t)(c0 + cb) * H + (ok ? gy : 0)) * W + (ok ? gx : 0), ok);
        }
        for (int i = tid; i < nc * 9 * CO; i += 256) {
            int cb = i / (9 * CO), rem = i - cb * (9 * CO), co = rem / 9, t = rem - co * 9;
            int cog = coBase + co; bool ok = (cog < Cout);
            cp_async4(smem_u32(&s_w[buf][cb][t][co]),
                      wgt + ((size_t)(ok ? cog : 0) * Cin + (c0 + cb)) * 9 + t, ok);
        }
        CP_COMMIT();
    };

    stage(0, 0);
    for (int b = 0; b < nB; b++) {
        CP_WAIT0();
        __syncthreads();
        if (b + 1 < nB) stage((b + 1) & 1, b + 1);
        const int buf = b & 1, nc = min(CBS, Cin - b * CBS);
        for (int cb = 0; cb < nc; cb++) {
#pragma unroll
            for (int dy = 0; dy < 3; dy++) {
                ull_t ps[4];
#pragma unroll
                for (int j = 0; j < 4; j++)
                    ps[j] = pack2s(s_in[buf][cb][ty + dy][2 * tx + j + 3]);
#pragma unroll
                for (int dx = 0; dx < 3; dx++) {
                    const int t = dy * 3 + dx;
#pragma unroll
                    for (int q2 = 0; q2 < NP / 2; q2++) {
                        ulonglong2 w = *reinterpret_cast<const ulonglong2*>(&s_w[buf][cb][t][4 * q2]);
                        ffma2(acc0[2 * q2],     ps[dx],     w.x);
                        ffma2(acc0[2 * q2 + 1], ps[dx],     w.y);
                        ffma2(acc1[2 * q2],     ps[dx + 1], w.x);
                        ffma2(acc1[2 * q2 + 1], ps[dx + 1], w.y);
                    }
                }
            }
        }
    }

    const int oy = oy0 + ty, oxb = ox0 + 2 * tx;
    if (oy >= H || oxb >= W) return;
    const size_t HWs = (size_t)H * W;

    if (ep == EP_H2) {
        uint32_t* hp = h2out + ((size_t)img * HWs + (size_t)oy * W + oxb) * 32 + chunk * 8;
        uint32_t v0[8], v1[8];
#pragma unroll
        for (int j = 0; j < NP; j++) {
            float2 u0 = unpack2(acc0[j]), u1 = unpack2(acc1[j]);
            float b0 = __ldg(bias + coBase + 2 * j);
            float b1 = __ldg(bias + coBase + 2 * j + 1);
            __half2 h0 = __floats2half2_rn(u0.x + b0, u0.y + b1);
            __half2 h1 = __floats2half2_rn(u1.x + b0, u1.y + b1);
            v0[j] = *reinterpret_cast<uint32_t*>(&h0);
            v1[j] = *reinterpret_cast<uint32_t*>(&h1);
        }
        *reinterpret_cast<uint4*>(hp)      = make_uint4(v0[0], v0[1], v0[2], v0[3]);
        *reinterpret_cast<uint4*>(hp + 4)  = make_uint4(v0[4], v0[5], v0[6], v0[7]);
        *reinterpret_cast<uint4*>(hp + 32) = make_uint4(v1[0], v1[1], v1[2], v1[3]);
        *reinterpret_cast<uint4*>(hp + 36) = make_uint4(v1[4], v1[5], v1[6], v1[7]);
        return;
    }

    float* ob = out + (size_t)img * Cout * HWs + (size_t)oy * W + oxb;
#pragma unroll
    for (int j = 0; j < NP; j++) {
        float2 u0 = unpack2(acc0[j]), u1 = unpack2(acc1[j]);
#pragma unroll
        for (int s = 0; s < 2; s++) {
            int cog = coBase + 2 * j + s;
            if (cog >= Cout) continue;
            float b = __ldg(bias + cog);
            float2 o;
            o.x = (s ? u0.y : u0.x) + b;
            o.y = (s ? u1.y : u1.x) + b;
            if (ep == EP_RELU) { o.x = fmaxf(o.x, 0.f); o.y = fmaxf(o.y, 0.f); }
            *reinterpret_cast<float2*>(ob + (size_t)cog * HWs) = o;
        }
    }
}

// ---------------------------------------------------------------------------
// Bt preps: fp16 [cout][k] images.
// ---------------------------------------------------------------------------
__global__ void prep_bt_kernel(const float* __restrict__ w, uint32_t* __restrict__ bt)
{
    int i = blockIdx.x * 256 + threadIdx.x;
    if (i >= 64 * 292) return;
    int cout = i / 292, j = i - cout * 292;
    uint32_t v = 0;
    if (j < 288) {
        int tap = j / 32, cin0 = 2 * (j % 32);
        __half2 h = __floats2half2_rn(w[((size_t)cout * 64 + cin0) * 9 + tap],
                                      w[((size_t)cout * 64 + cin0 + 1) * 9 + tap]);
        v = *reinterpret_cast<uint32_t*>(&h);
    }
    bt[i] = v;
}

__global__ void prep_btff_kernel(const float* __restrict__ w, uint32_t* __restrict__ bt)
{
    int i = blockIdx.x * 256 + threadIdx.x;
    if (i >= 64 * 2020) return;
    int cout = i / 2020, j = i - cout * 2020;
    uint32_t v = 0;
    if (j < 2016) {
        int f = j / 288, rem = j % 288, tap = rem / 32, cin0 = f * 64 + 2 * (rem % 32);
        __half2 h = __floats2half2_rn(w[((size_t)cout * 448 + cin0) * 9 + tap],
                                      w[((size_t)cout * 448 + cin0 + 1) * 9 + tap]);
        v = *reinterpret_cast<uint32_t*>(&h);
    }
    bt[i] = v;
}

__global__ void prep_btom_kernel(const float* __restrict__ w, uint32_t* __restrict__ bt)
{
    int i = blockIdx.x * 256 + threadIdx.x;
    if (i >= 192 * 292) return;
    int cout = i / 292, j = i - cout * 292;
    uint32_t v = 0;
    if (j < 288 && cout < 189) {
        int tap = j / 32, cin0 = 2 * (j % 32);
        __half2 h = __floats2half2_rn(w[((size_t)cout * 64 + cin0) * 9 + tap],
                                      w[((size_t)cout * 64 + cin0 + 1) * 9 + tap]);
        v = *reinterpret_cast<uint32_t*>(&h);
    }
    bt[i] = v;
}

// ---------------------------------------------------------------------------
// conv2 via mma.sync: 14 imgs, K=576. Also emits NHWC fp16 for imgs 0..6.
// ---------------------------------------------------------------------------
__global__ void __launch_bounds__(256, 1) conv2_mma_kernel(
    const uint32_t* __restrict__ h2in, const uint32_t* __restrict__ btimg,
    const float* __restrict__ bias, float* __restrict__ outF,
    uint32_t* __restrict__ f16out)
{
    extern __shared__ __align__(16) uint32_t sm[];
    const int RAW = 64 * 292;
    const int RBUF = 3 * 66 * 76;
    uint32_t sb = smem_u32(sm);
    const int tid = threadIdx.x, lane = tid & 31, w = tid >> 5;
    const int wm = w & 3, wn = w >> 2;
    const int g = lane >> 2, t = lane & 3;
    const int p0 = wm * 16;

    for (int i = tid; i < 4672; i += 256)
        cp_async16(sb + i * 16, btimg + i * 4, true);

    auto stage_raw = [&](int buf, int tile) {
        int img = tile / 576, rem = tile % 576;
        int y = rem / 3, x0 = (rem % 3) * 64;
        const uint32_t* src = h2in + (size_t)img * HW0 * 32;
        for (int i = tid; i < 1584; i += 256) {
            int pr = i >> 3, c = i & 7;
            int r = pr / 66, j = pr - r * 66;
            int gy = y - 1 + r, gx = x0 - 1 + j;
            bool ok = (gy >= 0 && gy < 192 && gx >= 0 && gx < 192);
            cp_async16(sb + (uint32_t)(RAW + buf * RBUF + (r * 66 + j) * 76 + c * 4) * 4,
                       src + ((size_t)(ok ? gy : 0) * 192 + (ok ? gx : 0)) * 32 + c * 4, ok);
        }
        CP_COMMIT();
    };

    const int tile0 = blockIdx.x * 56;
    stage_raw(0, tile0);

    for (int it = 0; it < 56; it++) {
        const int tile = tile0 + it;
        CP_WAIT0();
        __syncthreads();
        if (it + 1 < 56) stage_raw((it + 1) & 1, tile + 1);
        const uint32_t* raw = sm + RAW + (it & 1) * RBUF;
        const uint32_t* bt = sm;

        float acc[4][4];
#pragma unroll
        for (int nb = 0; nb < 4; nb++)
#pragma unroll
            for (int q = 0; q < 4; q++) acc[nb][q] = 0.f;

#pragma unroll
        for (int tap = 0; tap < 9; tap++) {
            const int dy = tap / 3, dx = tap % 3;
            const uint32_t* r0 = raw + (dy * 66 + p0 + g + dx) * 76;
            const uint32_t* r1 = r0 + 8 * 76;
#pragma unroll
            for (int s = 0; s < 4; s++) {
                uint32_t a[4];
                a[0] = r0[8 * s + t];
                a[2] = r0[8 * s + t + 4];
                a[1] = r1[8 * s + t];
                a[3] = r1[8 * s + t + 4];
#pragma unroll
                for (int nb = 0; nb < 4; nb++) {
                    const uint32_t* bp = bt + (wn * 32 + nb * 8 + g) * 292 + tap * 32 + 8 * s + t;
                    mma16816(acc[nb], a, bp[0], bp[4]);
                }
            }
        }

        const int img = tile / 576, rem = tile % 576;
        const int y = rem / 3, x0 = (rem % 3) * 64;
        const size_t pix = (size_t)y * 192 + x0 + p0 + g;
        float* ob = outF + (size_t)img * 64 * HW0 + pix;
        uint32_t* fp = (img < 7) ? f16out + ((size_t)img * HW0 + pix) * 32 : nullptr;
#pragma unroll
        for (int nb = 0; nb < 4; nb++) {
            int n0 = wn * 32 + nb * 8 + 2 * t;
            float b0 = __ldg(bias + n0), b1 = __ldg(bias + n0 + 1);
            float v00 = acc[nb][0] + b0, v01 = acc[nb][1] + b1;
            float v10 = acc[nb][2] + b0, v11 = acc[nb][3] + b1;
            ob[(size_t)n0 * HW0]           = v00;
            ob[(size_t)(n0 + 1) * HW0]     = v01;
            ob[(size_t)n0 * HW0 + 8]       = v10;
            ob[(size_t)(n0 + 1) * HW0 + 8] = v11;
            if (fp) {
                __half2 h0 = __floats2half2_rn(v00, v01);
                __half2 h1 = __floats2half2_rn(v10, v11);
                fp[n0 >> 1]           = *reinterpret_cast<uint32_t*>(&h0);
                fp[(n0 >> 1) + 8 * 32] = *reinterpret_cast<uint32_t*>(&h1);
            }
        }
    }
}

// ---------------------------------------------------------------------------
// dual fusion conv via mma.sync (shared weights, two inputs).
// ---------------------------------------------------------------------------
__global__ void __launch_bounds__(256, 1) dual_mma_kernel(
    const uint32_t* __restrict__ a16, const uint32_t* __restrict__ f16,
    const uint32_t* __restrict__ btff, const float* __restrict__ bias,
    float* __restrict__ out0)
{
    extern __shared__ __align__(16) uint32_t sm[];
    const int ABUF = 3 * 66 * 36;
    uint32_t sb = smem_u32(sm);
    const int tid = threadIdx.x, lane = tid & 31, w = tid >> 5;
    const int wm = w & 3, wn = w >> 2;
    const int g = lane >> 2, t = lane & 3;
    const int p0 = wm * 16;

    auto stage = [&](int buf, int step) {
        int ti = step / 7, f = step % 7;
        int tile = blockIdx.x * 4 + ti;
        int y = tile / 3, x0 = (tile % 3) * 64;
        const uint32_t* sA = a16 + (size_t)f * HW0 * 32;
        const uint32_t* sF = f16 + (size_t)f * HW0 * 32;
        for (int i = tid; i < 3168; i += 256) {
            int inp = (i >= 1584) ? 1 : 0;
            int ii = i - inp * 1584;
            int pr = ii >> 3, c = ii & 7;
            int r = pr / 66, j = pr - r * 66;
            int gy = y - 1 + r, gx = x0 - 1 + j;
            bool ok = (gy >= 0 && gy < 192 && gx >= 0 && gx < 192);
            const uint32_t* s = (inp ? sF : sA) +
                ((size_t)(ok ? gy : 0) * 192 + (ok ? gx : 0)) * 32 + c * 4;
            cp_async16(sb + (uint32_t)(buf * 2 * ABUF + inp * ABUF + (r * 66 + j) * 36 + c * 4) * 4,
                       s, ok);
        }
        CP_COMMIT();
    };

    stage(0, 0);
    float accA[4][4], accF[4][4];

    for (int step = 0; step < 28; step++) {
        const int f = step % 7;
        CP_WAIT0();
        __syncthreads();
        if (step + 1 < 28) stage((step + 1) & 1, step + 1);
        const uint32_t* Aa = sm + (step & 1) * 2 * ABUF;
        const uint32_t* Af = Aa + ABUF;

        if (f == 0) {
#pragma unroll
            for (int nb = 0; nb < 4; nb++)
#pragma unroll
                for (int q = 0; q < 4; q++) { accA[nb][q] = 0.f; accF[nb][q] = 0.f; }
        }

#pragma unroll
        for (int tap = 0; tap < 9; tap++) {
            const int dy = tap / 3, dx = tap % 3;
            const int rbase = (dy * 66 + p0 + g + dx) * 36;
#pragma unroll
            for (int s = 0; s < 4; s++) {
                const int o = rbase + 8 * s + t;
                uint32_t aA[4], aF[4];
                aA[0] = Aa[o];       aA[2] = Aa[o + 4];
                aA[1] = Aa[o + 288]; aA[3] = Aa[o + 292];
                aF[0] = Af[o];       aF[2] = Af[o + 4];
                aF[1] = Af[o + 288]; aF[3] = Af[o + 292];
#pragma unroll
                for (int nb = 0; nb < 4; nb++) {
                    const uint32_t* bp = btff + (size_t)(wn * 32 + nb * 8 + g) * 2020
                                       + f * 288 + tap * 32 + 8 * s + t;
                    uint32_t b0 = __ldg(bp), b1 = __ldg(bp + 4);
                    mma16816(accA[nb], aA, b0, b1);
                    mma16816(accF[nb], aF, b0, b1);
                }
            }
        }

        if (f == 6) {
            const int tile = blockIdx.x * 4 + step / 7;
            const int y = tile / 3, x0 = (tile % 3) * 64;
            float* ob = out0 + (size_t)y * 192 + x0 + p0 + g;
#pragma unroll
            for (int nb = 0; nb < 4; nb++) {
                int n0 = wn * 32 + nb * 8 + 2 * t;
                float b0 = __ldg(bias + n0), b1 = __ldg(bias + n0 + 1);
                ob[(size_t)n0 * HW0] =
                    0.1f * lrelu(accA[nb][0] + b0) + lrelu(accF[nb][0] + b0);
                ob[(size_t)(n0 + 1) * HW0] =
                    0.1f * lrelu(accA[nb][1] + b1) + lrelu(accF[nb][1] + b1);
                ob[(size_t)n0 * HW0 + 8] =
                    0.1f * lrelu(accA[nb][2] + b0) + lrelu(accF[nb][2] + b0);
                ob[(size_t)(n0 + 1) * HW0 + 8] =
                    0.1f * lrelu(accA[nb][3] + b1) + lrelu(accF[nb][3] + b1);
            }
        }
    }
}

// ---------------------------------------------------------------------------
// om conv via mma.sync: featf16 (NHWC fp16) -> offm[189][HW0] fp32.
// N=192 (189 padded), K=576. B via __ldg (L2), A smem double-buffered.
// 144 blocks x 256 thr, 4 row-tiles each.
// ---------------------------------------------------------------------------
__global__ void __launch_bounds__(256, 1) om_mma_kernel(
    const uint32_t* __restrict__ x16, const uint32_t* __restrict__ btom,
    const float* __restrict__ bias, float* __restrict__ offm)
{
    extern __shared__ __align__(16) uint32_t sm[];
    const int ABUF = 3 * 66 * 36;
    uint32_t sb = smem_u32(sm);
    const int tid = threadIdx.x, lane = tid & 31, w = tid >> 5;
    const int wm = w & 3, wn = w >> 2;
    const int g = lane >> 2, t = lane & 3;
    const int p0 = wm * 16;

    auto stage = [&](int buf, int tile) {
        int y = tile / 3, x0 = (tile % 3) * 64;
        for (int i = tid; i < 1584; i += 256) {
            int pr = i >> 3, c = i & 7;
            int r = pr / 66, j = pr - r * 66;
            int gy = y - 1 + r, gx = x0 - 1 + j;
            bool ok = (gy >= 0 && gy < 192 && gx >= 0 && gx < 192);
            cp_async16(sb + (uint32_t)(buf * ABUF + (r * 66 + j) * 36 + c * 4) * 4,
                       x16 + ((size_t)(ok ? gy : 0) * 192 + (ok ? gx : 0)) * 32 + c * 4, ok);
        }
        CP_COMMIT();
    };

    stage(0, blockIdx.x * 4);

    for (int it = 0; it < 4; it++) {
        const int tile = blockIdx.x * 4 + it;
        CP_WAIT0();
        __syncthreads();
        if (it + 1 < 4) stage((it + 1) & 1, tile + 1);
        const uint32_t* A = sm + (it & 1) * ABUF;

        float acc[12][4];
#pragma unroll
        for (int nb = 0; nb < 12; nb++)
#pragma unroll
            for (int q = 0; q < 4; q++) acc[nb][q] = 0.f;

#pragma unroll
        for (int tap = 0; tap < 9; tap++) {
            const int dy = tap / 3, dx = tap % 3;
            const int rbase = (dy * 66 + p0 + g + dx) * 36;
#pragma unroll
            for (int s = 0; s < 4; s++) {
                const int o = rbase + 8 * s + t;
                uint32_t a[4];
                a[0] = A[o];       a[2] = A[o + 4];
                a[1] = A[o + 288]; a[3] = A[o + 292];
#pragma unroll
                for (int nb = 0; nb < 12; nb++) {
                    const uint32_t* bp = btom + (size_t)(wn * 96 + nb * 8 + g) * 292
                                       + tap * 32 + 8 * s + t;
                    mma16816(acc[nb], a, __ldg(bp), __ldg(bp + 4));
                }
            }
        }

        const int y = tile / 3, x0 = (tile % 3) * 64;
        const size_t pix = (size_t)y * 192 + x0 + p0 + g;
#pragma unroll
        for (int nb = 0; nb < 12; nb++) {
            int n0 = wn * 96 + nb * 8 + 2 * t;
            if (n0 < 189) {
                float b0 = __ldg(bias + n0);
                offm[(size_t)n0 * HW0 + pix]     = acc[nb][0] + b0;
                offm[(size_t)n0 * HW0 + pix + 8] = acc[nb][2] + b0;
            }
            if (n0 + 1 < 189) {
                float b1 = __ldg(bias + n0 + 1);
                offm[(size_t)(n0 + 1) * HW0 + pix]     = acc[nb][1] + b1;
                offm[(size_t)(n0 + 1) * HW0 + pix + 8] = acc[nb][3] + b1;
            }
        }
    }
}

// ---------------------------------------------------------------------------
// 3x3 stride-2 conv, 16x16 tile, 8 cis per sync.
// ---------------------------------------------------------------------------
#define SCB 8
template <int CO>
__global__ void __launch_bounds__(256) conv3x3_s2(
    const float* __restrict__ in, const float* __restrict__ wgt,
    const float* __restrict__ bias, float* __restrict__ out,
    int Cin, int Cout, int Hin, int Win, int Hout, int Wout)
{
    __shared__ float s_in[SCB][33][33];
    __shared__ alignas(16) float s_w[SCB][9][CO];

    const int chunk = blockIdx.z;
    const int ox0 = blockIdx.x * 16, oy0 = blockIdx.y * 16;
    const int tid = threadIdx.x, tx = tid & 15, ty = tid >> 4;
    const int coBase = chunk * CO;

    float acc[CO];
#pragma unroll
    for (int i = 0; i < CO; i++) acc[i] = 0.f;

    for (int c0 = 0; c0 < Cin; c0 += SCB) {
        const int nc = min(SCB, Cin - c0);
        for (int i = tid; i < nc * 1089; i += 256) {
            int cb = i / 1089, rem = i - cb * 1089, r = rem / 33, c = rem - r * 33;
            int gy = 2 * oy0 - 1 + r, gx = 2 * ox0 - 1 + c;
            s_in[cb][r][c] = (gy >= 0 && gy < Hin && gx >= 0 && gx < Win)
                ? __ldg(in + ((size_t)(c0 + cb) * Hin + gy) * Win + gx) : 0.f;
        }
        for (int i = tid; i < nc * 9 * CO; i += 256) {
            int cb = i / (9 * CO), rem = i - cb * (9 * CO), co = rem / 9, t = rem - co * 9;
            int cog = coBase + co;
            s_w[cb][t][co] = (cog < Cout)
                ? __ldg(wgt + ((size_t)cog * Cin + (c0 + cb)) * 9 + t) : 0.f;
        }
        __syncthreads();
        for (int cb = 0; cb < nc; cb++) {
            float v[9];
#pragma unroll
            for (int t = 0; t < 9; t++) v[t] = s_in[cb][2 * ty + t / 3][2 * tx + t % 3];
#pragma unroll
            for (int t = 0; t < 9; t++) {
#pragma unroll
                for (int q = 0; q < CO / 4; q++) {
                    float4 w = *reinterpret_cast<const float4*>(&s_w[cb][t][4 * q]);
                    acc[4 * q + 0] += v[t] * w.x; acc[4 * q + 1] += v[t] * w.y;
                    acc[4 * q + 2] += v[t] * w.z; acc[4 * q + 3] += v[t] * w.w;
                }
            }
        }
        __syncthreads();
    }

    const int ox = ox0 + tx, oy = oy0 + ty;
    if (ox >= Wout || oy >= Hout) return;
    size_t pbase = (size_t)oy * Wout + ox;
#pragma unroll
    for (int co = 0; co < CO; co++) {
        int cog = coBase + co;
        if (cog >= Cout) break;
        float v = acc[co] + __ldg(bias + cog);
        out[(size_t)cog * Hout * Wout + pbase] = fmaxf(v, 0.f);
    }
}

// ---------------------------------------------------------------------------
// ConvTranspose2d k4 s2 p1, ReLU, 8 cis per sync.
// h2out != nullptr: emit NHWC fp16 (u32 channel pairs) instead of planar f32.
// ---------------------------------------------------------------------------
template <int CO>
__global__ void __launch_bounds__(256) convT4x4_s2(
    const float* __restrict__ in, const float* __restrict__ wgt,
    const float* __restrict__ bias, float* __restrict__ out,
    uint32_t* __restrict__ h2out,
    int Cin, int Cout, int Hin, int Win, int Hout, int Wout)
{
    __shared__ float s_in[SCB][10][10];
    __shared__ alignas(16) float s_w[SCB][16][CO];

    const int chunk = blockIdx.z;
    const int ox0 = blockIdx.x * 16, oy0 = blockIdx.y * 16;
    const int tid = threadIdx.x, tx = tid & 15, ty = tid >> 4;
    const int coBase = chunk * CO;
    const int iy0 = oy0 / 2 - 1, ix0 = ox0 / 2 - 1;

    const int oy = oy0 + ty, ox = ox0 + tx;
    const int py = (oy + 1) & 1, px = (ox + 1) & 1;
    const int r0 = ((oy + 1 - py) >> 1) - iy0, r1 = r0 - 1;
    const int c0i = ((ox + 1 - px) >> 1) - ix0, c1i = c0i - 1;

    float acc[CO];
#pragma unroll
    for (int i = 0; i < CO; i++) acc[i] = 0.f;

    for (int c0 = 0; c0 < Cin; c0 += SCB) {
        const int nc = min(SCB, Cin - c0);
        for (int i = tid; i < nc * 100; i += 256) {
            int cb = i / 100, rem = i - cb * 100, r = rem / 10, c = rem - r * 10;
            int gy = iy0 + r, gx = ix0 + c;
            s_in[cb][r][c] = (gy >= 0 && gy < Hin && gx >= 0 && gx < Win)
                ? __ldg(in + ((size_t)(c0 + cb) * Hin + gy) * Win + gx) : 0.f;
        }
        for (int i = tid; i < nc * 16 * CO; i += 256) {
            int cb = i / (16 * CO), rem = i - cb * (16 * CO), co = rem / 16, t = rem - co * 16;
            int cog = coBase + co;
            s_w[cb][t][co] = (cog < Cout)
                ? __ldg(wgt + ((size_t)(c0 + cb) * Cout + cog) * 16 + t) : 0.f;
        }
        __syncthreads();
        for (int cb = 0; cb < nc; cb++) {
            float v00 = s_in[cb][r0][c0i], v01 = s_in[cb][r0][c1i];
            float v10 = s_in[cb][r1][c0i], v11 = s_in[cb][r1][c1i];
#pragma unroll
            for (int a = 0; a < 2; a++) {
#pragma unroll
                for (int b = 0; b < 2; b++) {
                    float v = a ? (b ? v11 : v10) : (b ? v01 : v00);
                    int t = (py + 2 * a) * 4 + (px + 2 * b);
#pragma unroll
                    for (int q = 0; q < CO / 4; q++) {
                        float4 w = *reinterpret_cast<const float4*>(&s_w[cb][t][4 * q]);
                        acc[4 * q + 0] += v * w.x; acc[4 * q + 1] += v * w.y;
                        acc[4 * q + 2] += v * w.z; acc[4 * q + 3] += v * w.w;
                    }
                }
            }
        }
        __syncthreads();
    }

    if (ox >= Wout || oy >= Hout) return;
    size_t pbase = (size_t)oy * Wout + ox;

    if (h2out) {
        uint32_t* hp = h2out + pbase * 32 + coBase / 2;
        uint32_t v[CO / 2];
#pragma unroll
        for (int j = 0; j < CO / 2; j++) {
            float x0 = fmaxf(acc[2 * j] + __ldg(bias + coBase + 2 * j), 0.f);
            float x1 = fmaxf(acc[2 * j + 1] + __ldg(bias + coBase + 2 * j + 1), 0.f);
            __half2 h = __floats2half2_rn(x0, x1);
            v[j] = *reinterpret_cast<uint32_t*>(&h);
        }
#pragma unroll
        for (int j = 0; j < CO / 8; j++)
            *reinterpret_cast<uint4*>(hp + 4 * j) =
                make_uint4(v[4 * j], v[4 * j + 1], v[4 * j + 2], v[4 * j + 3]);
        return;
    }

#pragma unroll
    for (int co = 0; co < CO; co++) {
        int cog = coBase + co;
        if (cog >= Cout) break;
        float v = acc[co] + __ldg(bias + cog);
        out[(size_t)cog * Hout * Wout + pbase] = fmaxf(v, 0.f);
    }
}

// ---------------------------------------------------------------------------
// Fused flow-warp + gate -> NHWC fp16.
// ---------------------------------------------------------------------------
__global__ void warp_gate_kernel(const float* __restrict__ feat,
                                 const float* __restrict__ pred,
                                 const float* __restrict__ mv,
                                 uint32_t* __restrict__ a16)
{
    const int pix = blockIdx.x * 256 + threadIdx.x;
    if (pix >= HW0) return;
    const int t = blockIdx.y;

    float wgt[4]; int off[4]; bool val[4];
    const float* fb = nullptr;
    if (t > 0) {
        const int y = pix / W0, x = pix - y * W0;
        const float fx = mv[(size_t)(t - 1) * HW0 * 2 + (size_t)pix * 2 + 0];
        const float fy = mv[(size_t)(t - 1) * HW0 * 2 + (size_t)pix * 2 + 1];
        const float ys = (float)y + fy, xs = (float)x + fx;
        const float y0 = floorf(ys), x0 = floorf(xs);
        const float wy = ys - y0, wx = xs - x0;
#pragma unroll
        for (int i = 0; i < 4; i++) {
            int dy = i >> 1, dx = i & 1;
            float yi = y0 + dy, xi = x0 + dx;
            val[i] = (yi >= 0.f) && (yi <= (float)(H0 - 1)) &&
                     (xi >= 0.f) && (xi <= (float)(W0 - 1));
            wgt[i] = (dy ? wy : 1.f - wy) * (dx ? wx : 1.f - wx);
            off[i] = val[i] ? ((int)yi * W0 + (int)xi) : 0;
        }
        fb = feat + (size_t)(t - 1) * 64 * HW0;
    }

    const float* refb = feat + (size_t)3 * 64 * HW0 + pix;
    const float* prb  = pred + (size_t)t * 64 * HW0 + pix;
    const float* f0b  = feat + pix;
    uint32_t* ob = a16 + ((size_t)t * HW0 + pix) * 32;

    for (int c2 = 0; c2 < 32; c2++) {
        float o01[2];
#pragma unroll
        for (int s = 0; s < 2; s++) {
            const int c = 2 * c2 + s;
            float a;
            if (t == 0) {
                a = __ldg(f0b + (size_t)c * HW0);
            } else {
                const float* img = fb + (size_t)c * HW0;
                a = 0.f;
#pragma unroll
                for (int i = 0; i < 4; i++)
                    if (val[i]) a += __ldg(img + off[i]) * wgt[i];
            }
            float ref = __ldg(refb + (size_t)c * HW0);
            float p   = __ldg(prb + (size_t)c * HW0);
            o01[s] = a * fsigmoid(a * ref) + p * fsigmoid(p * ref);
        }
        __half2 h = __floats2half2_rn(o01[0], o01[1]);
        ob[c2] = *reinterpret_cast<uint32_t*>(&h);
    }
}

// ---------------------------------------------------------------------------
// Modulated deformable conv.
// ---------------------------------------------------------------------------
__global__ void __launch_bounds__(128) deform_kernel(
    const float* __restrict__ lqs, const float* __restrict__ offm,
    const float* __restrict__ dcw, const float* __restrict__ dcb,
    float* __restrict__ out)
{
    __shared__ alignas(16) float s_w[63 * 64];
    __shared__ float s_b[64];
    const int tid = threadIdx.x;
    for (int i = tid; i < 63 * 64; i += 128) {
        int o = i / 63, j = i - o * 63;
        s_w[j * 64 + o] = dcw[i];
    }
    if (tid < 64) s_b[tid] = dcb[tid];
    __syncthreads();

    const int pix = blockIdx.x * 128 + tid;
    if (pix >= HW0) return;
    const int y = pix / W0, x = pix - y * W0;

    ull_t acc[32];
#pragma unroll
    for (int q = 0; q < 32; q++) acc[q] = pack2(s_b[2 * q], s_b[2 * q + 1]);

    for (int g = 0; g < 7; g++) {
        const float* img = lqs + (size_t)g * HW0;
#pragma unroll
        for (int k = 0; k < 9; k++) {
            const int j = g * 9 + k;
            float offy = __ldg(offm + (size_t)(g * 18 + 2 * k + 0) * HW0 + pix);
            float offx = __ldg(offm + (size_t)(g * 18 + 2 * k + 1) * HW0 + pix);
            float mraw = __ldg(offm + (size_t)(126 + j) * HW0 + pix);
            float m = fsigmoid(mraw);
            float ys = (float)(y + k / 3 - 1) + offy;
            float xs = (float)(x + k % 3 - 1) + offx;
            float y0 = floorf(ys), x0 = floorf(xs);
            float wy = ys - y0, wx = xs - x0;
            float samp = 0.f;
#pragma unroll
            for (int ii = 0; ii < 4; ii++) {
                int dy = ii >> 1, dx = ii & 1;
                float yi = y0 + dy, xi = x0 + dx;
                if (yi >= 0.f && yi <= (float)(H0 - 1) &&
                    xi >= 0.f && xi <= (float)(W0 - 1))
                    samp += __ldg(img + (int)yi * W0 + (int)xi) *
                            ((dy ? wy : 1.f - wy) * (dx ? wx : 1.f - wx));
            }
            ull_t mod2 = pack2s(samp * m);
#pragma unroll
            for (int q2 = 0; q2 < 16; q2++) {
                ulonglong2 w = *reinterpret_cast<const ulonglong2*>(&s_w[j * 64 + 4 * q2]);
                ffma2(acc[2 * q2],     mod2, w.x);
                ffma2(acc[2 * q2 + 1], mod2, w.y);
            }
        }
    }
#pragma unroll
    for (int q = 0; q < 32; q++) {
        float2 u = unpack2(acc[q]);
        out[(size_t)(2 * q) * HW0 + pix]     = fmaxf(u.x, 0.f);
        out[(size_t)(2 * q + 1) * HW0 + pix] = fmaxf(u.y, 0.f);
    }
}

// ---------------------------------------------------------------------------
// Host orchestration (graph-capturable)
// ---------------------------------------------------------------------------
extern "C" void kernel_launch(void* const* d_in, const int* in_sizes, int n_in,
                              void* d_out, int out_size)
{
    const float* lqs    = (const float*)d_in[0];
    const float* preds  = (const float*)d_in[1];
    const float* mv     = (const float*)d_in[2];
    const float* bw1    = (const float*)d_in[3];
    const float* bb1    = (const float*)d_in[4];
    const float* bw2    = (const float*)d_in[5];
    const float* bb2    = (const float*)d_in[6];
    const float* dn1_w  = (const float*)d_in[7];
    const float* dn1_b  = (const float*)d_in[8];
    const float* dn2_w  = (const float*)d_in[9];
    const float* dn2_b  = (const float*)d_in[10];
    const float* up1_cw = (const float*)d_in[11];
    const float* up1_cb = (const float*)d_in[12];
    const float* up1_tw = (const float*)d_in[13];
    const float* up1_tb = (const float*)d_in[14];
    const float* up2_cw = (const float*)d_in[15];
    const float* up2_cb = (const float*)d_in[16];
    const float* up2_tw = (const float*)d_in[17];
    const float* up2_tb = (const float*)d_in[18];
    const float* tr_cw  = (const float*)d_in[19];
    const float* tr_cb  = (const float*)d_in[20];
    const float* tr_tw  = (const float*)d_in[21];
    const float* tr_tb  = (const float*)d_in[22];
    const float* ff_w   = (const float*)d_in[23];
    const float* ff_b   = (const float*)d_in[24];
    const float* om_w   = (const float*)d_in[25];
    const float* om_b   = (const float*)d_in[26];
    const float* dc_w   = (const float*)d_in[27];
    const float* dc_b   = (const float*)d_in[28];
    float* outp = (float*)d_out;

    float* S = nullptr;
    cudaGetSymbolAddress((void**)&S, g_scratch);
    float* feat  = S + OFF_FEAT;
    float* pred  = S + OFF_PRED;
    uint32_t* a16 = (uint32_t*)(S + OFF_ALG);
    uint32_t* f16 = (uint32_t*)(S + OFF_ALG) + (size_t)7 * HW0 * 32;
    uint32_t* h2buf = (uint32_t*)(S + OFF_H2);
    uint32_t* btimg = (uint32_t*)(S + OFF_WB);
    uint32_t* btff  = (uint32_t*)(S + OFF_WBF);
    uint32_t* btom  = (uint32_t*)(S + OFF_WBOM);
    float* out0  = S + OFF_OUT0;
    float* out1  = S + OFF_OUT1;
    float* out2  = S + OFF_OUT2;
    float* u24   = S + OFF_U24;
    float* cat48 = S + OFF_CAT48;
    float* c48   = S + OFF_C48;
    float* cat96 = S + OFF_CAT96;
    float* c96   = S + OFF_C96;
    uint32_t* featf16 = (uint32_t*)(S + OFF_FEATF);
    float* offm  = S + OFF_OFFM;

    cudaFuncSetAttribute(conv2_mma_kernel,
                         cudaFuncAttributeMaxDynamicSharedMemorySize, 195136);
    cudaFuncSetAttribute(dual_mma_kernel,
                         cudaFuncAttributeMaxDynamicSharedMemorySize, 114048);
    cudaFuncSetAttribute(om_mma_kernel,
                         cudaFuncAttributeMaxDynamicSharedMemorySize, 57024);

    dim3 blk(256);

    // conv1 (1->64) -> NHWC fp16: lqs imgs 0..6, preds imgs 7..13
    conv3x3_s1<8><<<dim3(6, 12, 7 * 4), blk>>>(lqs,   bw1, bb1, nullptr, h2buf,
                                               1, 64, 192, 192, 4, EP_H2);
    conv3x3_s1<8><<<dim3(6, 12, 7 * 4), blk>>>(preds, bw1, bb1, nullptr,
                                               h2buf + (size_t)7 * HW0 * 32,
                                               1, 64, 192, 192, 4, EP_H2);
    // conv2 via mma (planar fp32 [feat|pred] + NHWC fp16 feat for imgs 0..6)
    prep_bt_kernel<<<73, blk>>>(bw2, btimg);
    prep_btff_kernel<<<505, blk>>>(ff_w, btff);
    prep_btom_kernel<<<219, blk>>>(om_w, btom);
    conv2_mma_kernel<<<144, blk, 195136>>>(h2buf, btimg, bb2, feat, f16);

    // gated aligned features -> NHWC fp16
    warp_gate_kernel<<<dim3(HW0 / 256, 7), blk>>>(feat, pred, mv, a16);

    // fusion pair via mma (shared weights, both inputs in one pass)
    dual_mma_kernel<<<144, blk, 114048>>>(a16, f16, btff, ff_b, out0);

    // down path
    conv3x3_s2<8><<<dim3(6, 6, 8), blk>>>(out0, dn1_w, dn1_b, out1, 64, 64, 192, 192, 96, 96);
    conv3x3_s2<8><<<dim3(3, 3, 8), blk>>>(out1, dn2_w, dn2_b, out2, 64, 64, 96, 96, 48, 48);
    conv3x3_s2<8><<<dim3(2, 2, 8), blk>>>(out2, tr_cw, tr_cb, u24, 64, 64, 48, 48, 24, 24);

    // up path with skip concats
    convT4x4_s2<16><<<dim3(3, 3, 4), blk>>>(u24, tr_tw, tr_tb, cat48, nullptr,
                                            64, 64, 24, 24, 48, 48);
    cudaMemcpyAsync(cat48 + (size_t)64 * 48 * 48, out2,
                    (size_t)64 * 48 * 48 * sizeof(float), cudaMemcpyDeviceToDevice, 0);
    conv3x3_s1<8><<<dim3(2, 3, 4), blk>>>(cat48, up2_cw, up2_cb, c48, nullptr,
                                          128, 64, 48, 48, 4, EP_RELU);
    convT4x4_s2<16><<<dim3(6, 6, 4), blk>>>(c48, up2_tw, up2_tb, cat96, nullptr,
                                            64, 64, 48, 48, 96, 96);
    cudaMemcpyAsync(cat96 + (size_t)64 * 96 * 96, out1,
                    (size_t)64 * 96 * 96 * sizeof(float), cudaMemcpyDeviceToDevice, 0);
    conv3x3_s1<8><<<dim3(3, 6, 4), blk>>>(cat96, up1_cw, up1_cb, c96, nullptr,
                                          128, 64, 96, 96, 4, EP_RELU);
    // final convT emits NHWC fp16 directly for the om MMA
    convT4x4_s2<16><<<dim3(12, 12, 4), blk>>>(c96, up1_tw, up1_tb, nullptr, featf16,
                                              64, 64, 96, 96, 192, 192);

    // offsets + masks via mma
    om_mma_kernel<<<144, blk, 57024>>>(featf16, btom, om_b, offm);

    // modulated deformable conv -> output
    deform_kernel<<<HW0 / 128, dim3(128)>>>(lqs, offm, dc_w, dc_b, outp);
}